// round 3
// baseline (speedup 1.0000x reference)
#include <cuda_runtime.h>
#include <math.h>

#define BB   4
#define LL   4096
#define DD   1024
#define HH   16
#define DHH  64
#define MMF  256
#define DFF  4096
#define NT   (BB*LL)      /* 16384 tokens  */
#define NR   (NT*HH)      /* 262144 (t,h) rows */

// ---------------- scratch (device globals; no allocation allowed) ----------
__device__ float g_q   [(size_t)NT*DD];
__device__ float g_k   [(size_t)NT*DD];
__device__ float g_v   [(size_t)NT*DD];
__device__ float g_qp  [(size_t)NR*MMF];
__device__ float g_kp  [(size_t)NR*MMF];
__device__ float g_kv  [(size_t)BB*HH*MMF*DHH];
__device__ float g_ksum[BB*HH*MMF];
__device__ float g_den [NR];
__device__ float g_attn[(size_t)NT*DD];
__device__ float g_tmp [(size_t)NT*DD];
__device__ float g_out1[(size_t)NT*DD];
__device__ float g_hbuf[(size_t)NT*DFF];
__device__ float g_projT[DHH*MMF];
__device__ unsigned g_kmax;
// tf32-rounded copies of harness inputs
__device__ float g_xr  [(size_t)NT*DD];
__device__ float g_rwq [DD*DD];
__device__ float g_rwk [DD*DD];
__device__ float g_rwv [DD*DD];
__device__ float g_rwo [DD*DD];
__device__ float g_rw1 [(size_t)DD*DFF];
__device__ float g_rw2 [(size_t)DD*DFF];

enum { EPI_NONE = 0, EPI_BIAS = 1, EPI_BIAS_ELU = 2 };

// ---------------- tf32 / async helpers --------------------------------------
__device__ __forceinline__ float rtf(float x)
{
    unsigned u;
    asm("cvt.rna.tf32.f32 %0, %1;" : "=r"(u) : "f"(x));
    return __uint_as_float(u);
}

__device__ __forceinline__ void mma_tf32(float* d, const unsigned* a,
                                         const unsigned* b)
{
    asm volatile(
        "mma.sync.aligned.m16n8k8.row.col.f32.tf32.tf32.f32 "
        "{%0,%1,%2,%3}, {%4,%5,%6,%7}, {%8,%9}, {%0,%1,%2,%3};\n"
        : "+f"(d[0]), "+f"(d[1]), "+f"(d[2]), "+f"(d[3])
        : "r"(a[0]), "r"(a[1]), "r"(a[2]), "r"(a[3]),
          "r"(b[0]), "r"(b[1]));
}

__device__ __forceinline__ void cpa16(unsigned dst, const float* src)
{
    asm volatile("cp.async.cg.shared.global [%0], [%1], 16;" :: "r"(dst), "l"(src));
}
__device__ __forceinline__ void cpa_commit()
{
    asm volatile("cp.async.commit_group;");
}
template<int N> __device__ __forceinline__ void cpa_wait()
{
    asm volatile("cp.async.wait_group %0;" :: "n"(N));
}

// ---------------- tf32 tensor-core GEMM: C[M,N] = A[M,K] @ B[K,N] ------------
// 128x128 block tile, BK=16, 2-stage cp.async, 8 warps (4m x 2n),
// warp tile 32x64 via m16n8k8. Inputs must already be tf32-rounded fp32.
#define APAD 20
#define BPAD 136

template<int EPI, bool ROUND>
__global__ __launch_bounds__(256, 2)
void tgemm(const float* __restrict__ A, const float* __restrict__ B,
           const float* __restrict__ bias, float* __restrict__ C,
           int M, int N, int K)
{
    __shared__ float As[2][128 * APAD];
    __shared__ float Bs[2][16 * BPAD];

    const int tid  = threadIdx.x;
    const int wid  = tid >> 5;
    const int lane = tid & 31;
    const int wm   = (wid >> 1) * 32;
    const int wn   = (wid & 1)  * 64;
    const size_t m0 = (size_t)blockIdx.y * 128;
    const int    n0 = blockIdx.x * 128;

    const int arow = tid >> 2;
    const int acol = (tid & 3) << 2;
    const int brow = tid >> 5;
    const int bcol = (tid & 31) << 2;

    const unsigned sA = (unsigned)__cvta_generic_to_shared(&As[0][0]);
    const unsigned sB = (unsigned)__cvta_generic_to_shared(&Bs[0][0]);

    float acc[2][8][4];
#pragma unroll
    for (int mt = 0; mt < 2; mt++)
#pragma unroll
        for (int nt = 0; nt < 8; nt++)
#pragma unroll
            for (int i = 0; i < 4; i++) acc[mt][nt][i] = 0.f;

    const int iters = K >> 4;

    auto issue = [&](int s, int k0) {
        cpa16(sA + (unsigned)(s * (128 * APAD) + arow * APAD + acol) * 4u,
              A + (m0 + arow) * K + k0 + acol);
        cpa16(sA + (unsigned)(s * (128 * APAD) + (arow + 64) * APAD + acol) * 4u,
              A + (m0 + arow + 64) * K + k0 + acol);
        cpa16(sB + (unsigned)(s * (16 * BPAD) + brow * BPAD + bcol) * 4u,
              B + (size_t)(k0 + brow) * N + n0 + bcol);
        cpa16(sB + (unsigned)(s * (16 * BPAD) + (brow + 8) * BPAD + bcol) * 4u,
              B + (size_t)(k0 + brow + 8) * N + n0 + bcol);
    };

    issue(0, 0);
    cpa_commit();

    for (int it = 0; it < iters; it++) {
        if (it + 1 < iters) issue((it + 1) & 1, (it + 1) << 4);
        cpa_commit();
        cpa_wait<1>();
        __syncthreads();

        const float* as = As[it & 1];
        const float* bs = Bs[it & 1];
#pragma unroll
        for (int ks = 0; ks < 16; ks += 8) {
            unsigned af[2][4], bf[8][2];
#pragma unroll
            for (int mt = 0; mt < 2; mt++) {
                int r = wm + mt * 16 + (lane >> 2);
                int c = ks + (lane & 3);
                af[mt][0] = __float_as_uint(as[r * APAD + c]);
                af[mt][1] = __float_as_uint(as[(r + 8) * APAD + c]);
                af[mt][2] = __float_as_uint(as[r * APAD + c + 4]);
                af[mt][3] = __float_as_uint(as[(r + 8) * APAD + c + 4]);
            }
#pragma unroll
            for (int nt = 0; nt < 8; nt++) {
                int c = wn + nt * 8 + (lane >> 2);
                int r = ks + (lane & 3);
                bf[nt][0] = __float_as_uint(bs[r * BPAD + c]);
                bf[nt][1] = __float_as_uint(bs[(r + 4) * BPAD + c]);
            }
#pragma unroll
            for (int mt = 0; mt < 2; mt++)
#pragma unroll
                for (int nt = 0; nt < 8; nt++)
                    mma_tf32(acc[mt][nt], af[mt], bf[nt]);
        }
        __syncthreads();
    }

#pragma unroll
    for (int mt = 0; mt < 2; mt++) {
#pragma unroll
        for (int nt = 0; nt < 8; nt++) {
            size_t row = m0 + wm + mt * 16 + (lane >> 2);
            int col = n0 + wn + nt * 8 + ((lane & 3) << 1);
            float2 lo = make_float2(acc[mt][nt][0], acc[mt][nt][1]);
            float2 hi = make_float2(acc[mt][nt][2], acc[mt][nt][3]);
            if (EPI == EPI_BIAS || EPI == EPI_BIAS_ELU) {
                float2 bb = *(const float2*)(bias + col);
                lo.x += bb.x; lo.y += bb.y;
                hi.x += bb.x; hi.y += bb.y;
            }
            if (EPI == EPI_BIAS_ELU) {
                lo.x = lo.x > 0.f ? lo.x : expm1f(lo.x);
                lo.y = lo.y > 0.f ? lo.y : expm1f(lo.y);
                hi.x = hi.x > 0.f ? hi.x : expm1f(hi.x);
                hi.y = hi.y > 0.f ? hi.y : expm1f(hi.y);
            }
            if (ROUND) {
                lo.x = rtf(lo.x); lo.y = rtf(lo.y);
                hi.x = rtf(hi.x); hi.y = rtf(hi.y);
            }
            *(float2*)(C + row * N + col)       = lo;
            *(float2*)(C + (row + 8) * N + col) = hi;
        }
    }
}

// ------------- tf32 batched strided GEMM over (b,h): C = op(A) @ B ----------
// z = b*16 + h. BM=128, BN=64, BK=16, 2-stage cp.async, 8 warps (4m x 2n),
// warp tile 32x32.
#define AT_PAD 136   /* TRANSA: As[k][m] stride */
#define BH_BPAD 72   /* Bs[k][n] stride */

template<bool TRANSA, bool DIV, bool ROUND>
__global__ __launch_bounds__(256, 2)
void tgemm_bh(const float* __restrict__ A, size_t sAb, size_t sAh, int lda,
              const float* __restrict__ B, size_t sBb, size_t sBh, int ldb,
              float* __restrict__ C, size_t sCb, size_t sCh, int ldc,
              const float* __restrict__ aux, size_t sXb, size_t sXh, int ldx,
              int M, int N, int K)
{
    __shared__ float As[2][128 * APAD];   // !TRANSA: [m][k] stride 20 (2560)
                                          //  TRANSA: [k][m] stride 136 (2176)
    __shared__ float Bs[2][16 * BH_BPAD];

    const int z  = blockIdx.z;
    const int zb = z >> 4, zh = z & 15;
    const float* Ab = A + (size_t)zb * sAb + (size_t)zh * sAh;
    const float* Bb = B + (size_t)zb * sBb + (size_t)zh * sBh;
    float*       Cb = C + (size_t)zb * sCb + (size_t)zh * sCh;

    const int tid  = threadIdx.x;
    const int wid  = tid >> 5;
    const int lane = tid & 31;
    const int wm   = (wid >> 1) * 32;
    const int wn   = (wid & 1)  * 32;
    const int m0   = blockIdx.y * 128;
    const int n0   = blockIdx.x * 64;

    const unsigned sA = (unsigned)__cvta_generic_to_shared(&As[0][0]);
    const unsigned sB = (unsigned)__cvta_generic_to_shared(&Bs[0][0]);

    float acc[2][4][4];
#pragma unroll
    for (int mt = 0; mt < 2; mt++)
#pragma unroll
        for (int nt = 0; nt < 4; nt++)
#pragma unroll
            for (int i = 0; i < 4; i++) acc[mt][nt][i] = 0.f;

    const int iters = K >> 4;

    auto issue = [&](int s, int k0) {
        if (TRANSA) {
#pragma unroll
            for (int i = 0; i < 2; i++) {
                int lin = tid + i * 256;
                int kc  = lin >> 5;
                int mc  = (lin & 31) << 2;
                cpa16(sA + (unsigned)(s * (128 * APAD) + kc * AT_PAD + mc) * 4u,
                      Ab + (size_t)(k0 + kc) * lda + m0 + mc);
            }
        } else {
#pragma unroll
            for (int i = 0; i < 2; i++) {
                int lin = tid + i * 256;
                int row = lin >> 2;
                int col = (lin & 3) << 2;
                cpa16(sA + (unsigned)(s * (128 * APAD) + row * APAD + col) * 4u,
                      Ab + (size_t)(m0 + row) * lda + k0 + col);
            }
        }
        {
            int kc = tid >> 4;
            int nc = (tid & 15) << 2;
            cpa16(sB + (unsigned)(s * (16 * BH_BPAD) + kc * BH_BPAD + nc) * 4u,
                  Bb + (size_t)(k0 + kc) * ldb + n0 + nc);
        }
    };

    issue(0, 0);
    cpa_commit();

    for (int it = 0; it < iters; it++) {
        if (it + 1 < iters) issue((it + 1) & 1, (it + 1) << 4);
        cpa_commit();
        cpa_wait<1>();
        __syncthreads();

        const float* as = As[it & 1];
        const float* bs = Bs[it & 1];
#pragma unroll
        for (int ks = 0; ks < 16; ks += 8) {
            unsigned af[2][4], bf[4][2];
#pragma unroll
            for (int mt = 0; mt < 2; mt++) {
                int r = wm + mt * 16 + (lane >> 2);
                int c = ks + (lane & 3);
                if (TRANSA) {
                    af[mt][0] = __float_as_uint(as[c * AT_PAD + r]);
                    af[mt][1] = __float_as_uint(as[c * AT_PAD + r + 8]);
                    af[mt][2] = __float_as_uint(as[(c + 4) * AT_PAD + r]);
                    af[mt][3] = __float_as_uint(as[(c + 4) * AT_PAD + r + 8]);
                } else {
                    af[mt][0] = __float_as_uint(as[r * APAD + c]);
                    af[mt][1] = __float_as_uint(as[(r + 8) * APAD + c]);
                    af[mt][2] = __float_as_uint(as[r * APAD + c + 4]);
                    af[mt][3] = __float_as_uint(as[(r + 8) * APAD + c + 4]);
                }
            }
#pragma unroll
            for (int nt = 0; nt < 4; nt++) {
                int c = wn + nt * 8 + (lane >> 2);
                int r = ks + (lane & 3);
                bf[nt][0] = __float_as_uint(bs[r * BH_BPAD + c]);
                bf[nt][1] = __float_as_uint(bs[(r + 4) * BH_BPAD + c]);
            }
#pragma unroll
            for (int mt = 0; mt < 2; mt++)
#pragma unroll
                for (int nt = 0; nt < 4; nt++)
                    mma_tf32(acc[mt][nt], af[mt], bf[nt]);
        }
        __syncthreads();
    }

#pragma unroll
    for (int mt = 0; mt < 2; mt++) {
        int row = m0 + wm + mt * 16 + (lane >> 2);
        float dv0 = 1.f, dv1 = 1.f;
        if (DIV) {
            dv0 = 1.f / aux[(size_t)zb * sXb + (size_t)zh * sXh + (size_t)row * ldx];
            dv1 = 1.f / aux[(size_t)zb * sXb + (size_t)zh * sXh + (size_t)(row + 8) * ldx];
        }
#pragma unroll
        for (int nt = 0; nt < 4; nt++) {
            int col = n0 + wn + nt * 8 + ((lane & 3) << 1);
            float2 lo = make_float2(acc[mt][nt][0] * dv0, acc[mt][nt][1] * dv0);
            float2 hi = make_float2(acc[mt][nt][2] * dv1, acc[mt][nt][3] * dv1);
            if (ROUND) {
                lo.x = rtf(lo.x); lo.y = rtf(lo.y);
                hi.x = rtf(hi.x); hi.y = rtf(hi.y);
            }
            *(float2*)(Cb + (size_t)row * ldc + col)       = lo;
            *(float2*)(Cb + (size_t)(row + 8) * ldc + col) = hi;
        }
    }
}

// ---------------- small helper kernels --------------------------------------
__global__ void k_round4(const float4* __restrict__ in, float4* __restrict__ out,
                         int n4)
{
    int i = blockIdx.x * 256 + threadIdx.x;
    if (i < n4) {
        float4 v = in[i];
        v.x = rtf(v.x); v.y = rtf(v.y); v.z = rtf(v.z); v.w = rtf(v.w);
        out[i] = v;
    }
}

__global__ void k_projT(const float* __restrict__ proj, float* __restrict__ pT)
{
    int i = blockIdx.x * 256 + threadIdx.x;     // 0..16383
    int m = i >> 6, k = i & 63;
    pT[k * 256 + m] = rtf(proj[i] * 0.35355339059327373f);
}

__global__ void k_max(const float4* __restrict__ d, size_t n4, unsigned* __restrict__ out)
{
    float m = -3.4e38f;
    for (size_t i = (size_t)blockIdx.x * blockDim.x + threadIdx.x; i < n4;
         i += (size_t)gridDim.x * blockDim.x) {
        float4 v = d[i];
        m = fmaxf(m, fmaxf(fmaxf(v.x, v.y), fmaxf(v.z, v.w)));
    }
#pragma unroll
    for (int o = 16; o; o >>= 1) m = fmaxf(m, __shfl_xor_sync(0xffffffffu, m, o));
    __shared__ float sm[8];
    if ((threadIdx.x & 31) == 0) sm[threadIdx.x >> 5] = m;
    __syncthreads();
    if (threadIdx.x == 0) {
        float mm = sm[0];
        for (int i = 1; i < 8; i++) mm = fmaxf(mm, sm[i]);
        unsigned u = __float_as_uint(mm);
        u = (u & 0x80000000u) ? ~u : (u | 0x80000000u);
        atomicMax(out, u);
    }
}

__device__ __forceinline__ float unflip(unsigned u)
{
    return __uint_as_float((u & 0x80000000u) ? (u ^ 0x80000000u) : ~u);
}

// qp = ratio*(exp(dd - diag - rowmax) + eps), in place (tf32-rounded output)
__global__ void k_expq(float* __restrict__ dd, const float* __restrict__ q)
{
    size_t w   = ((size_t)blockIdx.x * blockDim.x + threadIdx.x) >> 5;
    int   lane = threadIdx.x & 31;
    float4* row = (float4*)(dd + w * 256);
    float4 v0 = row[lane];
    float4 v1 = row[lane + 32];
    float m = fmaxf(fmaxf(fmaxf(v0.x, v0.y), fmaxf(v0.z, v0.w)),
                    fmaxf(fmaxf(v1.x, v1.y), fmaxf(v1.z, v1.w)));
#pragma unroll
    for (int o = 16; o; o >>= 1) m = fmaxf(m, __shfl_xor_sync(0xffffffffu, m, o));
    float2 qq = ((const float2*)(q + w * 64))[lane];
    float ss = qq.x * qq.x + qq.y * qq.y;
#pragma unroll
    for (int o = 16; o; o >>= 1) ss += __shfl_xor_sync(0xffffffffu, ss, o);
    float c = 0.0625f * ss + m;
    v0.x = rtf(0.0625f * (expf(v0.x - c) + 1e-6f));
    v0.y = rtf(0.0625f * (expf(v0.y - c) + 1e-6f));
    v0.z = rtf(0.0625f * (expf(v0.z - c) + 1e-6f));
    v0.w = rtf(0.0625f * (expf(v0.w - c) + 1e-6f));
    v1.x = rtf(0.0625f * (expf(v1.x - c) + 1e-6f));
    v1.y = rtf(0.0625f * (expf(v1.y - c) + 1e-6f));
    v1.z = rtf(0.0625f * (expf(v1.z - c) + 1e-6f));
    v1.w = rtf(0.0625f * (expf(v1.w - c) + 1e-6f));
    row[lane] = v0; row[lane + 32] = v1;
}

// kp = ratio*(exp(dd - diag - globalmax) + eps), in place (tf32-rounded)
__global__ void k_expk(float* __restrict__ dd, const float* __restrict__ k,
                       const unsigned* __restrict__ gmax)
{
    size_t w   = ((size_t)blockIdx.x * blockDim.x + threadIdx.x) >> 5;
    int   lane = threadIdx.x & 31;
    float4* row = (float4*)(dd + w * 256);
    float4 v0 = row[lane];
    float4 v1 = row[lane + 32];
    float2 kk = ((const float2*)(k + w * 64))[lane];
    float ss = kk.x * kk.x + kk.y * kk.y;
#pragma unroll
    for (int o = 16; o; o >>= 1) ss += __shfl_xor_sync(0xffffffffu, ss, o);
    float c = 0.0625f * ss + unflip(*gmax);
    v0.x = rtf(0.0625f * (expf(v0.x - c) + 1e-6f));
    v0.y = rtf(0.0625f * (expf(v0.y - c) + 1e-6f));
    v0.z = rtf(0.0625f * (expf(v0.z - c) + 1e-6f));
    v0.w = rtf(0.0625f * (expf(v0.w - c) + 1e-6f));
    v1.x = rtf(0.0625f * (expf(v1.x - c) + 1e-6f));
    v1.y = rtf(0.0625f * (expf(v1.y - c) + 1e-6f));
    v1.z = rtf(0.0625f * (expf(v1.z - c) + 1e-6f));
    v1.w = rtf(0.0625f * (expf(v1.w - c) + 1e-6f));
    row[lane] = v0; row[lane + 32] = v1;
}

// ksum[b,h,m] = sum_l kp[b,l,h,m]
__global__ void k_ksum(const float* __restrict__ kp, float* __restrict__ ksum)
{
    int z = blockIdx.y;
    int b = z >> 4, h = z & 15;
    int m = threadIdx.x;
    size_t base = (size_t)b * 16777216 + (size_t)h * 256 + m;
    float s = 0.f;
    int l0 = blockIdx.x * 512;
    for (int l = l0; l < l0 + 512; l++) s += kp[base + (size_t)l * 4096];
    atomicAdd(&ksum[z * 256 + m], s);
}

// denom[r] = dot(qp[r,:], ksum[b,h,:]); warp per row
__global__ void k_denom(const float* __restrict__ qp, const float* __restrict__ ksum,
                        float* __restrict__ den)
{
    size_t w   = ((size_t)blockIdx.x * blockDim.x + threadIdx.x) >> 5;
    int   lane = threadIdx.x & 31;
    int   b    = (int)(w >> 16);
    int   h    = (int)(w & 15);
    const float4* row = (const float4*)(qp + w * 256);
    const float4* ks  = (const float4*)(ksum + ((size_t)b * 16 + h) * 256);
    float4 a0 = row[lane], a1 = row[lane + 32];
    float4 k0 = ks[lane],  k1 = ks[lane + 32];
    float s = a0.x * k0.x + a0.y * k0.y + a0.z * k0.z + a0.w * k0.w
            + a1.x * k1.x + a1.y * k1.y + a1.z * k1.z + a1.w * k1.w;
#pragma unroll
    for (int o = 16; o; o >>= 1) s += __shfl_xor_sync(0xffffffffu, s, o);
    if (lane == 0) den[w] = s;
}

// out = LN(a + r) * g + b ; one block per 1024-wide row
template<bool ROUND>
__global__ void k_ln(const float* __restrict__ a, const float* __restrict__ r,
                     const float* __restrict__ g, const float* __restrict__ b,
                     float* __restrict__ out)
{
    const int row = blockIdx.x;
    const int t   = threadIdx.x;
    const size_t base = (size_t)row * 1024;
    float4 xa = *(const float4*)(a + base + t * 4);
    float4 xr = *(const float4*)(r + base + t * 4);
    float4 s  = make_float4(xa.x + xr.x, xa.y + xr.y, xa.z + xr.z, xa.w + xr.w);
    float sum = s.x + s.y + s.z + s.w;
    float sq  = s.x * s.x + s.y * s.y + s.z * s.z + s.w * s.w;
#pragma unroll
    for (int o = 16; o; o >>= 1) {
        sum += __shfl_xor_sync(0xffffffffu, sum, o);
        sq  += __shfl_xor_sync(0xffffffffu, sq,  o);
    }
    __shared__ float ssum[8], ssq[8];
    __shared__ float s_mu, s_inv;
    int w = t >> 5;
    if ((t & 31) == 0) { ssum[w] = sum; ssq[w] = sq; }
    __syncthreads();
    if (t == 0) {
        float ts = 0.f, tq = 0.f;
        for (int i = 0; i < 8; i++) { ts += ssum[i]; tq += ssq[i]; }
        float mu  = ts * (1.f / 1024.f);
        float var = tq * (1.f / 1024.f) - mu * mu;
        s_mu = mu;
        s_inv = rsqrtf(var + 1e-6f);
    }
    __syncthreads();
    float mu = s_mu, inv = s_inv;
    float4 gg = *(const float4*)(g + t * 4);
    float4 bb = *(const float4*)(b + t * 4);
    float4 o = make_float4((s.x - mu) * inv * gg.x + bb.x,
                           (s.y - mu) * inv * gg.y + bb.y,
                           (s.z - mu) * inv * gg.z + bb.z,
                           (s.w - mu) * inv * gg.w + bb.w);
    if (ROUND) { o.x = rtf(o.x); o.y = rtf(o.y); o.z = rtf(o.z); o.w = rtf(o.w); }
    *(float4*)(out + base + t * 4) = o;
}

// ---------------- driver -----------------------------------------------------
extern "C" void kernel_launch(void* const* d_in, const int* in_sizes, int n_in,
                              void* d_out, int out_size)
{
    const float* x    = (const float*)d_in[0];
    const float* wq   = (const float*)d_in[1];
    const float* wk   = (const float*)d_in[2];
    const float* wv   = (const float*)d_in[3];
    const float* wo   = (const float*)d_in[4];
    const float* proj = (const float*)d_in[5];
    const float* ln1g = (const float*)d_in[6];
    const float* ln1b = (const float*)d_in[7];
    const float* ln2g = (const float*)d_in[8];
    const float* ln2b = (const float*)d_in[9];
    const float* w1   = (const float*)d_in[10];
    const float* b1   = (const float*)d_in[11];
    const float* w2   = (const float*)d_in[12];
    const float* b2   = (const float*)d_in[13];
    float* out = (float*)d_out;

    float *p_q, *p_k, *p_v, *p_qp, *p_kp, *p_kv, *p_ksum, *p_den;
    float *p_attn, *p_tmp, *p_out1, *p_h, *p_pT;
    float *p_xr, *p_rwq, *p_rwk, *p_rwv, *p_rwo, *p_rw1, *p_rw2;
    unsigned* p_kmax;
    cudaGetSymbolAddress((void**)&p_q,    g_q);
    cudaGetSymbolAddress((void**)&p_k,    g_k);
    cudaGetSymbolAddress((void**)&p_v,    g_v);
    cudaGetSymbolAddress((void**)&p_qp,   g_qp);
    cudaGetSymbolAddress((void**)&p_kp,   g_kp);
    cudaGetSymbolAddress((void**)&p_kv,   g_kv);
    cudaGetSymbolAddress((void**)&p_ksum, g_ksum);
    cudaGetSymbolAddress((void**)&p_den,  g_den);
    cudaGetSymbolAddress((void**)&p_attn, g_attn);
    cudaGetSymbolAddress((void**)&p_tmp,  g_tmp);
    cudaGetSymbolAddress((void**)&p_out1, g_out1);
    cudaGetSymbolAddress((void**)&p_h,    g_hbuf);
    cudaGetSymbolAddress((void**)&p_pT,   g_projT);
    cudaGetSymbolAddress((void**)&p_kmax, g_kmax);
    cudaGetSymbolAddress((void**)&p_xr,   g_xr);
    cudaGetSymbolAddress((void**)&p_rwq,  g_rwq);
    cudaGetSymbolAddress((void**)&p_rwk,  g_rwk);
    cudaGetSymbolAddress((void**)&p_rwv,  g_rwv);
    cudaGetSymbolAddress((void**)&p_rwo,  g_rwo);
    cudaGetSymbolAddress((void**)&p_rw1,  g_rw1);
    cudaGetSymbolAddress((void**)&p_rw2,  g_rw2);

    // tf32-round inputs once
    k_round4<<<(NT * DD / 4 + 255) / 256, 256>>>((const float4*)x,  (float4*)p_xr,  NT * DD / 4);
    k_round4<<<(DD * DD / 4 + 255) / 256, 256>>>((const float4*)wq, (float4*)p_rwq, DD * DD / 4);
    k_round4<<<(DD * DD / 4 + 255) / 256, 256>>>((const float4*)wk, (float4*)p_rwk, DD * DD / 4);
    k_round4<<<(DD * DD / 4 + 255) / 256, 256>>>((const float4*)wv, (float4*)p_rwv, DD * DD / 4);
    k_round4<<<(DD * DD / 4 + 255) / 256, 256>>>((const float4*)wo, (float4*)p_rwo, DD * DD / 4);
    k_round4<<<(DD * DFF / 4 + 255) / 256, 256>>>((const float4*)w1, (float4*)p_rw1, DD * DFF / 4);
    k_round4<<<(DD * DFF / 4 + 255) / 256, 256>>>((const float4*)w2, (float4*)p_rw2, DD * DFF / 4);
    k_projT<<<64, 256>>>(proj, p_pT);

    // q,k,v projections (outputs tf32-rounded)
    tgemm<EPI_NONE, true><<<dim3(8, 128), 256>>>(p_xr, p_rwq, nullptr, p_q, NT, 1024, 1024);
    tgemm<EPI_NONE, true><<<dim3(8, 128), 256>>>(p_xr, p_rwk, nullptr, p_k, NT, 1024, 1024);
    tgemm<EPI_NONE, true><<<dim3(8, 128), 256>>>(p_xr, p_rwv, nullptr, p_v, NT, 1024, 1024);

    // dd = q_resh[262144,64] @ projT[64,256]  (raw fp32 out, exp rounds later)
    tgemm<EPI_NONE, false><<<dim3(2, 2048), 256>>>(p_q, p_pT, nullptr, p_qp, NR, 256, 64);
    tgemm<EPI_NONE, false><<<dim3(2, 2048), 256>>>(p_k, p_pT, nullptr, p_kp, NR, 256, 64);

    cudaMemsetAsync(p_kmax, 0, 4);
    cudaMemsetAsync(p_ksum, 0, BB * HH * MMF * sizeof(float));

    k_max<<<2048, 256>>>((const float4*)p_kp, (size_t)NR * 64, p_kmax);

    k_expq<<<NR / 8, 256>>>(p_qp, p_q);
    k_expk<<<NR / 8, 256>>>(p_kp, p_k, p_kmax);

    // kv[bh][256][64] = kp^T @ v : M=256 N=64 K=4096 (tf32, rounded out)
    tgemm_bh<true, false, true><<<dim3(1, 2, 64), 256>>>(
        p_kp, (size_t)16777216, (size_t)256, 4096,
        p_v,  (size_t)4194304,  (size_t)64,  1024,
        p_kv, (size_t)(16 * 16384), (size_t)16384, 64,
        nullptr, 0, 0, 0,
        256, 64, 4096);

    k_ksum<<<dim3(8, 64), 256>>>(p_kp, p_ksum);
    k_denom<<<NR / 8, 256>>>(p_qp, p_ksum, p_den);

    // attn = (qp @ kv) / denom : M=4096 N=64 K=256 (tf32, rounded out)
    tgemm_bh<false, true, true><<<dim3(1, 32, 64), 256>>>(
        p_qp, (size_t)16777216, (size_t)256, 4096,
        p_kv, (size_t)(16 * 16384), (size_t)16384, 64,
        p_attn, (size_t)4194304, (size_t)64, 1024,
        p_den,  (size_t)65536,   (size_t)1,  16,
        4096, 64, 256);

    // attn_out = attn @ wo
    tgemm<EPI_NONE, false><<<dim3(8, 128), 256>>>(p_attn, p_rwo, nullptr, p_tmp, NT, 1024, 1024);

    // out1 = LN(x + attn_out)  (rounded: feeds FFN1)
    k_ln<true><<<NT, 256>>>(p_tmp, x, ln1g, ln1b, p_out1);

    // FFN
    tgemm<EPI_BIAS_ELU, true><<<dim3(32, 128), 256>>>(p_out1, p_rw1, b1, p_h, NT, DFF, 1024);
    tgemm<EPI_BIAS, false><<<dim3(8, 128), 256>>>(p_h, p_rw2, b2, p_tmp, NT, 1024, DFF);

    // out2 = LN(out1 + ffn)
    k_ln<false><<<NT, 256>>>(p_tmp, p_out1, ln2g, ln2b, out);
}

// round 4
// speedup vs baseline: 1.1698x; 1.1698x over previous
#include <cuda_runtime.h>
#include <math.h>

#define BB   4
#define LL   4096
#define DD   1024
#define HH   16
#define DHH  64
#define MMF  256
#define DFF  4096
#define NT   (BB*LL)      /* 16384 tokens  */
#define NR   (NT*HH)      /* 262144 (t,h) rows */

// ---------------- scratch (device globals; no allocation allowed) ----------
__device__ float g_q   [(size_t)NT*DD];
__device__ float g_k   [(size_t)NT*DD];
__device__ float g_v   [(size_t)NT*DD];
__device__ float g_qp  [(size_t)NR*MMF];
__device__ float g_kp  [(size_t)NR*MMF];
__device__ float g_kv  [(size_t)BB*HH*MMF*DHH];
__device__ float g_ksum[BB*HH*MMF];
__device__ float g_den [NR];
__device__ float g_attn[(size_t)NT*DD];
__device__ float g_tmp [(size_t)NT*DD];
__device__ float g_out1[(size_t)NT*DD];
__device__ float g_hbuf[(size_t)NT*DFF];
__device__ float g_projT[DHH*MMF];
__device__ unsigned g_kmax;
// tf32-rounded copies of harness inputs
__device__ float g_xr  [(size_t)NT*DD];
__device__ float g_rwq [DD*DD];
__device__ float g_rwk [DD*DD];
__device__ float g_rwv [DD*DD];
__device__ float g_rwo [DD*DD];
__device__ float g_rw1 [(size_t)DD*DFF];
__device__ float g_rw2 [(size_t)DD*DFF];

enum { EPI_NONE = 0, EPI_BIAS = 1, EPI_BIAS_ELU = 2 };

// ---------------- tf32 helpers ----------------------------------------------
__device__ __forceinline__ float rtf(float x)
{
    unsigned u;
    asm("cvt.rna.tf32.f32 %0, %1;" : "=r"(u) : "f"(x));
    return __uint_as_float(u);
}

__device__ __forceinline__ void mma_tf32(float* d, const unsigned* a,
                                         const unsigned* b)
{
    asm volatile(
        "mma.sync.aligned.m16n8k8.row.col.f32.tf32.tf32.f32 "
        "{%0,%1,%2,%3}, {%4,%5,%6,%7}, {%8,%9}, {%0,%1,%2,%3};\n"
        : "+f"(d[0]), "+f"(d[1]), "+f"(d[2]), "+f"(d[3])
        : "r"(a[0]), "r"(a[1]), "r"(a[2]), "r"(a[3]),
          "r"(b[0]), "r"(b[1]));
}

// ---------------- tf32 tensor-core GEMM: C[M,N] = A[M,K] @ B[K,N] ------------
// 128x128 block tile, BK=16, 128 threads = 4 warps (2m x 2n),
// warp tile 64x64 via m16n8k8 (4 m-tiles x 8 n-tiles).
// R2-proven pipeline: LDG->regs prefetch spanning compute, STS after.
// Inputs must already be tf32(RNA)-rounded fp32.
#define APAD 20
#define BPAD 136

template<int EPI, bool ROUND>
__global__ __launch_bounds__(128, 2)
void tgemm(const float* __restrict__ A, const float* __restrict__ B,
           const float* __restrict__ bias, float* __restrict__ C,
           int M, int N, int K)
{
    __shared__ float As[128 * APAD];
    __shared__ float Bs[16 * BPAD];

    const int tid  = threadIdx.x;
    const int wid  = tid >> 5;
    const int lane = tid & 31;
    const int wm   = (wid >> 1) * 64;
    const int wn   = (wid & 1)  * 64;
    const size_t m0 = (size_t)blockIdx.y * 128;
    const int    n0 = blockIdx.x * 128;

    // staging: A one row per thread (4 float4), B rows tid>>5, +4.. (4 float4)
    const int brow = tid >> 5;
    const int bcol = lane << 2;

    float4 ra[4], rb[4];
    float acc[4][8][4];
#pragma unroll
    for (int mt = 0; mt < 4; mt++)
#pragma unroll
        for (int nt = 0; nt < 8; nt++)
#pragma unroll
            for (int i = 0; i < 4; i++) acc[mt][nt][i] = 0.f;

    const int iters = K >> 4;
    const float* Arow = A + (m0 + tid) * K;

    // prologue load
#pragma unroll
    for (int i = 0; i < 4; i++) ra[i] = *(const float4*)(Arow + i * 4);
#pragma unroll
    for (int i = 0; i < 4; i++)
        rb[i] = *(const float4*)(B + (size_t)(brow + i * 4) * N + n0 + bcol);

    for (int it = 0; it < iters; it++) {
#pragma unroll
        for (int i = 0; i < 4; i++)
            *(float4*)&As[tid * APAD + i * 4] = ra[i];
#pragma unroll
        for (int i = 0; i < 4; i++)
            *(float4*)&Bs[(brow + i * 4) * BPAD + bcol] = rb[i];
        __syncthreads();

        if (it + 1 < iters) {
            int k0 = (it + 1) << 4;
#pragma unroll
            for (int i = 0; i < 4; i++)
                ra[i] = *(const float4*)(Arow + k0 + i * 4);
#pragma unroll
            for (int i = 0; i < 4; i++)
                rb[i] = *(const float4*)(B + (size_t)(k0 + brow + i * 4) * N + n0 + bcol);
        }

#pragma unroll
        for (int ks = 0; ks < 16; ks += 8) {
            unsigned af[4][4], bf[8][2];
#pragma unroll
            for (int mt = 0; mt < 4; mt++) {
                int r = wm + mt * 16 + (lane >> 2);
                int c = ks + (lane & 3);
                af[mt][0] = __float_as_uint(As[r * APAD + c]);
                af[mt][1] = __float_as_uint(As[(r + 8) * APAD + c]);
                af[mt][2] = __float_as_uint(As[r * APAD + c + 4]);
                af[mt][3] = __float_as_uint(As[(r + 8) * APAD + c + 4]);
            }
#pragma unroll
            for (int nt = 0; nt < 8; nt++) {
                int c = wn + nt * 8 + (lane >> 2);
                int r = ks + (lane & 3);
                bf[nt][0] = __float_as_uint(Bs[r * BPAD + c]);
                bf[nt][1] = __float_as_uint(Bs[(r + 4) * BPAD + c]);
            }
#pragma unroll
            for (int mt = 0; mt < 4; mt++)
#pragma unroll
                for (int nt = 0; nt < 8; nt++)
                    mma_tf32(acc[mt][nt], af[mt], bf[nt]);
        }
        __syncthreads();
    }

#pragma unroll
    for (int mt = 0; mt < 4; mt++) {
#pragma unroll
        for (int nt = 0; nt < 8; nt++) {
            size_t row = m0 + wm + mt * 16 + (lane >> 2);
            int col = n0 + wn + nt * 8 + ((lane & 3) << 1);
            float2 lo = make_float2(acc[mt][nt][0], acc[mt][nt][1]);
            float2 hi = make_float2(acc[mt][nt][2], acc[mt][nt][3]);
            if (EPI == EPI_BIAS || EPI == EPI_BIAS_ELU) {
                float2 bb = *(const float2*)(bias + col);
                lo.x += bb.x; lo.y += bb.y;
                hi.x += bb.x; hi.y += bb.y;
            }
            if (EPI == EPI_BIAS_ELU) {
                lo.x = lo.x > 0.f ? lo.x : expm1f(lo.x);
                lo.y = lo.y > 0.f ? lo.y : expm1f(lo.y);
                hi.x = hi.x > 0.f ? hi.x : expm1f(hi.x);
                hi.y = hi.y > 0.f ? hi.y : expm1f(hi.y);
            }
            if (ROUND) {
                lo.x = rtf(lo.x); lo.y = rtf(lo.y);
                hi.x = rtf(hi.x); hi.y = rtf(hi.y);
            }
            *(float2*)(C + row * N + col)       = lo;
            *(float2*)(C + (row + 8) * N + col) = hi;
        }
    }
}

// ------------- tf32 batched strided GEMM over (b,h): C = op(A) @ B ----------
// z = b*16 + h. BM=128, BN=64, BK=16, 256 threads = 8 warps (4m x 2n),
// warp tile 32x32. R2-style reg-prefetch pipeline.
#define AT_PAD 136   /* TRANSA: As[k][m] stride */
#define BH_BPAD 72   /* Bs[k][n] stride */

template<bool TRANSA, bool DIV, bool ROUND>
__global__ __launch_bounds__(256, 2)
void tgemm_bh(const float* __restrict__ A, size_t sAb, size_t sAh, int lda,
              const float* __restrict__ B, size_t sBb, size_t sBh, int ldb,
              float* __restrict__ C, size_t sCb, size_t sCh, int ldc,
              const float* __restrict__ aux, size_t sXb, size_t sXh, int ldx,
              int M, int N, int K)
{
    __shared__ float As[128 * APAD];   // !TRANSA [m][k] stride 20; TRANSA [k][m] stride 136
    __shared__ float Bs[16 * BH_BPAD];

    const int z  = blockIdx.z;
    const int zb = z >> 4, zh = z & 15;
    const float* Ab = A + (size_t)zb * sAb + (size_t)zh * sAh;
    const float* Bb = B + (size_t)zb * sBb + (size_t)zh * sBh;
    float*       Cb = C + (size_t)zb * sCb + (size_t)zh * sCh;

    const int tid  = threadIdx.x;
    const int wid  = tid >> 5;
    const int lane = tid & 31;
    const int wm   = (wid >> 1) * 32;
    const int wn   = (wid & 1)  * 32;
    const int m0   = blockIdx.y * 128;
    const int n0   = blockIdx.x * 64;

    // staging maps
    const int t_kr = tid >> 5;          // TRANSA A: rows lin>>5 (via 2 chunks)
    const int t_mc = lane << 2;
    const int n_row = tid & 127;        // !TRANSA A: row per thread, kh = tid>>7
    const int n_kh  = (tid >> 7) << 3;
    const int b_kr = tid >> 4;
    const int b_nc = (tid & 15) << 2;

    float4 ra[2], rb1;
    float acc[2][4][4];
#pragma unroll
    for (int mt = 0; mt < 2; mt++)
#pragma unroll
        for (int nt = 0; nt < 4; nt++)
#pragma unroll
            for (int i = 0; i < 4; i++) acc[mt][nt][i] = 0.f;

    const int iters = K >> 4;

    auto ldA = [&](int k0) {
        if (TRANSA) {
            ra[0] = *(const float4*)(Ab + (size_t)(k0 + t_kr)     * lda + m0 + t_mc);
            ra[1] = *(const float4*)(Ab + (size_t)(k0 + t_kr + 8) * lda + m0 + t_mc);
        } else {
            ra[0] = *(const float4*)(Ab + (size_t)(m0 + n_row) * lda + k0 + n_kh);
            ra[1] = *(const float4*)(Ab + (size_t)(m0 + n_row) * lda + k0 + n_kh + 4);
        }
    };
    auto ldB = [&](int k0) {
        rb1 = *(const float4*)(Bb + (size_t)(k0 + b_kr) * ldb + n0 + b_nc);
    };

    ldA(0); ldB(0);

    for (int it = 0; it < iters; it++) {
        if (TRANSA) {
            *(float4*)&As[t_kr * AT_PAD + t_mc]       = ra[0];
            *(float4*)&As[(t_kr + 8) * AT_PAD + t_mc] = ra[1];
        } else {
            *(float4*)&As[n_row * APAD + n_kh]     = ra[0];
            *(float4*)&As[n_row * APAD + n_kh + 4] = ra[1];
        }
        *(float4*)&Bs[b_kr * BH_BPAD + b_nc] = rb1;
        __syncthreads();

        if (it + 1 < iters) { ldA((it + 1) << 4); ldB((it + 1) << 4); }

#pragma unroll
        for (int ks = 0; ks < 16; ks += 8) {
            unsigned af[2][4], bf[4][2];
#pragma unroll
            for (int mt = 0; mt < 2; mt++) {
                int r = wm + mt * 16 + (lane >> 2);
                int c = ks + (lane & 3);
                if (TRANSA) {
                    af[mt][0] = __float_as_uint(As[c * AT_PAD + r]);
                    af[mt][1] = __float_as_uint(As[c * AT_PAD + r + 8]);
                    af[mt][2] = __float_as_uint(As[(c + 4) * AT_PAD + r]);
                    af[mt][3] = __float_as_uint(As[(c + 4) * AT_PAD + r + 8]);
                } else {
                    af[mt][0] = __float_as_uint(As[r * APAD + c]);
                    af[mt][1] = __float_as_uint(As[(r + 8) * APAD + c]);
                    af[mt][2] = __float_as_uint(As[r * APAD + c + 4]);
                    af[mt][3] = __float_as_uint(As[(r + 8) * APAD + c + 4]);
                }
            }
#pragma unroll
            for (int nt = 0; nt < 4; nt++) {
                int c = wn + nt * 8 + (lane >> 2);
                int r = ks + (lane & 3);
                bf[nt][0] = __float_as_uint(Bs[r * BH_BPAD + c]);
                bf[nt][1] = __float_as_uint(Bs[(r + 4) * BH_BPAD + c]);
            }
#pragma unroll
            for (int mt = 0; mt < 2; mt++)
#pragma unroll
                for (int nt = 0; nt < 4; nt++)
                    mma_tf32(acc[mt][nt], af[mt], bf[nt]);
        }
        __syncthreads();
    }

#pragma unroll
    for (int mt = 0; mt < 2; mt++) {
        int row = m0 + wm + mt * 16 + (lane >> 2);
        float dv0 = 1.f, dv1 = 1.f;
        if (DIV) {
            dv0 = 1.f / aux[(size_t)zb * sXb + (size_t)zh * sXh + (size_t)row * ldx];
            dv1 = 1.f / aux[(size_t)zb * sXb + (size_t)zh * sXh + (size_t)(row + 8) * ldx];
        }
#pragma unroll
        for (int nt = 0; nt < 4; nt++) {
            int col = n0 + wn + nt * 8 + ((lane & 3) << 1);
            float2 lo = make_float2(acc[mt][nt][0] * dv0, acc[mt][nt][1] * dv0);
            float2 hi = make_float2(acc[mt][nt][2] * dv1, acc[mt][nt][3] * dv1);
            if (ROUND) {
                lo.x = rtf(lo.x); lo.y = rtf(lo.y);
                hi.x = rtf(hi.x); hi.y = rtf(hi.y);
            }
            *(float2*)(Cb + (size_t)row * ldc + col)       = lo;
            *(float2*)(Cb + (size_t)(row + 8) * ldc + col) = hi;
        }
    }
}

// ---------------- small helper kernels --------------------------------------
__global__ void k_round4(const float4* __restrict__ in, float4* __restrict__ out,
                         int n4)
{
    int i = blockIdx.x * 256 + threadIdx.x;
    if (i < n4) {
        float4 v = in[i];
        v.x = rtf(v.x); v.y = rtf(v.y); v.z = rtf(v.z); v.w = rtf(v.w);
        out[i] = v;
    }
}

__global__ void k_projT(const float* __restrict__ proj, float* __restrict__ pT)
{
    int i = blockIdx.x * 256 + threadIdx.x;     // 0..16383
    int m = i >> 6, k = i & 63;
    pT[k * 256 + m] = rtf(proj[i] * 0.35355339059327373f);
}

__global__ void k_max(const float4* __restrict__ d, size_t n4, unsigned* __restrict__ out)
{
    float m = -3.4e38f;
    for (size_t i = (size_t)blockIdx.x * blockDim.x + threadIdx.x; i < n4;
         i += (size_t)gridDim.x * blockDim.x) {
        float4 v = d[i];
        m = fmaxf(m, fmaxf(fmaxf(v.x, v.y), fmaxf(v.z, v.w)));
    }
#pragma unroll
    for (int o = 16; o; o >>= 1) m = fmaxf(m, __shfl_xor_sync(0xffffffffu, m, o));
    __shared__ float sm[8];
    if ((threadIdx.x & 31) == 0) sm[threadIdx.x >> 5] = m;
    __syncthreads();
    if (threadIdx.x == 0) {
        float mm = sm[0];
        for (int i = 1; i < 8; i++) mm = fmaxf(mm, sm[i]);
        unsigned u = __float_as_uint(mm);
        u = (u & 0x80000000u) ? ~u : (u | 0x80000000u);
        atomicMax(out, u);
    }
}

__device__ __forceinline__ float unflip(unsigned u)
{
    return __uint_as_float((u & 0x80000000u) ? (u ^ 0x80000000u) : ~u);
}

// qp = ratio*(exp(dd - diag - rowmax) + eps), in place (tf32-rounded output)
__global__ void k_expq(float* __restrict__ dd, const float* __restrict__ q)
{
    size_t w   = ((size_t)blockIdx.x * blockDim.x + threadIdx.x) >> 5;
    int   lane = threadIdx.x & 31;
    float4* row = (float4*)(dd + w * 256);
    float4 v0 = row[lane];
    float4 v1 = row[lane + 32];
    float m = fmaxf(fmaxf(fmaxf(v0.x, v0.y), fmaxf(v0.z, v0.w)),
                    fmaxf(fmaxf(v1.x, v1.y), fmaxf(v1.z, v1.w)));
#pragma unroll
    for (int o = 16; o; o >>= 1) m = fmaxf(m, __shfl_xor_sync(0xffffffffu, m, o));
    float2 qq = ((const float2*)(q + w * 64))[lane];
    float ss = qq.x * qq.x + qq.y * qq.y;
#pragma unroll
    for (int o = 16; o; o >>= 1) ss += __shfl_xor_sync(0xffffffffu, ss, o);
    float c = 0.0625f * ss + m;
    v0.x = rtf(0.0625f * (expf(v0.x - c) + 1e-6f));
    v0.y = rtf(0.0625f * (expf(v0.y - c) + 1e-6f));
    v0.z = rtf(0.0625f * (expf(v0.z - c) + 1e-6f));
    v0.w = rtf(0.0625f * (expf(v0.w - c) + 1e-6f));
    v1.x = rtf(0.0625f * (expf(v1.x - c) + 1e-6f));
    v1.y = rtf(0.0625f * (expf(v1.y - c) + 1e-6f));
    v1.z = rtf(0.0625f * (expf(v1.z - c) + 1e-6f));
    v1.w = rtf(0.0625f * (expf(v1.w - c) + 1e-6f));
    row[lane] = v0; row[lane + 32] = v1;
}

// kp = ratio*(exp(dd - diag - globalmax) + eps), in place (tf32-rounded)
__global__ void k_expk(float* __restrict__ dd, const float* __restrict__ k,
                       const unsigned* __restrict__ gmax)
{
    size_t w   = ((size_t)blockIdx.x * blockDim.x + threadIdx.x) >> 5;
    int   lane = threadIdx.x & 31;
    float4* row = (float4*)(dd + w * 256);
    float4 v0 = row[lane];
    float4 v1 = row[lane + 32];
    float2 kk = ((const float2*)(k + w * 64))[lane];
    float ss = kk.x * kk.x + kk.y * kk.y;
#pragma unroll
    for (int o = 16; o; o >>= 1) ss += __shfl_xor_sync(0xffffffffu, ss, o);
    float c = 0.0625f * ss + unflip(*gmax);
    v0.x = rtf(0.0625f * (expf(v0.x - c) + 1e-6f));
    v0.y = rtf(0.0625f * (expf(v0.y - c) + 1e-6f));
    v0.z = rtf(0.0625f * (expf(v0.z - c) + 1e-6f));
    v0.w = rtf(0.0625f * (expf(v0.w - c) + 1e-6f));
    v1.x = rtf(0.0625f * (expf(v1.x - c) + 1e-6f));
    v1.y = rtf(0.0625f * (expf(v1.y - c) + 1e-6f));
    v1.z = rtf(0.0625f * (expf(v1.z - c) + 1e-6f));
    v1.w = rtf(0.0625f * (expf(v1.w - c) + 1e-6f));
    row[lane] = v0; row[lane + 32] = v1;
}

// ksum[b,h,m] = sum_l kp[b,l,h,m]
__global__ void k_ksum(const float* __restrict__ kp, float* __restrict__ ksum)
{
    int z = blockIdx.y;
    int b = z >> 4, h = z & 15;
    int m = threadIdx.x;
    size_t base = (size_t)b * 16777216 + (size_t)h * 256 + m;
    float s = 0.f;
    int l0 = blockIdx.x * 512;
    for (int l = l0; l < l0 + 512; l++) s += kp[base + (size_t)l * 4096];
    atomicAdd(&ksum[z * 256 + m], s);
}

// denom[r] = dot(qp[r,:], ksum[b,h,:]); warp per row
__global__ void k_denom(const float* __restrict__ qp, const float* __restrict__ ksum,
                        float* __restrict__ den)
{
    size_t w   = ((size_t)blockIdx.x * blockDim.x + threadIdx.x) >> 5;
    int   lane = threadIdx.x & 31;
    int   b    = (int)(w >> 16);
    int   h    = (int)(w & 15);
    const float4* row = (const float4*)(qp + w * 256);
    const float4* ks  = (const float4*)(ksum + ((size_t)b * 16 + h) * 256);
    float4 a0 = row[lane], a1 = row[lane + 32];
    float4 k0 = ks[lane],  k1 = ks[lane + 32];
    float s = a0.x * k0.x + a0.y * k0.y + a0.z * k0.z + a0.w * k0.w
            + a1.x * k1.x + a1.y * k1.y + a1.z * k1.z + a1.w * k1.w;
#pragma unroll
    for (int o = 16; o; o >>= 1) s += __shfl_xor_sync(0xffffffffu, s, o);
    if (lane == 0) den[w] = s;
}

// out = LN(a + r) * g + b ; one block per 1024-wide row
template<bool ROUND>
__global__ void k_ln(const float* __restrict__ a, const float* __restrict__ r,
                     const float* __restrict__ g, const float* __restrict__ b,
                     float* __restrict__ out)
{
    const int row = blockIdx.x;
    const int t   = threadIdx.x;
    const size_t base = (size_t)row * 1024;
    float4 xa = *(const float4*)(a + base + t * 4);
    float4 xr = *(const float4*)(r + base + t * 4);
    float4 s  = make_float4(xa.x + xr.x, xa.y + xr.y, xa.z + xr.z, xa.w + xr.w);
    float sum = s.x + s.y + s.z + s.w;
    float sq  = s.x * s.x + s.y * s.y + s.z * s.z + s.w * s.w;
#pragma unroll
    for (int o = 16; o; o >>= 1) {
        sum += __shfl_xor_sync(0xffffffffu, sum, o);
        sq  += __shfl_xor_sync(0xffffffffu, sq,  o);
    }
    __shared__ float ssum[8], ssq[8];
    __shared__ float s_mu, s_inv;
    int w = t >> 5;
    if ((t & 31) == 0) { ssum[w] = sum; ssq[w] = sq; }
    __syncthreads();
    if (t == 0) {
        float ts = 0.f, tq = 0.f;
        for (int i = 0; i < 8; i++) { ts += ssum[i]; tq += ssq[i]; }
        float mu  = ts * (1.f / 1024.f);
        float var = tq * (1.f / 1024.f) - mu * mu;
        s_mu = mu;
        s_inv = rsqrtf(var + 1e-6f);
    }
    __syncthreads();
    float mu = s_mu, inv = s_inv;
    float4 gg = *(const float4*)(g + t * 4);
    float4 bb = *(const float4*)(b + t * 4);
    float4 o = make_float4((s.x - mu) * inv * gg.x + bb.x,
                           (s.y - mu) * inv * gg.y + bb.y,
                           (s.z - mu) * inv * gg.z + bb.z,
                           (s.w - mu) * inv * gg.w + bb.w);
    if (ROUND) { o.x = rtf(o.x); o.y = rtf(o.y); o.z = rtf(o.z); o.w = rtf(o.w); }
    *(float4*)(out + base + t * 4) = o;
}

// ---------------- driver -----------------------------------------------------
extern "C" void kernel_launch(void* const* d_in, const int* in_sizes, int n_in,
                              void* d_out, int out_size)
{
    const float* x    = (const float*)d_in[0];
    const float* wq   = (const float*)d_in[1];
    const float* wk   = (const float*)d_in[2];
    const float* wv   = (const float*)d_in[3];
    const float* wo   = (const float*)d_in[4];
    const float* proj = (const float*)d_in[5];
    const float* ln1g = (const float*)d_in[6];
    const float* ln1b = (const float*)d_in[7];
    const float* ln2g = (const float*)d_in[8];
    const float* ln2b = (const float*)d_in[9];
    const float* w1   = (const float*)d_in[10];
    const float* b1   = (const float*)d_in[11];
    const float* w2   = (const float*)d_in[12];
    const float* b2   = (const float*)d_in[13];
    float* out = (float*)d_out;

    float *p_q, *p_k, *p_v, *p_qp, *p_kp, *p_kv, *p_ksum, *p_den;
    float *p_attn, *p_tmp, *p_out1, *p_h, *p_pT;
    float *p_xr, *p_rwq, *p_rwk, *p_rwv, *p_rwo, *p_rw1, *p_rw2;
    unsigned* p_kmax;
    cudaGetSymbolAddress((void**)&p_q,    g_q);
    cudaGetSymbolAddress((void**)&p_k,    g_k);
    cudaGetSymbolAddress((void**)&p_v,    g_v);
    cudaGetSymbolAddress((void**)&p_qp,   g_qp);
    cudaGetSymbolAddress((void**)&p_kp,   g_kp);
    cudaGetSymbolAddress((void**)&p_kv,   g_kv);
    cudaGetSymbolAddress((void**)&p_ksum, g_ksum);
    cudaGetSymbolAddress((void**)&p_den,  g_den);
    cudaGetSymbolAddress((void**)&p_attn, g_attn);
    cudaGetSymbolAddress((void**)&p_tmp,  g_tmp);
    cudaGetSymbolAddress((void**)&p_out1, g_out1);
    cudaGetSymbolAddress((void**)&p_h,    g_hbuf);
    cudaGetSymbolAddress((void**)&p_pT,   g_projT);
    cudaGetSymbolAddress((void**)&p_kmax, g_kmax);
    cudaGetSymbolAddress((void**)&p_xr,   g_xr);
    cudaGetSymbolAddress((void**)&p_rwq,  g_rwq);
    cudaGetSymbolAddress((void**)&p_rwk,  g_rwk);
    cudaGetSymbolAddress((void**)&p_rwv,  g_rwv);
    cudaGetSymbolAddress((void**)&p_rwo,  g_rwo);
    cudaGetSymbolAddress((void**)&p_rw1,  g_rw1);
    cudaGetSymbolAddress((void**)&p_rw2,  g_rw2);

    // tf32-round inputs once
    k_round4<<<(NT * DD / 4 + 255) / 256, 256>>>((const float4*)x,  (float4*)p_xr,  NT * DD / 4);
    k_round4<<<(DD * DD / 4 + 255) / 256, 256>>>((const float4*)wq, (float4*)p_rwq, DD * DD / 4);
    k_round4<<<(DD * DD / 4 + 255) / 256, 256>>>((const float4*)wk, (float4*)p_rwk, DD * DD / 4);
    k_round4<<<(DD * DD / 4 + 255) / 256, 256>>>((const float4*)wv, (float4*)p_rwv, DD * DD / 4);
    k_round4<<<(DD * DD / 4 + 255) / 256, 256>>>((const float4*)wo, (float4*)p_rwo, DD * DD / 4);
    k_round4<<<(DD * DFF / 4 + 255) / 256, 256>>>((const float4*)w1, (float4*)p_rw1, DD * DFF / 4);
    k_round4<<<(DD * DFF / 4 + 255) / 256, 256>>>((const float4*)w2, (float4*)p_rw2, DD * DFF / 4);
    k_projT<<<64, 256>>>(proj, p_pT);

    // q,k,v projections (outputs tf32-rounded: feed dd / kv GEMMs)
    tgemm<EPI_NONE, true><<<dim3(8, 128), 128>>>(p_xr, p_rwq, nullptr, p_q, NT, 1024, 1024);
    tgemm<EPI_NONE, true><<<dim3(8, 128), 128>>>(p_xr, p_rwk, nullptr, p_k, NT, 1024, 1024);
    tgemm<EPI_NONE, true><<<dim3(8, 128), 128>>>(p_xr, p_rwv, nullptr, p_v, NT, 1024, 1024);

    // dd = q_resh[262144,64] @ projT[64,256]  (raw fp32 out, exp rounds later)
    tgemm<EPI_NONE, false><<<dim3(2, 2048), 128>>>(p_q, p_pT, nullptr, p_qp, NR, 256, 64);
    tgemm<EPI_NONE, false><<<dim3(2, 2048), 128>>>(p_k, p_pT, nullptr, p_kp, NR, 256, 64);

    cudaMemsetAsync(p_kmax, 0, 4);
    cudaMemsetAsync(p_ksum, 0, BB * HH * MMF * sizeof(float));

    k_max<<<2048, 256>>>((const float4*)p_kp, (size_t)NR * 64, p_kmax);

    k_expq<<<NR / 8, 256>>>(p_qp, p_q);
    k_expk<<<NR / 8, 256>>>(p_kp, p_k, p_kmax);

    // kv[bh][256][64] = kp^T @ v : M=256 N=64 K=4096 (tf32, rounded out)
    tgemm_bh<true, false, true><<<dim3(1, 2, 64), 256>>>(
        p_kp, (size_t)16777216, (size_t)256, 4096,
        p_v,  (size_t)4194304,  (size_t)64,  1024,
        p_kv, (size_t)(16 * 16384), (size_t)16384, 64,
        nullptr, 0, 0, 0,
        256, 64, 4096);

    k_ksum<<<dim3(8, 64), 256>>>(p_kp, p_ksum);
    k_denom<<<NR / 8, 256>>>(p_qp, p_ksum, p_den);

    // attn = (qp @ kv) / denom : M=4096 N=64 K=256 (tf32, rounded out -> feeds wo)
    tgemm_bh<false, true, true><<<dim3(1, 32, 64), 256>>>(
        p_qp, (size_t)16777216, (size_t)256, 4096,
        p_kv, (size_t)(16 * 16384), (size_t)16384, 64,
        p_attn, (size_t)4194304, (size_t)64, 1024,
        p_den,  (size_t)65536,   (size_t)1,  16,
        4096, 64, 256);

    // attn_out = attn @ wo
    tgemm<EPI_NONE, false><<<dim3(8, 128), 128>>>(p_attn, p_rwo, nullptr, p_tmp, NT, 1024, 1024);

    // out1 = LN(x + attn_out)  (rounded: feeds FFN1)
    k_ln<true><<<NT, 256>>>(p_tmp, x, ln1g, ln1b, p_out1);

    // FFN
    tgemm<EPI_BIAS_ELU, true><<<dim3(32, 128), 128>>>(p_out1, p_rw1, b1, p_h, NT, DFF, 1024);
    tgemm<EPI_BIAS, false><<<dim3(8, 128), 128>>>(p_h, p_rw2, b2, p_tmp, NT, 1024, DFF);

    // out2 = LN(out1 + ffn)
    k_ln<false><<<NT, 256>>>(p_tmp, p_out1, ln2g, ln2b, out);
}

// round 6
// speedup vs baseline: 1.2549x; 1.0728x over previous
#include <cuda_runtime.h>
#include <math.h>

#define BB   4
#define LL   4096
#define DD   1024
#define HH   16
#define DHH  64
#define MMF  256
#define DFF  4096
#define NT   (BB*LL)      /* 16384 tokens  */
#define NR   (NT*HH)      /* 262144 (t,h) rows */

// ---------------- scratch (device globals; no allocation allowed) ----------
__device__ float g_q   [(size_t)NT*DD];
__device__ float g_k   [(size_t)NT*DD];
__device__ float g_v   [(size_t)NT*DD];
__device__ float g_qp  [(size_t)NR*MMF];
__device__ float g_kp  [(size_t)NR*MMF];
__device__ float g_kv  [(size_t)BB*HH*MMF*DHH];
__device__ float g_ksum[BB*HH*MMF];
__device__ float g_den [NR];
__device__ float g_attn[(size_t)NT*DD];
__device__ float g_tmp [(size_t)NT*DD];
__device__ float g_out1[(size_t)NT*DD];
__device__ float g_hbuf[(size_t)NT*DFF];
__device__ float g_projT[DHH*MMF];
__device__ unsigned g_kmax;
// tf32-rounded copies of harness inputs
__device__ float g_xr  [(size_t)NT*DD];
__device__ float g_rwq [DD*DD];
__device__ float g_rwk [DD*DD];
__device__ float g_rwv [DD*DD];
__device__ float g_rwo [DD*DD];
__device__ float g_rw1 [(size_t)DD*DFF];
__device__ float g_rw2 [(size_t)DD*DFF];

enum { EPI_NONE = 0, EPI_BIAS = 1, EPI_BIAS_ELU = 2 };

// ---------------- tf32 helpers ----------------------------------------------
__device__ __forceinline__ float rtf(float x)
{
    unsigned u;
    asm("cvt.rna.tf32.f32 %0, %1;" : "=r"(u) : "f"(x));
    return __uint_as_float(u);
}

__device__ __forceinline__ void mma_tf32(float* d, const unsigned* a,
                                         const unsigned* b)
{
    asm volatile(
        "mma.sync.aligned.m16n8k8.row.col.f32.tf32.tf32.f32 "
        "{%0,%1,%2,%3}, {%4,%5,%6,%7}, {%8,%9}, {%0,%1,%2,%3};\n"
        : "+f"(d[0]), "+f"(d[1]), "+f"(d[2]), "+f"(d[3])
        : "r"(a[0]), "r"(a[1]), "r"(a[2]), "r"(a[3]),
          "r"(b[0]), "r"(b[1]));
}

// ---------------- tf32 tensor-core GEMM: C[M,N] = A[M,K] @ B[K,N] ------------
// R2-proven pipeline: 128x128 block tile, BK=16, 256 threads = 8 warps
// (4m x 2n), warp tile 32x64, single-buffer smem, LDG->reg prefetch spanning
// compute, float4 STS staging. Inputs must be tf32(RNA)-rounded fp32.
#define APAD 20    /* As row stride (words) */
#define BPAD 136   /* Bs row stride (words) */

template<int EPI, bool ROUND>
__global__ __launch_bounds__(256, 2)
void tgemm(const float* __restrict__ A, const float* __restrict__ B,
           const float* __restrict__ bias, float* __restrict__ C,
           int M, int N, int K)
{
    __shared__ float As[128 * APAD];
    __shared__ float Bs[16 * BPAD];

    const int tid  = threadIdx.x;
    const int wid  = tid >> 5;
    const int lane = tid & 31;
    const int wm   = (wid >> 1) * 32;
    const int wn   = (wid & 1)  * 64;
    const size_t m0 = (size_t)blockIdx.y * 128;
    const int    n0 = blockIdx.x * 128;

    // staging indices (4-word contiguous -> float4 STS, verified conflict-free)
    const int arow = tid >> 2;
    const int acol = (tid & 3) << 2;
    const int brow = tid >> 5;
    const int bcol = lane << 2;

    float4 ra[2], rb[2];
    float acc[2][8][4];
#pragma unroll
    for (int mt = 0; mt < 2; mt++)
#pragma unroll
        for (int nt = 0; nt < 8; nt++)
#pragma unroll
            for (int i = 0; i < 4; i++) acc[mt][nt][i] = 0.f;

    const int iters = K >> 4;

    // prologue load
    ra[0] = *(const float4*)(A + (m0 + arow)      * K + acol);
    ra[1] = *(const float4*)(A + (m0 + arow + 64) * K + acol);
    rb[0] = *(const float4*)(B + (size_t)(brow)     * N + n0 + bcol);
    rb[1] = *(const float4*)(B + (size_t)(brow + 8) * N + n0 + bcol);

    for (int it = 0; it < iters; it++) {
        *(float4*)&As[arow * APAD + acol]        = ra[0];
        *(float4*)&As[(arow + 64) * APAD + acol] = ra[1];
        *(float4*)&Bs[brow * BPAD + bcol]        = rb[0];
        *(float4*)&Bs[(brow + 8) * BPAD + bcol]  = rb[1];
        __syncthreads();

        // prefetch next tile (spans whole compute phase)
        if (it + 1 < iters) {
            int k0 = (it + 1) << 4;
            ra[0] = *(const float4*)(A + (m0 + arow)      * K + k0 + acol);
            ra[1] = *(const float4*)(A + (m0 + arow + 64) * K + k0 + acol);
            rb[0] = *(const float4*)(B + (size_t)(k0 + brow)     * N + n0 + bcol);
            rb[1] = *(const float4*)(B + (size_t)(k0 + brow + 8) * N + n0 + bcol);
        }

#pragma unroll
        for (int ks = 0; ks < 16; ks += 8) {
            unsigned af[2][4], bf[8][2];
#pragma unroll
            for (int mt = 0; mt < 2; mt++) {
                int r = wm + mt * 16 + (lane >> 2);
                int c = ks + (lane & 3);
                af[mt][0] = __float_as_uint(As[r * APAD + c]);
                af[mt][1] = __float_as_uint(As[(r + 8) * APAD + c]);
                af[mt][2] = __float_as_uint(As[r * APAD + c + 4]);
                af[mt][3] = __float_as_uint(As[(r + 8) * APAD + c + 4]);
            }
#pragma unroll
            for (int nt = 0; nt < 8; nt++) {
                int c = wn + nt * 8 + (lane >> 2);
                int r = ks + (lane & 3);
                bf[nt][0] = __float_as_uint(Bs[r * BPAD + c]);
                bf[nt][1] = __float_as_uint(Bs[(r + 4) * BPAD + c]);
            }
#pragma unroll
            for (int mt = 0; mt < 2; mt++)
#pragma unroll
                for (int nt = 0; nt < 8; nt++)
                    mma_tf32(acc[mt][nt], af[mt], bf[nt]);
        }
        __syncthreads();
    }

#pragma unroll
    for (int mt = 0; mt < 2; mt++) {
#pragma unroll
        for (int nt = 0; nt < 8; nt++) {
            size_t row = m0 + wm + mt * 16 + (lane >> 2);
            int col = n0 + wn + nt * 8 + ((lane & 3) << 1);
            float2 lo = make_float2(acc[mt][nt][0], acc[mt][nt][1]);
            float2 hi = make_float2(acc[mt][nt][2], acc[mt][nt][3]);
            if (EPI == EPI_BIAS || EPI == EPI_BIAS_ELU) {
                float2 bb = *(const float2*)(bias + col);
                lo.x += bb.x; lo.y += bb.y;
                hi.x += bb.x; hi.y += bb.y;
            }
            if (EPI == EPI_BIAS_ELU) {
                lo.x = lo.x > 0.f ? lo.x : expm1f(lo.x);
                lo.y = lo.y > 0.f ? lo.y : expm1f(lo.y);
                hi.x = hi.x > 0.f ? hi.x : expm1f(hi.x);
                hi.y = hi.y > 0.f ? hi.y : expm1f(hi.y);
            }
            if (ROUND) {
                lo.x = rtf(lo.x); lo.y = rtf(lo.y);
                hi.x = rtf(hi.x); hi.y = rtf(hi.y);
            }
            *(float2*)(C + row * N + col)       = lo;
            *(float2*)(C + (row + 8) * N + col) = hi;
        }
    }
}

// ------------- tf32 batched strided GEMM over (b,h): C = op(A) @ B ----------
// (unchanged from R4 — proven correct/pass)
#define AT_PAD 136
#define BH_BPAD 72

template<bool TRANSA, bool DIV, bool ROUND>
__global__ __launch_bounds__(256, 2)
void tgemm_bh(const float* __restrict__ A, size_t sAb, size_t sAh, int lda,
              const float* __restrict__ B, size_t sBb, size_t sBh, int ldb,
              float* __restrict__ C, size_t sCb, size_t sCh, int ldc,
              const float* __restrict__ aux, size_t sXb, size_t sXh, int ldx,
              int M, int N, int K)
{
    __shared__ float As[128 * APAD];
    __shared__ float Bs[16 * BH_BPAD];

    const int z  = blockIdx.z;
    const int zb = z >> 4, zh = z & 15;
    const float* Ab = A + (size_t)zb * sAb + (size_t)zh * sAh;
    const float* Bb = B + (size_t)zb * sBb + (size_t)zh * sBh;
    float*       Cb = C + (size_t)zb * sCb + (size_t)zh * sCh;

    const int tid  = threadIdx.x;
    const int wid  = tid >> 5;
    const int lane = tid & 31;
    const int wm   = (wid >> 1) * 32;
    const int wn   = (wid & 1)  * 32;
    const int m0   = blockIdx.y * 128;
    const int n0   = blockIdx.x * 64;

    const int t_kr = tid >> 5;
    const int t_mc = lane << 2;
    const int n_row = tid & 127;
    const int n_kh  = (tid >> 7) << 3;
    const int b_kr = tid >> 4;
    const int b_nc = (tid & 15) << 2;

    float4 ra[2], rb1;
    float acc[2][4][4];
#pragma unroll
    for (int mt = 0; mt < 2; mt++)
#pragma unroll
        for (int nt = 0; nt < 4; nt++)
#pragma unroll
            for (int i = 0; i < 4; i++) acc[mt][nt][i] = 0.f;

    const int iters = K >> 4;

    auto ldA = [&](int k0) {
        if (TRANSA) {
            ra[0] = *(const float4*)(Ab + (size_t)(k0 + t_kr)     * lda + m0 + t_mc);
            ra[1] = *(const float4*)(Ab + (size_t)(k0 + t_kr + 8) * lda + m0 + t_mc);
        } else {
            ra[0] = *(const float4*)(Ab + (size_t)(m0 + n_row) * lda + k0 + n_kh);
            ra[1] = *(const float4*)(Ab + (size_t)(m0 + n_row) * lda + k0 + n_kh + 4);
        }
    };
    auto ldB = [&](int k0) {
        rb1 = *(const float4*)(Bb + (size_t)(k0 + b_kr) * ldb + n0 + b_nc);
    };

    ldA(0); ldB(0);

    for (int it = 0; it < iters; it++) {
        if (TRANSA) {
            *(float4*)&As[t_kr * AT_PAD + t_mc]       = ra[0];
            *(float4*)&As[(t_kr + 8) * AT_PAD + t_mc] = ra[1];
        } else {
            *(float4*)&As[n_row * APAD + n_kh]     = ra[0];
            *(float4*)&As[n_row * APAD + n_kh + 4] = ra[1];
        }
        *(float4*)&Bs[b_kr * BH_BPAD + b_nc] = rb1;
        __syncthreads();

        if (it + 1 < iters) { ldA((it + 1) << 4); ldB((it + 1) << 4); }

#pragma unroll
        for (int ks = 0; ks < 16; ks += 8) {
            unsigned af[2][4], bf[4][2];
#pragma unroll
            for (int mt = 0; mt < 2; mt++) {
                int r = wm + mt * 16 + (lane >> 2);
                int c = ks + (lane & 3);
                if (TRANSA) {
                    af[mt][0] = __float_as_uint(As[c * AT_PAD + r]);
                    af[mt][1] = __float_as_uint(As[c * AT_PAD + r + 8]);
                    af[mt][2] = __float_as_uint(As[(c + 4) * AT_PAD + r]);
                    af[mt][3] = __float_as_uint(As[(c + 4) * AT_PAD + r + 8]);
                } else {
                    af[mt][0] = __float_as_uint(As[r * APAD + c]);
                    af[mt][1] = __float_as_uint(As[(r + 8) * APAD + c]);
                    af[mt][2] = __float_as_uint(As[r * APAD + c + 4]);
                    af[mt][3] = __float_as_uint(As[(r + 8) * APAD + c + 4]);
                }
            }
#pragma unroll
            for (int nt = 0; nt < 4; nt++) {
                int c = wn + nt * 8 + (lane >> 2);
                int r = ks + (lane & 3);
                bf[nt][0] = __float_as_uint(Bs[r * BH_BPAD + c]);
                bf[nt][1] = __float_as_uint(Bs[(r + 4) * BH_BPAD + c]);
            }
#pragma unroll
            for (int mt = 0; mt < 2; mt++)
#pragma unroll
                for (int nt = 0; nt < 4; nt++)
                    mma_tf32(acc[mt][nt], af[mt], bf[nt]);
        }
        __syncthreads();
    }

#pragma unroll
    for (int mt = 0; mt < 2; mt++) {
        int row = m0 + wm + mt * 16 + (lane >> 2);
        float dv0 = 1.f, dv1 = 1.f;
        if (DIV) {
            dv0 = 1.f / aux[(size_t)zb * sXb + (size_t)zh * sXh + (size_t)row * ldx];
            dv1 = 1.f / aux[(size_t)zb * sXb + (size_t)zh * sXh + (size_t)(row + 8) * ldx];
        }
#pragma unroll
        for (int nt = 0; nt < 4; nt++) {
            int col = n0 + wn + nt * 8 + ((lane & 3) << 1);
            float2 lo = make_float2(acc[mt][nt][0] * dv0, acc[mt][nt][1] * dv0);
            float2 hi = make_float2(acc[mt][nt][2] * dv1, acc[mt][nt][3] * dv1);
            if (ROUND) {
                lo.x = rtf(lo.x); lo.y = rtf(lo.y);
                hi.x = rtf(hi.x); hi.y = rtf(hi.y);
            }
            *(float2*)(Cb + (size_t)row * ldc + col)       = lo;
            *(float2*)(Cb + (size_t)(row + 8) * ldc + col) = hi;
        }
    }
}

// ---------------- small helper kernels --------------------------------------
__global__ void k_round4(const float4* __restrict__ in, float4* __restrict__ out,
                         int n4)
{
    int i = blockIdx.x * 256 + threadIdx.x;
    if (i < n4) {
        float4 v = in[i];
        v.x = rtf(v.x); v.y = rtf(v.y); v.z = rtf(v.z); v.w = rtf(v.w);
        out[i] = v;
    }
}

__global__ void k_projT(const float* __restrict__ proj, float* __restrict__ pT)
{
    int i = blockIdx.x * 256 + threadIdx.x;     // 0..16383
    int m = i >> 6, k = i & 63;
    pT[k * 256 + m] = rtf(proj[i] * 0.35355339059327373f);
}

__global__ void k_max(const float4* __restrict__ d, size_t n4, unsigned* __restrict__ out)
{
    float m = -3.4e38f;
    for (size_t i = (size_t)blockIdx.x * blockDim.x + threadIdx.x; i < n4;
         i += (size_t)gridDim.x * blockDim.x) {
        float4 v = d[i];
        m = fmaxf(m, fmaxf(fmaxf(v.x, v.y), fmaxf(v.z, v.w)));
    }
#pragma unroll
    for (int o = 16; o; o >>= 1) m = fmaxf(m, __shfl_xor_sync(0xffffffffu, m, o));
    __shared__ float sm[8];
    if ((threadIdx.x & 31) == 0) sm[threadIdx.x >> 5] = m;
    __syncthreads();
    if (threadIdx.x == 0) {
        float mm = sm[0];
        for (int i = 1; i < 8; i++) mm = fmaxf(mm, sm[i]);
        unsigned u = __float_as_uint(mm);
        u = (u & 0x80000000u) ? ~u : (u | 0x80000000u);
        atomicMax(out, u);
    }
}

__device__ __forceinline__ float unflip(unsigned u)
{
    return __uint_as_float((u & 0x80000000u) ? (u ^ 0x80000000u) : ~u);
}

__global__ void k_expq(float* __restrict__ dd, const float* __restrict__ q)
{
    size_t w   = ((size_t)blockIdx.x * blockDim.x + threadIdx.x) >> 5;
    int   lane = threadIdx.x & 31;
    float4* row = (float4*)(dd + w * 256);
    float4 v0 = row[lane];
    float4 v1 = row[lane + 32];
    float m = fmaxf(fmaxf(fmaxf(v0.x, v0.y), fmaxf(v0.z, v0.w)),
                    fmaxf(fmaxf(v1.x, v1.y), fmaxf(v1.z, v1.w)));
#pragma unroll
    for (int o = 16; o; o >>= 1) m = fmaxf(m, __shfl_xor_sync(0xffffffffu, m, o));
    float2 qq = ((const float2*)(q + w * 64))[lane];
    float ss = qq.x * qq.x + qq.y * qq.y;
#pragma unroll
    for (int o = 16; o; o >>= 1) ss += __shfl_xor_sync(0xffffffffu, ss, o);
    float c = 0.0625f * ss + m;
    v0.x = rtf(0.0625f * (expf(v0.x - c) + 1e-6f));
    v0.y = rtf(0.0625f * (expf(v0.y - c) + 1e-6f));
    v0.z = rtf(0.0625f * (expf(v0.z - c) + 1e-6f));
    v0.w = rtf(0.0625f * (expf(v0.w - c) + 1e-6f));
    v1.x = rtf(0.0625f * (expf(v1.x - c) + 1e-6f));
    v1.y = rtf(0.0625f * (expf(v1.y - c) + 1e-6f));
    v1.z = rtf(0.0625f * (expf(v1.z - c) + 1e-6f));
    v1.w = rtf(0.0625f * (expf(v1.w - c) + 1e-6f));
    row[lane] = v0; row[lane + 32] = v1;
}

__global__ void k_expk(float* __restrict__ dd, const float* __restrict__ k,
                       const unsigned* __restrict__ gmax)
{
    size_t w   = ((size_t)blockIdx.x * blockDim.x + threadIdx.x) >> 5;
    int   lane = threadIdx.x & 31;
    float4* row = (float4*)(dd + w * 256);
    float4 v0 = row[lane];
    float4 v1 = row[lane + 32];
    float2 kk = ((const float2*)(k + w * 64))[lane];
    float ss = kk.x * kk.x + kk.y * kk.y;
#pragma unroll
    for (int o = 16; o; o >>= 1) ss += __shfl_xor_sync(0xffffffffu, ss, o);
    float c = 0.0625f * ss + unflip(*gmax);
    v0.x = rtf(0.0625f * (expf(v0.x - c) + 1e-6f));
    v0.y = rtf(0.0625f * (expf(v0.y - c) + 1e-6f));
    v0.z = rtf(0.0625f * (expf(v0.z - c) + 1e-6f));
    v0.w = rtf(0.0625f * (expf(v0.w - c) + 1e-6f));
    v1.x = rtf(0.0625f * (expf(v1.x - c) + 1e-6f));
    v1.y = rtf(0.0625f * (expf(v1.y - c) + 1e-6f));
    v1.z = rtf(0.0625f * (expf(v1.z - c) + 1e-6f));
    v1.w = rtf(0.0625f * (expf(v1.w - c) + 1e-6f));
    row[lane] = v0; row[lane + 32] = v1;
}

__global__ void k_ksum(const float* __restrict__ kp, float* __restrict__ ksum)
{
    int z = blockIdx.y;
    int b = z >> 4, h = z & 15;
    int m = threadIdx.x;
    size_t base = (size_t)b * 16777216 + (size_t)h * 256 + m;
    float s = 0.f;
    int l0 = blockIdx.x * 512;
    for (int l = l0; l < l0 + 512; l++) s += kp[base + (size_t)l * 4096];
    atomicAdd(&ksum[z * 256 + m], s);
}

__global__ void k_denom(const float* __restrict__ qp, const float* __restrict__ ksum,
                        float* __restrict__ den)
{
    size_t w   = ((size_t)blockIdx.x * blockDim.x + threadIdx.x) >> 5;
    int   lane = threadIdx.x & 31;
    int   b    = (int)(w >> 16);
    int   h    = (int)(w & 15);
    const float4* row = (const float4*)(qp + w * 256);
    const float4* ks  = (const float4*)(ksum + ((size_t)b * 16 + h) * 256);
    float4 a0 = row[lane], a1 = row[lane + 32];
    float4 k0 = ks[lane],  k1 = ks[lane + 32];
    float s = a0.x * k0.x + a0.y * k0.y + a0.z * k0.z + a0.w * k0.w
            + a1.x * k1.x + a1.y * k1.y + a1.z * k1.z + a1.w * k1.w;
#pragma unroll
    for (int o = 16; o; o >>= 1) s += __shfl_xor_sync(0xffffffffu, s, o);
    if (lane == 0) den[w] = s;
}

template<bool ROUND>
__global__ void k_ln(const float* __restrict__ a, const float* __restrict__ r,
                     const float* __restrict__ g, const float* __restrict__ b,
                     float* __restrict__ out)
{
    const int row = blockIdx.x;
    const int t   = threadIdx.x;
    const size_t base = (size_t)row * 1024;
    float4 xa = *(const float4*)(a + base + t * 4);
    float4 xr = *(const float4*)(r + base + t * 4);
    float4 s  = make_float4(xa.x + xr.x, xa.y + xr.y, xa.z + xr.z, xa.w + xr.w);
    float sum = s.x + s.y + s.z + s.w;
    float sq  = s.x * s.x + s.y * s.y + s.z * s.z + s.w * s.w;
#pragma unroll
    for (int o = 16; o; o >>= 1) {
        sum += __shfl_xor_sync(0xffffffffu, sum, o);
        sq  += __shfl_xor_sync(0xffffffffu, sq,  o);
    }
    __shared__ float ssum[8], ssq[8];
    __shared__ float s_mu, s_inv;
    int w = t >> 5;
    if ((t & 31) == 0) { ssum[w] = sum; ssq[w] = sq; }
    __syncthreads();
    if (t == 0) {
        float ts = 0.f, tq = 0.f;
        for (int i = 0; i < 8; i++) { ts += ssum[i]; tq += ssq[i]; }
        float mu  = ts * (1.f / 1024.f);
        float var = tq * (1.f / 1024.f) - mu * mu;
        s_mu = mu;
        s_inv = rsqrtf(var + 1e-6f);
    }
    __syncthreads();
    float mu = s_mu, inv = s_inv;
    float4 gg = *(const float4*)(g + t * 4);
    float4 bb = *(const float4*)(b + t * 4);
    float4 o = make_float4((s.x - mu) * inv * gg.x + bb.x,
                           (s.y - mu) * inv * gg.y + bb.y,
                           (s.z - mu) * inv * gg.z + bb.z,
                           (s.w - mu) * inv * gg.w + bb.w);
    if (ROUND) { o.x = rtf(o.x); o.y = rtf(o.y); o.z = rtf(o.z); o.w = rtf(o.w); }
    *(float4*)(out + base + t * 4) = o;
}

// ---------------- driver -----------------------------------------------------
extern "C" void kernel_launch(void* const* d_in, const int* in_sizes, int n_in,
                              void* d_out, int out_size)
{
    const float* x    = (const float*)d_in[0];
    const float* wq   = (const float*)d_in[1];
    const float* wk   = (const float*)d_in[2];
    const float* wv   = (const float*)d_in[3];
    const float* wo   = (const float*)d_in[4];
    const float* proj = (const float*)d_in[5];
    const float* ln1g = (const float*)d_in[6];
    const float* ln1b = (const float*)d_in[7];
    const float* ln2g = (const float*)d_in[8];
    const float* ln2b = (const float*)d_in[9];
    const float* w1   = (const float*)d_in[10];
    const float* b1   = (const float*)d_in[11];
    const float* w2   = (const float*)d_in[12];
    const float* b2   = (const float*)d_in[13];
    float* out = (float*)d_out;

    float *p_q, *p_k, *p_v, *p_qp, *p_kp, *p_kv, *p_ksum, *p_den;
    float *p_attn, *p_tmp, *p_out1, *p_h, *p_pT;
    float *p_xr, *p_rwq, *p_rwk, *p_rwv, *p_rwo, *p_rw1, *p_rw2;
    unsigned* p_kmax;
    cudaGetSymbolAddress((void**)&p_q,    g_q);
    cudaGetSymbolAddress((void**)&p_k,    g_k);
    cudaGetSymbolAddress((void**)&p_v,    g_v);
    cudaGetSymbolAddress((void**)&p_qp,   g_qp);
    cudaGetSymbolAddress((void**)&p_kp,   g_kp);
    cudaGetSymbolAddress((void**)&p_kv,   g_kv);
    cudaGetSymbolAddress((void**)&p_ksum, g_ksum);
    cudaGetSymbolAddress((void**)&p_den,  g_den);
    cudaGetSymbolAddress((void**)&p_attn, g_attn);
    cudaGetSymbolAddress((void**)&p_tmp,  g_tmp);
    cudaGetSymbolAddress((void**)&p_out1, g_out1);
    cudaGetSymbolAddress((void**)&p_h,    g_hbuf);
    cudaGetSymbolAddress((void**)&p_pT,   g_projT);
    cudaGetSymbolAddress((void**)&p_kmax, g_kmax);
    cudaGetSymbolAddress((void**)&p_xr,   g_xr);
    cudaGetSymbolAddress((void**)&p_rwq,  g_rwq);
    cudaGetSymbolAddress((void**)&p_rwk,  g_rwk);
    cudaGetSymbolAddress((void**)&p_rwv,  g_rwv);
    cudaGetSymbolAddress((void**)&p_rwo,  g_rwo);
    cudaGetSymbolAddress((void**)&p_rw1,  g_rw1);
    cudaGetSymbolAddress((void**)&p_rw2,  g_rw2);

    // tf32-round inputs once
    k_round4<<<(NT * DD / 4 + 255) / 256, 256>>>((const float4*)x,  (float4*)p_xr,  NT * DD / 4);
    k_round4<<<(DD * DD / 4 + 255) / 256, 256>>>((const float4*)wq, (float4*)p_rwq, DD * DD / 4);
    k_round4<<<(DD * DD / 4 + 255) / 256, 256>>>((const float4*)wk, (float4*)p_rwk, DD * DD / 4);
    k_round4<<<(DD * DD / 4 + 255) / 256, 256>>>((const float4*)wv, (float4*)p_rwv, DD * DD / 4);
    k_round4<<<(DD * DD / 4 + 255) / 256, 256>>>((const float4*)wo, (float4*)p_rwo, DD * DD / 4);
    k_round4<<<(DD * DFF / 4 + 255) / 256, 256>>>((const float4*)w1, (float4*)p_rw1, DD * DFF / 4);
    k_round4<<<(DD * DFF / 4 + 255) / 256, 256>>>((const float4*)w2, (float4*)p_rw2, DD * DFF / 4);
    k_projT<<<64, 256>>>(proj, p_pT);

    // q,k,v projections (outputs tf32-rounded: feed dd / kv GEMMs)
    tgemm<EPI_NONE, true><<<dim3(8, 128), 256>>>(p_xr, p_rwq, nullptr, p_q, NT, 1024, 1024);
    tgemm<EPI_NONE, true><<<dim3(8, 128), 256>>>(p_xr, p_rwk, nullptr, p_k, NT, 1024, 1024);
    tgemm<EPI_NONE, true><<<dim3(8, 128), 256>>>(p_xr, p_rwv, nullptr, p_v, NT, 1024, 1024);

    // dd = q_resh[262144,64] @ projT[64,256]  (raw fp32 out, exp rounds later)
    tgemm<EPI_NONE, false><<<dim3(2, 2048), 256>>>(p_q, p_pT, nullptr, p_qp, NR, 256, 64);
    tgemm<EPI_NONE, false><<<dim3(2, 2048), 256>>>(p_k, p_pT, nullptr, p_kp, NR, 256, 64);

    cudaMemsetAsync(p_kmax, 0, 4);
    cudaMemsetAsync(p_ksum, 0, BB * HH * MMF * sizeof(float));

    k_max<<<2048, 256>>>((const float4*)p_kp, (size_t)NR * 64, p_kmax);
    k_expq<<<NR / 8, 256>>>(p_qp, p_q);
    k_expk<<<NR / 8, 256>>>(p_kp, p_k, p_kmax);

    // kv[bh][256][64] = kp^T @ v : M=256 N=64 K=4096 (tf32, rounded out)
    tgemm_bh<true, false, true><<<dim3(1, 2, 64), 256>>>(
        p_kp, (size_t)16777216, (size_t)256, 4096,
        p_v,  (size_t)4194304,  (size_t)64,  1024,
        p_kv, (size_t)(16 * 16384), (size_t)16384, 64,
        nullptr, 0, 0, 0,
        256, 64, 4096);

    k_ksum<<<dim3(8, 64), 256>>>(p_kp, p_ksum);
    k_denom<<<NR / 8, 256>>>(p_qp, p_ksum, p_den);

    // attn = (qp @ kv) / denom : M=4096 N=64 K=256 (tf32, rounded out)
    tgemm_bh<false, true, true><<<dim3(1, 32, 64), 256>>>(
        p_qp, (size_t)16777216, (size_t)256, 4096,
        p_kv, (size_t)(16 * 16384), (size_t)16384, 64,
        p_attn, (size_t)4194304, (size_t)64, 1024,
        p_den,  (size_t)65536,   (size_t)1,  16,
        4096, 64, 256);

    // attn_out = attn @ wo
    tgemm<EPI_NONE, false><<<dim3(8, 128), 256>>>(p_attn, p_rwo, nullptr, p_tmp, NT, 1024, 1024);

    // out1 = LN(x + attn_out)  (rounded: feeds FFN1)
    k_ln<true><<<NT, 256>>>(p_tmp, x, ln1g, ln1b, p_out1);

    // FFN
    tgemm<EPI_BIAS_ELU, true><<<dim3(32, 128), 256>>>(p_out1, p_rw1, b1, p_h, NT, DFF, 1024);
    tgemm<EPI_BIAS, false><<<dim3(8, 128), 256>>>(p_h, p_rw2, b2, p_tmp, NT, 1024, DFF);

    // out2 = LN(out1 + ffn)
    k_ln<false><<<NT, 256>>>(p_tmp, p_out1, ln2g, ln2b, out);
}

// round 7
// speedup vs baseline: 1.3740x; 1.0949x over previous
#include <cuda_runtime.h>
#include <cuda_fp16.h>
#include <math.h>
#include <stdint.h>

#define BB   4
#define LL   4096
#define DD   1024
#define HH   16
#define DHH  64
#define MMF  256
#define DFF  4096
#define NT   (BB*LL)      /* 16384 tokens  */
#define NR   (NT*HH)      /* 262144 (t,h) rows */

// ---------------- scratch (device globals; no allocation allowed) ----------
__device__ float  g_v    [(size_t)NT*DD];       // fp32 (feeds tf32 kv GEMM)
__device__ float  g_qp   [(size_t)NR*MMF];      // dd_q -> qp (fp32)
__device__ float  g_kp   [(size_t)NR*MMF];      // dd_k -> kp (fp32)
__device__ float  g_kv   [(size_t)BB*HH*MMF*DHH];
__device__ float  g_ksum [BB*HH*MMF];
__device__ float  g_den  [NR];
__device__ float  g_tmp  [(size_t)NT*DD];
__device__ float  g_out1 [(size_t)NT*DD];       // fp32 residual copy
__device__ unsigned g_kmax;
// fp16 operand buffers
__device__ __half g_xh   [(size_t)NT*DD];
__device__ __half g_qh   [(size_t)NT*DD];
__device__ __half g_kh   [(size_t)NT*DD];
__device__ __half g_out1h[(size_t)NT*DD];
__device__ __half g_attnh[(size_t)NT*DD];
__device__ __half g_hh   [(size_t)NT*DFF];
__device__ __half g_projh[MMF*DHH];             // [N=256][K=64], * dn
__device__ __half g_wqT  [DD*DD];               // [N][K]
__device__ __half g_wkT  [DD*DD];
__device__ __half g_wvT  [DD*DD];
__device__ __half g_woT  [DD*DD];
__device__ __half g_w1T  [(size_t)DFF*DD];      // [DFF][D]
__device__ __half g_w2T  [(size_t)DD*DFF];      // [D][DFF]

enum { EPI_NONE = 0, EPI_BIAS = 1, EPI_BIAS_ELU = 2 };

// ---------------- helpers ----------------------------------------------------
__device__ __forceinline__ float rtf(float x)
{
    unsigned u;
    asm("cvt.rna.tf32.f32 %0, %1;" : "=r"(u) : "f"(x));
    return __uint_as_float(u);
}

__device__ __forceinline__ void mma_tf32(float* d, const unsigned* a,
                                         const unsigned* b)
{
    asm volatile(
        "mma.sync.aligned.m16n8k8.row.col.f32.tf32.tf32.f32 "
        "{%0,%1,%2,%3}, {%4,%5,%6,%7}, {%8,%9}, {%0,%1,%2,%3};\n"
        : "+f"(d[0]), "+f"(d[1]), "+f"(d[2]), "+f"(d[3])
        : "r"(a[0]), "r"(a[1]), "r"(a[2]), "r"(a[3]),
          "r"(b[0]), "r"(b[1]));
}

__device__ __forceinline__ void mma_f16(float* d, const unsigned* a,
                                        const unsigned* b)
{
    asm volatile(
        "mma.sync.aligned.m16n8k16.row.col.f32.f16.f16.f32 "
        "{%0,%1,%2,%3}, {%4,%5,%6,%7}, {%8,%9}, {%0,%1,%2,%3};\n"
        : "+f"(d[0]), "+f"(d[1]), "+f"(d[2]), "+f"(d[3])
        : "r"(a[0]), "r"(a[1]), "r"(a[2]), "r"(a[3]),
          "r"(b[0]), "r"(b[1]));
}

// ---------------- fp16 tensor-core GEMM: C[M,N] = A[M,K] @ B^T ----------------
// A: [M][K] fp16 row-major.  B: [N][K] fp16 (pre-transposed weights).
// 128x128 block tile, BK=32, 256 threads = 8 warps (4m x 2n), warp tile 32x64
// via m16n8k16. Single-buffer smem + LDG->reg prefetch (proven pipeline).
// As/Bs row stride = 40 halves (80B): fragment LDS.32 banks (20r + j) mod 32
// are all-distinct -> conflict-free.
#define HS 40

template<int EPI, typename OutT, bool RND>
__global__ __launch_bounds__(256, 2)
void hgemm(const __half* __restrict__ A, const __half* __restrict__ B,
           const float* __restrict__ bias, OutT* __restrict__ C,
           int M, int N, int K)
{
    __shared__ __align__(16) __half As[128 * HS];
    __shared__ __align__(16) __half Bs[128 * HS];

    const int tid  = threadIdx.x;
    const int wid  = tid >> 5;
    const int lane = tid & 31;
    const int wm   = (wid >> 1) * 32;
    const int wn   = (wid & 1)  * 64;
    const size_t m0 = (size_t)blockIdx.y * 128;
    const int    n0 = blockIdx.x * 128;

    // staging: 512 chunks of 16B per tile; thread handles chunks tid, tid+256
    const int r0 = tid >> 1;                 // chunk tid    : row tid>>2 ... use explicit
    (void)r0;
    const int ar0 = tid >> 2,          aq0 = (tid & 3) << 3;
    const int ar1 = (tid + 256) >> 2,  aq1 = ((tid + 256) & 3) << 3;

    uint4 ra0, ra1, rb0, rb1;
    float acc[2][8][4];
#pragma unroll
    for (int mt = 0; mt < 2; mt++)
#pragma unroll
        for (int nt = 0; nt < 8; nt++)
#pragma unroll
            for (int i = 0; i < 4; i++) acc[mt][nt][i] = 0.f;

    const int iters = K >> 5;

    ra0 = *(const uint4*)(A + (m0 + ar0) * K + aq0);
    ra1 = *(const uint4*)(A + (m0 + ar1) * K + aq1);
    rb0 = *(const uint4*)(B + (size_t)(n0 + ar0) * K + aq0);
    rb1 = *(const uint4*)(B + (size_t)(n0 + ar1) * K + aq1);

    for (int it = 0; it < iters; it++) {
        *(uint4*)&As[ar0 * HS + aq0] = ra0;
        *(uint4*)&As[ar1 * HS + aq1] = ra1;
        *(uint4*)&Bs[ar0 * HS + aq0] = rb0;
        *(uint4*)&Bs[ar1 * HS + aq1] = rb1;
        __syncthreads();

        if (it + 1 < iters) {
            int k0 = (it + 1) << 5;
            ra0 = *(const uint4*)(A + (m0 + ar0) * K + k0 + aq0);
            ra1 = *(const uint4*)(A + (m0 + ar1) * K + k0 + aq1);
            rb0 = *(const uint4*)(B + (size_t)(n0 + ar0) * K + k0 + aq0);
            rb1 = *(const uint4*)(B + (size_t)(n0 + ar1) * K + k0 + aq1);
        }

#pragma unroll
        for (int ks = 0; ks < 2; ks++) {
            const int c2 = (ks << 4) + ((lane & 3) << 1);
            unsigned af[2][4], bf[8][2];
#pragma unroll
            for (int mt = 0; mt < 2; mt++) {
                int r = wm + mt * 16 + (lane >> 2);
                af[mt][0] = *(const unsigned*)&As[r * HS + c2];
                af[mt][1] = *(const unsigned*)&As[(r + 8) * HS + c2];
                af[mt][2] = *(const unsigned*)&As[r * HS + c2 + 8];
                af[mt][3] = *(const unsigned*)&As[(r + 8) * HS + c2 + 8];
            }
#pragma unroll
            for (int nt = 0; nt < 8; nt++) {
                int cn = wn + nt * 8 + (lane >> 2);
                bf[nt][0] = *(const unsigned*)&Bs[cn * HS + c2];
                bf[nt][1] = *(const unsigned*)&Bs[cn * HS + c2 + 8];
            }
#pragma unroll
            for (int mt = 0; mt < 2; mt++)
#pragma unroll
                for (int nt = 0; nt < 8; nt++)
                    mma_f16(acc[mt][nt], af[mt], bf[nt]);
        }
        __syncthreads();
    }

#pragma unroll
    for (int mt = 0; mt < 2; mt++) {
#pragma unroll
        for (int nt = 0; nt < 8; nt++) {
            size_t row = m0 + wm + mt * 16 + (lane >> 2);
            int col = n0 + wn + nt * 8 + ((lane & 3) << 1);
            float2 lo = make_float2(acc[mt][nt][0], acc[mt][nt][1]);
            float2 hi = make_float2(acc[mt][nt][2], acc[mt][nt][3]);
            if (EPI == EPI_BIAS || EPI == EPI_BIAS_ELU) {
                float2 bb = *(const float2*)(bias + col);
                lo.x += bb.x; lo.y += bb.y;
                hi.x += bb.x; hi.y += bb.y;
            }
            if (EPI == EPI_BIAS_ELU) {
                lo.x = lo.x > 0.f ? lo.x : expm1f(lo.x);
                lo.y = lo.y > 0.f ? lo.y : expm1f(lo.y);
                hi.x = hi.x > 0.f ? hi.x : expm1f(hi.x);
                hi.y = hi.y > 0.f ? hi.y : expm1f(hi.y);
            }
            if (sizeof(OutT) == 2) {
                __half2* p0 = (__half2*)((__half*)C + row * N + col);
                __half2* p1 = (__half2*)((__half*)C + (row + 8) * N + col);
                *p0 = __floats2half2_rn(lo.x, lo.y);
                *p1 = __floats2half2_rn(hi.x, hi.y);
            } else {
                if (RND) {
                    lo.x = rtf(lo.x); lo.y = rtf(lo.y);
                    hi.x = rtf(hi.x); hi.y = rtf(hi.y);
                }
                *(float2*)((float*)C + row * N + col)       = lo;
                *(float2*)((float*)C + (row + 8) * N + col) = hi;
            }
        }
    }
}

// ------------- tf32 batched strided GEMM over (b,h): C = op(A) @ B ----------
// (proven R4/R6 kernel; OutT added for fp16 attn output)
#define APAD 20
#define AT_PAD 136
#define BH_BPAD 72

template<bool TRANSA, bool DIV, bool RND, typename OutT>
__global__ __launch_bounds__(256, 2)
void tgemm_bh(const float* __restrict__ A, size_t sAb, size_t sAh, int lda,
              const float* __restrict__ B, size_t sBb, size_t sBh, int ldb,
              OutT* __restrict__ C, size_t sCb, size_t sCh, int ldc,
              const float* __restrict__ aux, size_t sXb, size_t sXh, int ldx,
              int M, int N, int K)
{
    __shared__ float As[128 * APAD];
    __shared__ float Bs[16 * BH_BPAD];

    const int z  = blockIdx.z;
    const int zb = z >> 4, zh = z & 15;
    const float* Ab = A + (size_t)zb * sAb + (size_t)zh * sAh;
    const float* Bb = B + (size_t)zb * sBb + (size_t)zh * sBh;
    OutT*        Cb = C + (size_t)zb * sCb + (size_t)zh * sCh;

    const int tid  = threadIdx.x;
    const int wid  = tid >> 5;
    const int lane = tid & 31;
    const int wm   = (wid >> 1) * 32;
    const int wn   = (wid & 1)  * 32;
    const int m0   = blockIdx.y * 128;
    const int n0   = blockIdx.x * 64;

    const int t_kr = tid >> 5;
    const int t_mc = lane << 2;
    const int n_row = tid & 127;
    const int n_kh  = (tid >> 7) << 3;
    const int b_kr = tid >> 4;
    const int b_nc = (tid & 15) << 2;

    float4 ra[2], rb1;
    float acc[2][4][4];
#pragma unroll
    for (int mt = 0; mt < 2; mt++)
#pragma unroll
        for (int nt = 0; nt < 4; nt++)
#pragma unroll
            for (int i = 0; i < 4; i++) acc[mt][nt][i] = 0.f;

    const int iters = K >> 4;

    auto ldA = [&](int k0) {
        if (TRANSA) {
            ra[0] = *(const float4*)(Ab + (size_t)(k0 + t_kr)     * lda + m0 + t_mc);
            ra[1] = *(const float4*)(Ab + (size_t)(k0 + t_kr + 8) * lda + m0 + t_mc);
        } else {
            ra[0] = *(const float4*)(Ab + (size_t)(m0 + n_row) * lda + k0 + n_kh);
            ra[1] = *(const float4*)(Ab + (size_t)(m0 + n_row) * lda + k0 + n_kh + 4);
        }
    };
    auto ldB = [&](int k0) {
        rb1 = *(const float4*)(Bb + (size_t)(k0 + b_kr) * ldb + n0 + b_nc);
    };

    ldA(0); ldB(0);

    for (int it = 0; it < iters; it++) {
        if (TRANSA) {
            *(float4*)&As[t_kr * AT_PAD + t_mc]       = ra[0];
            *(float4*)&As[(t_kr + 8) * AT_PAD + t_mc] = ra[1];
        } else {
            *(float4*)&As[n_row * APAD + n_kh]     = ra[0];
            *(float4*)&As[n_row * APAD + n_kh + 4] = ra[1];
        }
        *(float4*)&Bs[b_kr * BH_BPAD + b_nc] = rb1;
        __syncthreads();

        if (it + 1 < iters) { ldA((it + 1) << 4); ldB((it + 1) << 4); }

#pragma unroll
        for (int ks = 0; ks < 16; ks += 8) {
            unsigned af[2][4], bf[4][2];
#pragma unroll
            for (int mt = 0; mt < 2; mt++) {
                int r = wm + mt * 16 + (lane >> 2);
                int c = ks + (lane & 3);
                if (TRANSA) {
                    af[mt][0] = __float_as_uint(As[c * AT_PAD + r]);
                    af[mt][1] = __float_as_uint(As[c * AT_PAD + r + 8]);
                    af[mt][2] = __float_as_uint(As[(c + 4) * AT_PAD + r]);
                    af[mt][3] = __float_as_uint(As[(c + 4) * AT_PAD + r + 8]);
                } else {
                    af[mt][0] = __float_as_uint(As[r * APAD + c]);
                    af[mt][1] = __float_as_uint(As[(r + 8) * APAD + c]);
                    af[mt][2] = __float_as_uint(As[r * APAD + c + 4]);
                    af[mt][3] = __float_as_uint(As[(r + 8) * APAD + c + 4]);
                }
            }
#pragma unroll
            for (int nt = 0; nt < 4; nt++) {
                int c = wn + nt * 8 + (lane >> 2);
                int r = ks + (lane & 3);
                bf[nt][0] = __float_as_uint(Bs[r * BH_BPAD + c]);
                bf[nt][1] = __float_as_uint(Bs[(r + 4) * BH_BPAD + c]);
            }
#pragma unroll
            for (int mt = 0; mt < 2; mt++)
#pragma unroll
                for (int nt = 0; nt < 4; nt++)
                    mma_tf32(acc[mt][nt], af[mt], bf[nt]);
        }
        __syncthreads();
    }

#pragma unroll
    for (int mt = 0; mt < 2; mt++) {
        int row = m0 + wm + mt * 16 + (lane >> 2);
        float dv0 = 1.f, dv1 = 1.f;
        if (DIV) {
            dv0 = 1.f / aux[(size_t)zb * sXb + (size_t)zh * sXh + (size_t)row * ldx];
            dv1 = 1.f / aux[(size_t)zb * sXb + (size_t)zh * sXh + (size_t)(row + 8) * ldx];
        }
#pragma unroll
        for (int nt = 0; nt < 4; nt++) {
            int col = n0 + wn + nt * 8 + ((lane & 3) << 1);
            float2 lo = make_float2(acc[mt][nt][0] * dv0, acc[mt][nt][1] * dv0);
            float2 hi = make_float2(acc[mt][nt][2] * dv1, acc[mt][nt][3] * dv1);
            if (sizeof(OutT) == 2) {
                *(__half2*)((__half*)Cb + (size_t)row * ldc + col)       = __floats2half2_rn(lo.x, lo.y);
                *(__half2*)((__half*)Cb + (size_t)(row + 8) * ldc + col) = __floats2half2_rn(hi.x, hi.y);
            } else {
                if (RND) {
                    lo.x = rtf(lo.x); lo.y = rtf(lo.y);
                    hi.x = rtf(hi.x); hi.y = rtf(hi.y);
                }
                *(float2*)((float*)Cb + (size_t)row * ldc + col)       = lo;
                *(float2*)((float*)Cb + (size_t)(row + 8) * ldc + col) = hi;
            }
        }
    }
}

// ---------------- small helper kernels --------------------------------------
__global__ void k_half4(const float4* __restrict__ in, __half2* __restrict__ out,
                        int n4)
{
    int i = blockIdx.x * 256 + threadIdx.x;
    if (i < n4) {
        float4 v = in[i];
        out[2 * i]     = __floats2half2_rn(v.x, v.y);
        out[2 * i + 1] = __floats2half2_rn(v.z, v.w);
    }
}

// out[n][k] = fp16(in[k][n]); grid (N/32, K/32), block (32,8)
__global__ void k_transH(const float* __restrict__ in, __half* __restrict__ out,
                         int K, int N)
{
    __shared__ float t[32][33];
    const int n0 = blockIdx.x * 32, k0 = blockIdx.y * 32;
#pragma unroll
    for (int i = 0; i < 4; i++) {
        int kk = threadIdx.y + i * 8;
        t[kk][threadIdx.x] = in[(size_t)(k0 + kk) * N + n0 + threadIdx.x];
    }
    __syncthreads();
#pragma unroll
    for (int i = 0; i < 4; i++) {
        int nn = threadIdx.y + i * 8;
        out[(size_t)(n0 + nn) * K + k0 + threadIdx.x] = __float2half(t[threadIdx.x][nn]);
    }
}

__global__ void k_projH(const float* __restrict__ proj, __half* __restrict__ ph)
{
    int i = blockIdx.x * 256 + threadIdx.x;     // 0..16383
    if (i < MMF * DHH)
        ph[i] = __float2half(proj[i] * 0.35355339059327373f);
}

__global__ void k_max(const float4* __restrict__ d, size_t n4, unsigned* __restrict__ out)
{
    float m = -3.4e38f;
    for (size_t i = (size_t)blockIdx.x * blockDim.x + threadIdx.x; i < n4;
         i += (size_t)gridDim.x * blockDim.x) {
        float4 v = d[i];
        m = fmaxf(m, fmaxf(fmaxf(v.x, v.y), fmaxf(v.z, v.w)));
    }
#pragma unroll
    for (int o = 16; o; o >>= 1) m = fmaxf(m, __shfl_xor_sync(0xffffffffu, m, o));
    __shared__ float sm[8];
    if ((threadIdx.x & 31) == 0) sm[threadIdx.x >> 5] = m;
    __syncthreads();
    if (threadIdx.x == 0) {
        float mm = sm[0];
        for (int i = 1; i < 8; i++) mm = fmaxf(mm, sm[i]);
        unsigned u = __float_as_uint(mm);
        u = (u & 0x80000000u) ? ~u : (u | 0x80000000u);
        atomicMax(out, u);
    }
}

__device__ __forceinline__ float unflip(unsigned u)
{
    return __uint_as_float((u & 0x80000000u) ? (u ^ 0x80000000u) : ~u);
}

// qp = ratio*(exp(dd - diag - rowmax) + eps), in place; diag from fp16 q
__global__ void k_expq(float* __restrict__ dd, const __half* __restrict__ q)
{
    size_t w   = ((size_t)blockIdx.x * blockDim.x + threadIdx.x) >> 5;
    int   lane = threadIdx.x & 31;
    float4* row = (float4*)(dd + w * 256);
    float4 v0 = row[lane];
    float4 v1 = row[lane + 32];
    float m = fmaxf(fmaxf(fmaxf(v0.x, v0.y), fmaxf(v0.z, v0.w)),
                    fmaxf(fmaxf(v1.x, v1.y), fmaxf(v1.z, v1.w)));
#pragma unroll
    for (int o = 16; o; o >>= 1) m = fmaxf(m, __shfl_xor_sync(0xffffffffu, m, o));
    float2 qq = __half22float2(((const __half2*)(q + w * 64))[lane]);
    float ss = qq.x * qq.x + qq.y * qq.y;
#pragma unroll
    for (int o = 16; o; o >>= 1) ss += __shfl_xor_sync(0xffffffffu, ss, o);
    float c = 0.0625f * ss + m;
    v0.x = rtf(0.0625f * (expf(v0.x - c) + 1e-6f));
    v0.y = rtf(0.0625f * (expf(v0.y - c) + 1e-6f));
    v0.z = rtf(0.0625f * (expf(v0.z - c) + 1e-6f));
    v0.w = rtf(0.0625f * (expf(v0.w - c) + 1e-6f));
    v1.x = rtf(0.0625f * (expf(v1.x - c) + 1e-6f));
    v1.y = rtf(0.0625f * (expf(v1.y - c) + 1e-6f));
    v1.z = rtf(0.0625f * (expf(v1.z - c) + 1e-6f));
    v1.w = rtf(0.0625f * (expf(v1.w - c) + 1e-6f));
    row[lane] = v0; row[lane + 32] = v1;
}

__global__ void k_expk(float* __restrict__ dd, const __half* __restrict__ k,
                       const unsigned* __restrict__ gmax)
{
    size_t w   = ((size_t)blockIdx.x * blockDim.x + threadIdx.x) >> 5;
    int   lane = threadIdx.x & 31;
    float4* row = (float4*)(dd + w * 256);
    float4 v0 = row[lane];
    float4 v1 = row[lane + 32];
    float2 kk = __half22float2(((const __half2*)(k + w * 64))[lane]);
    float ss = kk.x * kk.x + kk.y * kk.y;
#pragma unroll
    for (int o = 16; o; o >>= 1) ss += __shfl_xor_sync(0xffffffffu, ss, o);
    float c = 0.0625f * ss + unflip(*gmax);
    v0.x = rtf(0.0625f * (expf(v0.x - c) + 1e-6f));
    v0.y = rtf(0.0625f * (expf(v0.y - c) + 1e-6f));
    v0.z = rtf(0.0625f * (expf(v0.z - c) + 1e-6f));
    v0.w = rtf(0.0625f * (expf(v0.w - c) + 1e-6f));
    v1.x = rtf(0.0625f * (expf(v1.x - c) + 1e-6f));
    v1.y = rtf(0.0625f * (expf(v1.y - c) + 1e-6f));
    v1.z = rtf(0.0625f * (expf(v1.z - c) + 1e-6f));
    v1.w = rtf(0.0625f * (expf(v1.w - c) + 1e-6f));
    row[lane] = v0; row[lane + 32] = v1;
}

__global__ void k_ksum(const float* __restrict__ kp, float* __restrict__ ksum)
{
    int z = blockIdx.y;
    int b = z >> 4, h = z & 15;
    int m = threadIdx.x;
    size_t base = (size_t)b * 16777216 + (size_t)h * 256 + m;
    float s = 0.f;
    int l0 = blockIdx.x * 512;
    for (int l = l0; l < l0 + 512; l++) s += kp[base + (size_t)l * 4096];
    atomicAdd(&ksum[z * 256 + m], s);
}

__global__ void k_denom(const float* __restrict__ qp, const float* __restrict__ ksum,
                        float* __restrict__ den)
{
    size_t w   = ((size_t)blockIdx.x * blockDim.x + threadIdx.x) >> 5;
    int   lane = threadIdx.x & 31;
    int   b    = (int)(w >> 16);
    int   h    = (int)(w & 15);
    const float4* row = (const float4*)(qp + w * 256);
    const float4* ks  = (const float4*)(ksum + ((size_t)b * 16 + h) * 256);
    float4 a0 = row[lane], a1 = row[lane + 32];
    float4 k0 = ks[lane],  k1 = ks[lane + 32];
    float s = a0.x * k0.x + a0.y * k0.y + a0.z * k0.z + a0.w * k0.w
            + a1.x * k1.x + a1.y * k1.y + a1.z * k1.z + a1.w * k1.w;
#pragma unroll
    for (int o = 16; o; o >>= 1) s += __shfl_xor_sync(0xffffffffu, s, o);
    if (lane == 0) den[w] = s;
}

// out = LN(a + r) * g + b; optional fp16 copy
template<bool WRITE_H>
__global__ void k_ln(const float* __restrict__ a, const float* __restrict__ r,
                     const float* __restrict__ g, const float* __restrict__ b,
                     float* __restrict__ out, __half* __restrict__ outh)
{
    const int row = blockIdx.x;
    const int t   = threadIdx.x;
    const size_t base = (size_t)row * 1024;
    float4 xa = *(const float4*)(a + base + t * 4);
    float4 xr = *(const float4*)(r + base + t * 4);
    float4 s  = make_float4(xa.x + xr.x, xa.y + xr.y, xa.z + xr.z, xa.w + xr.w);
    float sum = s.x + s.y + s.z + s.w;
    float sq  = s.x * s.x + s.y * s.y + s.z * s.z + s.w * s.w;
#pragma unroll
    for (int o = 16; o; o >>= 1) {
        sum += __shfl_xor_sync(0xffffffffu, sum, o);
        sq  += __shfl_xor_sync(0xffffffffu, sq,  o);
    }
    __shared__ float ssum[8], ssq[8];
    __shared__ float s_mu, s_inv;
    int w = t >> 5;
    if ((t & 31) == 0) { ssum[w] = sum; ssq[w] = sq; }
    __syncthreads();
    if (t == 0) {
        float ts = 0.f, tq = 0.f;
        for (int i = 0; i < 8; i++) { ts += ssum[i]; tq += ssq[i]; }
        float mu  = ts * (1.f / 1024.f);
        float var = tq * (1.f / 1024.f) - mu * mu;
        s_mu = mu;
        s_inv = rsqrtf(var + 1e-6f);
    }
    __syncthreads();
    float mu = s_mu, inv = s_inv;
    float4 gg = *(const float4*)(g + t * 4);
    float4 bb = *(const float4*)(b + t * 4);
    float4 o = make_float4((s.x - mu) * inv * gg.x + bb.x,
                           (s.y - mu) * inv * gg.y + bb.y,
                           (s.z - mu) * inv * gg.z + bb.z,
                           (s.w - mu) * inv * gg.w + bb.w);
    *(float4*)(out + base + t * 4) = o;
    if (WRITE_H) {
        __half2* oh = (__half2*)(outh + base + t * 4);
        oh[0] = __floats2half2_rn(o.x, o.y);
        oh[1] = __floats2half2_rn(o.z, o.w);
    }
}

// ---------------- driver -----------------------------------------------------
extern "C" void kernel_launch(void* const* d_in, const int* in_sizes, int n_in,
                              void* d_out, int out_size)
{
    const float* x    = (const float*)d_in[0];
    const float* wq   = (const float*)d_in[1];
    const float* wk   = (const float*)d_in[2];
    const float* wv   = (const float*)d_in[3];
    const float* wo   = (const float*)d_in[4];
    const float* proj = (const float*)d_in[5];
    const float* ln1g = (const float*)d_in[6];
    const float* ln1b = (const float*)d_in[7];
    const float* ln2g = (const float*)d_in[8];
    const float* ln2b = (const float*)d_in[9];
    const float* w1   = (const float*)d_in[10];
    const float* b1   = (const float*)d_in[11];
    const float* w2   = (const float*)d_in[12];
    const float* b2   = (const float*)d_in[13];
    float* out = (float*)d_out;

    float *p_v, *p_qp, *p_kp, *p_kv, *p_ksum, *p_den, *p_tmp, *p_out1;
    __half *p_xh, *p_qh, *p_kh, *p_out1h, *p_attnh, *p_hh, *p_projh;
    __half *p_wqT, *p_wkT, *p_wvT, *p_woT, *p_w1T, *p_w2T;
    unsigned* p_kmax;
    cudaGetSymbolAddress((void**)&p_v,     g_v);
    cudaGetSymbolAddress((void**)&p_qp,    g_qp);
    cudaGetSymbolAddress((void**)&p_kp,    g_kp);
    cudaGetSymbolAddress((void**)&p_kv,    g_kv);
    cudaGetSymbolAddress((void**)&p_ksum,  g_ksum);
    cudaGetSymbolAddress((void**)&p_den,   g_den);
    cudaGetSymbolAddress((void**)&p_tmp,   g_tmp);
    cudaGetSymbolAddress((void**)&p_out1,  g_out1);
    cudaGetSymbolAddress((void**)&p_kmax,  g_kmax);
    cudaGetSymbolAddress((void**)&p_xh,    g_xh);
    cudaGetSymbolAddress((void**)&p_qh,    g_qh);
    cudaGetSymbolAddress((void**)&p_kh,    g_kh);
    cudaGetSymbolAddress((void**)&p_out1h, g_out1h);
    cudaGetSymbolAddress((void**)&p_attnh, g_attnh);
    cudaGetSymbolAddress((void**)&p_hh,    g_hh);
    cudaGetSymbolAddress((void**)&p_projh, g_projh);
    cudaGetSymbolAddress((void**)&p_wqT,   g_wqT);
    cudaGetSymbolAddress((void**)&p_wkT,   g_wkT);
    cudaGetSymbolAddress((void**)&p_wvT,   g_wvT);
    cudaGetSymbolAddress((void**)&p_woT,   g_woT);
    cudaGetSymbolAddress((void**)&p_w1T,   g_w1T);
    cudaGetSymbolAddress((void**)&p_w2T,   g_w2T);

    // prep: fp16 conversions / transposes
    k_half4<<<(NT * DD / 4 + 255) / 256, 256>>>((const float4*)x, (__half2*)p_xh, NT * DD / 4);
    k_transH<<<dim3(32, 32),  dim3(32, 8)>>>(wq, p_wqT, DD, DD);
    k_transH<<<dim3(32, 32),  dim3(32, 8)>>>(wk, p_wkT, DD, DD);
    k_transH<<<dim3(32, 32),  dim3(32, 8)>>>(wv, p_wvT, DD, DD);
    k_transH<<<dim3(32, 32),  dim3(32, 8)>>>(wo, p_woT, DD, DD);
    k_transH<<<dim3(128, 32), dim3(32, 8)>>>(w1, p_w1T, DD, DFF);   // [DFF][D]
    k_transH<<<dim3(32, 128), dim3(32, 8)>>>(w2, p_w2T, DFF, DD);   // [D][DFF]
    k_projH<<<64, 256>>>(proj, p_projh);

    // q,k projections -> fp16; v -> fp32 (tf32-rounded, feeds tf32 kv GEMM)
    hgemm<EPI_NONE, __half, false><<<dim3(8, 128), 256>>>(p_xh, p_wqT, nullptr, p_qh, NT, 1024, 1024);
    hgemm<EPI_NONE, __half, false><<<dim3(8, 128), 256>>>(p_xh, p_wkT, nullptr, p_kh, NT, 1024, 1024);
    hgemm<EPI_NONE, float,  true ><<<dim3(8, 128), 256>>>(p_xh, p_wvT, nullptr, p_v,  NT, 1024, 1024);

    // dd = q_resh[NR,64] @ proj^T -> fp32 (exp rounds later)
    hgemm<EPI_NONE, float, false><<<dim3(2, 2048), 256>>>(p_qh, p_projh, nullptr, p_qp, NR, 256, 64);
    hgemm<EPI_NONE, float, false><<<dim3(2, 2048), 256>>>(p_kh, p_projh, nullptr, p_kp, NR, 256, 64);

    cudaMemsetAsync(p_kmax, 0, 4);
    cudaMemsetAsync(p_ksum, 0, BB * HH * MMF * sizeof(float));

    k_max<<<2048, 256>>>((const float4*)p_kp, (size_t)NR * 64, p_kmax);
    k_expq<<<NR / 8, 256>>>(p_qp, p_qh);
    k_expk<<<NR / 8, 256>>>(p_kp, p_kh, p_kmax);

    // kv[bh][256][64] = kp^T @ v : tf32 (fp32 in/out, rounded)
    tgemm_bh<true, false, true, float><<<dim3(1, 2, 64), 256>>>(
        p_kp, (size_t)16777216, (size_t)256, 4096,
        p_v,  (size_t)4194304,  (size_t)64,  1024,
        p_kv, (size_t)(16 * 16384), (size_t)16384, 64,
        nullptr, 0, 0, 0,
        256, 64, 4096);

    k_ksum<<<dim3(8, 64), 256>>>(p_kp, p_ksum);
    k_denom<<<NR / 8, 256>>>(p_qp, p_ksum, p_den);

    // attn = (qp @ kv) / denom : tf32, output fp16 (feeds wo hgemm)
    tgemm_bh<false, true, false, __half><<<dim3(1, 32, 64), 256>>>(
        p_qp, (size_t)16777216, (size_t)256, 4096,
        p_kv, (size_t)(16 * 16384), (size_t)16384, 64,
        p_attnh, (size_t)4194304, (size_t)64, 1024,
        p_den,  (size_t)65536,   (size_t)1,  16,
        4096, 64, 256);

    // attn_out = attn @ wo^T -> fp32 tmp
    hgemm<EPI_NONE, float, false><<<dim3(8, 128), 256>>>(p_attnh, p_woT, nullptr, p_tmp, NT, 1024, 1024);

    // out1 = LN(x + attn_out) -> fp32 residual + fp16 for FFN1
    k_ln<true><<<NT, 256>>>(p_tmp, x, ln1g, ln1b, p_out1, p_out1h);

    // FFN
    hgemm<EPI_BIAS_ELU, __half, false><<<dim3(32, 128), 256>>>(p_out1h, p_w1T, b1, p_hh, NT, DFF, 1024);
    hgemm<EPI_BIAS, float, false><<<dim3(8, 128), 256>>>(p_hh, p_w2T, b2, p_tmp, NT, 1024, DFF);

    // out2 = LN(out1 + ffn)
    k_ln<false><<<NT, 256>>>(p_tmp, p_out1, ln2g, ln2b, out, nullptr);
}

// round 8
// speedup vs baseline: 2.0547x; 1.4954x over previous
#include <cuda_runtime.h>
#include <cuda_fp16.h>
#include <math.h>
#include <stdint.h>

#define BB   4
#define LL   4096
#define DD   1024
#define HH   16
#define DHH  64
#define MMF  256
#define DFF  4096
#define NT   (BB*LL)      /* 16384 tokens  */
#define NR   (NT*HH)      /* 262144 (t,h) rows */
#define KVN  (BB*HH*MMF*DHH)   /* 1048576 */

// ---------------- scratch (device globals; no allocation allowed) ----------
__device__ float  g_v    [(size_t)NT*DD];
__device__ float  g_qp   [(size_t)NR*MMF];
__device__ float  g_kp   [(size_t)NR*MMF];
__device__ float  g_kv   [KVN];
__device__ float  g_kvp  [4*KVN];               // split-K partials
__device__ float  g_ksum [BB*HH*MMF];
__device__ float  g_den  [NR];
__device__ float  g_tmp  [(size_t)NT*DD];
__device__ float  g_out1 [(size_t)NT*DD];
__device__ unsigned g_kmax;
// fp16 operand buffers
__device__ __half g_xh   [(size_t)NT*DD];
__device__ __half g_qh   [(size_t)NT*DD];
__device__ __half g_kh   [(size_t)NT*DD];
__device__ __half g_out1h[(size_t)NT*DD];
__device__ __half g_attnh[(size_t)NT*DD];
__device__ __half g_hh   [(size_t)NT*DFF];
__device__ __half g_projh[MMF*DHH];
__device__ __half g_wqT  [DD*DD];
__device__ __half g_wkT  [DD*DD];
__device__ __half g_wvT  [DD*DD];
__device__ __half g_woT  [DD*DD];
__device__ __half g_w1T  [(size_t)DFF*DD];
__device__ __half g_w2T  [(size_t)DD*DFF];

enum { EPI_NONE = 0, EPI_BIAS = 1, EPI_BIAS_ELU = 2 };

// ---------------- helpers ----------------------------------------------------
__device__ __forceinline__ float rtf(float x)
{
    unsigned u;
    asm("cvt.rna.tf32.f32 %0, %1;" : "=r"(u) : "f"(x));
    return __uint_as_float(u);
}

__device__ __forceinline__ void mma_tf32(float* d, const unsigned* a,
                                         const unsigned* b)
{
    asm volatile(
        "mma.sync.aligned.m16n8k8.row.col.f32.tf32.tf32.f32 "
        "{%0,%1,%2,%3}, {%4,%5,%6,%7}, {%8,%9}, {%0,%1,%2,%3};\n"
        : "+f"(d[0]), "+f"(d[1]), "+f"(d[2]), "+f"(d[3])
        : "r"(a[0]), "r"(a[1]), "r"(a[2]), "r"(a[3]),
          "r"(b[0]), "r"(b[1]));
}

__device__ __forceinline__ void mma_f16(float* d, const unsigned* a,
                                        const unsigned* b)
{
    asm volatile(
        "mma.sync.aligned.m16n8k16.row.col.f32.f16.f16.f32 "
        "{%0,%1,%2,%3}, {%4,%5,%6,%7}, {%8,%9}, {%0,%1,%2,%3};\n"
        : "+f"(d[0]), "+f"(d[1]), "+f"(d[2]), "+f"(d[3])
        : "r"(a[0]), "r"(a[1]), "r"(a[2]), "r"(a[3]),
          "r"(b[0]), "r"(b[1]));
}

__device__ __forceinline__ void ldsm_x4(unsigned* r, unsigned addr)
{
    asm volatile("ldmatrix.sync.aligned.m8n8.x4.shared.b16 {%0,%1,%2,%3}, [%4];"
        : "=r"(r[0]), "=r"(r[1]), "=r"(r[2]), "=r"(r[3]) : "r"(addr));
}

// ---------------- fp16 tensor-core GEMM: C[M,N] = A[M,K] @ B^T ----------------
// A: [M][K] fp16 row-major.  B: [N][K] fp16 (pre-transposed).
// 128x128 block tile, BK=32, 256 threads = 8 warps (4m x 2n), warp tile 32x64
// via m16n8k16 + ldmatrix.x4 fragment loads. Single-buffer smem + reg prefetch.
#define HS 40

template<int EPI, typename OutT, bool RND>
__global__ __launch_bounds__(256, 2)
void hgemm(const __half* __restrict__ A, const __half* __restrict__ B,
           const float* __restrict__ bias, OutT* __restrict__ C,
           int M, int N, int K)
{
    __shared__ __align__(16) __half As[128 * HS];
    __shared__ __align__(16) __half Bs[128 * HS];

    const int tid  = threadIdx.x;
    const int wid  = tid >> 5;
    const int lane = tid & 31;
    const int wm   = (wid >> 1) * 32;
    const int wn   = (wid & 1)  * 64;
    const size_t m0 = (size_t)blockIdx.y * 128;
    const int    n0 = blockIdx.x * 128;

    const int ar0 = tid >> 2,          aq0 = (tid & 3) << 3;
    const int ar1 = (tid + 256) >> 2,  aq1 = ((tid + 256) & 3) << 3;

    // ldmatrix per-lane base offsets (bytes)
    const int matid = lane >> 3, rowin = lane & 7;
    const unsigned sAb = (unsigned)__cvta_generic_to_shared(As);
    const unsigned sBb = (unsigned)__cvta_generic_to_shared(Bs);
    unsigned aoff[2], boff[4];
#pragma unroll
    for (int mt = 0; mt < 2; mt++)
        aoff[mt] = sAb + (unsigned)(((wm + mt * 16 + rowin + ((matid & 1) << 3)) * HS
                                     + ((matid & 2) << 2)) << 1);
#pragma unroll
    for (int p = 0; p < 4; p++)
        boff[p] = sBb + (unsigned)(((wn + ((p << 1) + ((matid >> 1) & 1)) * 8 + rowin) * HS
                                     + ((matid & 1) << 3)) << 1);

    uint4 ra0, ra1, rb0, rb1;
    float acc[2][8][4];
#pragma unroll
    for (int mt = 0; mt < 2; mt++)
#pragma unroll
        for (int nt = 0; nt < 8; nt++)
#pragma unroll
            for (int i = 0; i < 4; i++) acc[mt][nt][i] = 0.f;

    const int iters = K >> 5;

    ra0 = *(const uint4*)(A + (m0 + ar0) * K + aq0);
    ra1 = *(const uint4*)(A + (m0 + ar1) * K + aq1);
    rb0 = *(const uint4*)(B + (size_t)(n0 + ar0) * K + aq0);
    rb1 = *(const uint4*)(B + (size_t)(n0 + ar1) * K + aq1);

    for (int it = 0; it < iters; it++) {
        *(uint4*)&As[ar0 * HS + aq0] = ra0;
        *(uint4*)&As[ar1 * HS + aq1] = ra1;
        *(uint4*)&Bs[ar0 * HS + aq0] = rb0;
        *(uint4*)&Bs[ar1 * HS + aq1] = rb1;
        __syncthreads();

        if (it + 1 < iters) {
            int k0 = (it + 1) << 5;
            ra0 = *(const uint4*)(A + (m0 + ar0) * K + k0 + aq0);
            ra1 = *(const uint4*)(A + (m0 + ar1) * K + k0 + aq1);
            rb0 = *(const uint4*)(B + (size_t)(n0 + ar0) * K + k0 + aq0);
            rb1 = *(const uint4*)(B + (size_t)(n0 + ar1) * K + k0 + aq1);
        }

#pragma unroll
        for (int ks = 0; ks < 2; ks++) {
            const unsigned cb = (unsigned)(ks << 5);    // ks*16 halves in bytes
            unsigned af[2][4], bf[4][4];
#pragma unroll
            for (int mt = 0; mt < 2; mt++) ldsm_x4(af[mt], aoff[mt] + cb);
#pragma unroll
            for (int p = 0; p < 4; p++)   ldsm_x4(bf[p],  boff[p]  + cb);
#pragma unroll
            for (int mt = 0; mt < 2; mt++)
#pragma unroll
                for (int p = 0; p < 4; p++) {
                    mma_f16(acc[mt][2 * p],     af[mt], &bf[p][0]);
                    mma_f16(acc[mt][2 * p + 1], af[mt], &bf[p][2]);
                }
        }
        __syncthreads();
    }

#pragma unroll
    for (int mt = 0; mt < 2; mt++) {
#pragma unroll
        for (int nt = 0; nt < 8; nt++) {
            size_t row = m0 + wm + mt * 16 + (lane >> 2);
            int col = n0 + wn + nt * 8 + ((lane & 3) << 1);
            float2 lo = make_float2(acc[mt][nt][0], acc[mt][nt][1]);
            float2 hi = make_float2(acc[mt][nt][2], acc[mt][nt][3]);
            if (EPI == EPI_BIAS || EPI == EPI_BIAS_ELU) {
                float2 bb = *(const float2*)(bias + col);
                lo.x += bb.x; lo.y += bb.y;
                hi.x += bb.x; hi.y += bb.y;
            }
            if (EPI == EPI_BIAS_ELU) {
                lo.x = lo.x > 0.f ? lo.x : expm1f(lo.x);
                lo.y = lo.y > 0.f ? lo.y : expm1f(lo.y);
                hi.x = hi.x > 0.f ? hi.x : expm1f(hi.x);
                hi.y = hi.y > 0.f ? hi.y : expm1f(hi.y);
            }
            if (sizeof(OutT) == 2) {
                *(__half2*)((__half*)C + row * N + col)       = __floats2half2_rn(lo.x, lo.y);
                *(__half2*)((__half*)C + (row + 8) * N + col) = __floats2half2_rn(hi.x, hi.y);
            } else {
                if (RND) {
                    lo.x = rtf(lo.x); lo.y = rtf(lo.y);
                    hi.x = rtf(hi.x); hi.y = rtf(hi.y);
                }
                *(float2*)((float*)C + row * N + col)       = lo;
                *(float2*)((float*)C + (row + 8) * N + col) = hi;
            }
        }
    }
}

// ------------- tf32 batched strided GEMM over (b,h), optional split-K --------
// blockIdx.z = split*64 + (b*16+h); NSPLIT splits of K (host passes K/NSPLIT).
#define APAD 20
#define AT_PAD 136
#define BH_BPAD 72

template<bool TRANSA, bool DIV, bool RND, typename OutT, int NSPLIT>
__global__ __launch_bounds__(256, 2)
void tgemm_bh(const float* __restrict__ A, size_t sAb, size_t sAh, int lda,
              const float* __restrict__ B, size_t sBb, size_t sBh, int ldb,
              OutT* __restrict__ C, size_t sCb, size_t sCh, int ldc, size_t sCsplit,
              const float* __restrict__ aux, size_t sXb, size_t sXh, int ldx,
              int M, int N, int K)
{
    __shared__ float As[128 * APAD];
    __shared__ float Bs[16 * BH_BPAD];

    const int z     = blockIdx.z;
    const int split = (NSPLIT > 1) ? (z >> 6) : 0;
    const int zz    = (NSPLIT > 1) ? (z & 63) : z;
    const int zb = zz >> 4, zh = zz & 15;
    const float* Ab = A + (size_t)zb * sAb + (size_t)zh * sAh;
    const float* Bb = B + (size_t)zb * sBb + (size_t)zh * sBh;
    OutT*        Cb = C + (size_t)zb * sCb + (size_t)zh * sCh
                        + (size_t)split * sCsplit;
    if (NSPLIT > 1) {
        if (TRANSA) Ab += (size_t)split * K * lda;
        else        Ab += (size_t)split * K;
        Bb += (size_t)split * K * ldb;
    }

    const int tid  = threadIdx.x;
    const int wid  = tid >> 5;
    const int lane = tid & 31;
    const int wm   = (wid >> 1) * 32;
    const int wn   = (wid & 1)  * 32;
    const int m0   = blockIdx.y * 128;
    const int n0   = blockIdx.x * 64;

    const int t_kr = tid >> 5;
    const int t_mc = lane << 2;
    const int n_row = tid & 127;
    const int n_kh  = (tid >> 7) << 3;
    const int b_kr = tid >> 4;
    const int b_nc = (tid & 15) << 2;

    float4 ra[2], rb1;
    float acc[2][4][4];
#pragma unroll
    for (int mt = 0; mt < 2; mt++)
#pragma unroll
        for (int nt = 0; nt < 4; nt++)
#pragma unroll
            for (int i = 0; i < 4; i++) acc[mt][nt][i] = 0.f;

    const int iters = K >> 4;

    auto ldA = [&](int k0) {
        if (TRANSA) {
            ra[0] = *(const float4*)(Ab + (size_t)(k0 + t_kr)     * lda + m0 + t_mc);
            ra[1] = *(const float4*)(Ab + (size_t)(k0 + t_kr + 8) * lda + m0 + t_mc);
        } else {
            ra[0] = *(const float4*)(Ab + (size_t)(m0 + n_row) * lda + k0 + n_kh);
            ra[1] = *(const float4*)(Ab + (size_t)(m0 + n_row) * lda + k0 + n_kh + 4);
        }
    };
    auto ldB = [&](int k0) {
        rb1 = *(const float4*)(Bb + (size_t)(k0 + b_kr) * ldb + n0 + b_nc);
    };

    ldA(0); ldB(0);

    for (int it = 0; it < iters; it++) {
        if (TRANSA) {
            *(float4*)&As[t_kr * AT_PAD + t_mc]       = ra[0];
            *(float4*)&As[(t_kr + 8) * AT_PAD + t_mc] = ra[1];
        } else {
            *(float4*)&As[n_row * APAD + n_kh]     = ra[0];
            *(float4*)&As[n_row * APAD + n_kh + 4] = ra[1];
        }
        *(float4*)&Bs[b_kr * BH_BPAD + b_nc] = rb1;
        __syncthreads();

        if (it + 1 < iters) { ldA((it + 1) << 4); ldB((it + 1) << 4); }

#pragma unroll
        for (int ks = 0; ks < 16; ks += 8) {
            unsigned af[2][4], bf[4][2];
#pragma unroll
            for (int mt = 0; mt < 2; mt++) {
                int r = wm + mt * 16 + (lane >> 2);
                int c = ks + (lane & 3);
                if (TRANSA) {
                    af[mt][0] = __float_as_uint(As[c * AT_PAD + r]);
                    af[mt][1] = __float_as_uint(As[c * AT_PAD + r + 8]);
                    af[mt][2] = __float_as_uint(As[(c + 4) * AT_PAD + r]);
                    af[mt][3] = __float_as_uint(As[(c + 4) * AT_PAD + r + 8]);
                } else {
                    af[mt][0] = __float_as_uint(As[r * APAD + c]);
                    af[mt][1] = __float_as_uint(As[(r + 8) * APAD + c]);
                    af[mt][2] = __float_as_uint(As[r * APAD + c + 4]);
                    af[mt][3] = __float_as_uint(As[(r + 8) * APAD + c + 4]);
                }
            }
#pragma unroll
            for (int nt = 0; nt < 4; nt++) {
                int c = wn + nt * 8 + (lane >> 2);
                int r = ks + (lane & 3);
                bf[nt][0] = __float_as_uint(Bs[r * BH_BPAD + c]);
                bf[nt][1] = __float_as_uint(Bs[(r + 4) * BH_BPAD + c]);
            }
#pragma unroll
            for (int mt = 0; mt < 2; mt++)
#pragma unroll
                for (int nt = 0; nt < 4; nt++)
                    mma_tf32(acc[mt][nt], af[mt], bf[nt]);
        }
        __syncthreads();
    }

#pragma unroll
    for (int mt = 0; mt < 2; mt++) {
        int row = m0 + wm + mt * 16 + (lane >> 2);
        float dv0 = 1.f, dv1 = 1.f;
        if (DIV) {
            dv0 = 1.f / aux[(size_t)zb * sXb + (size_t)zh * sXh + (size_t)row * ldx];
            dv1 = 1.f / aux[(size_t)zb * sXb + (size_t)zh * sXh + (size_t)(row + 8) * ldx];
        }
#pragma unroll
        for (int nt = 0; nt < 4; nt++) {
            int col = n0 + wn + nt * 8 + ((lane & 3) << 1);
            float2 lo = make_float2(acc[mt][nt][0] * dv0, acc[mt][nt][1] * dv0);
            float2 hi = make_float2(acc[mt][nt][2] * dv1, acc[mt][nt][3] * dv1);
            if (sizeof(OutT) == 2) {
                *(__half2*)((__half*)Cb + (size_t)row * ldc + col)       = __floats2half2_rn(lo.x, lo.y);
                *(__half2*)((__half*)Cb + (size_t)(row + 8) * ldc + col) = __floats2half2_rn(hi.x, hi.y);
            } else {
                if (RND) {
                    lo.x = rtf(lo.x); lo.y = rtf(lo.y);
                    hi.x = rtf(hi.x); hi.y = rtf(hi.y);
                }
                *(float2*)((float*)Cb + (size_t)row * ldc + col)       = lo;
                *(float2*)((float*)Cb + (size_t)(row + 8) * ldc + col) = hi;
            }
        }
    }
}

// ---------------- small helper kernels --------------------------------------
__global__ void k_half4(const float4* __restrict__ in, __half2* __restrict__ out,
                        int n4)
{
    int i = blockIdx.x * 256 + threadIdx.x;
    if (i < n4) {
        float4 v = in[i];
        out[2 * i]     = __floats2half2_rn(v.x, v.y);
        out[2 * i + 1] = __floats2half2_rn(v.z, v.w);
    }
}

__global__ void k_transH(const float* __restrict__ in, __half* __restrict__ out,
                         int K, int N)
{
    __shared__ float t[32][33];
    const int n0 = blockIdx.x * 32, k0 = blockIdx.y * 32;
#pragma unroll
    for (int i = 0; i < 4; i++) {
        int kk = threadIdx.y + i * 8;
        t[kk][threadIdx.x] = in[(size_t)(k0 + kk) * N + n0 + threadIdx.x];
    }
    __syncthreads();
#pragma unroll
    for (int i = 0; i < 4; i++) {
        int nn = threadIdx.y + i * 8;
        out[(size_t)(n0 + nn) * K + k0 + threadIdx.x] = __float2half(t[threadIdx.x][nn]);
    }
}

__global__ void k_projH(const float* __restrict__ proj, __half* __restrict__ ph)
{
    int i = blockIdx.x * 256 + threadIdx.x;
    if (i < MMF * DHH)
        ph[i] = __float2half(proj[i] * 0.35355339059327373f);
}

// kv = rtf(sum of 4 split-K partials)
__global__ void k_kvred(const float4* __restrict__ part, float4* __restrict__ kv)
{
    int i = blockIdx.x * 256 + threadIdx.x;
    if (i < KVN / 4) {
        float4 a = part[i];
        float4 b = part[i + KVN / 4];
        float4 c = part[i + 2 * (KVN / 4)];
        float4 d = part[i + 3 * (KVN / 4)];
        float4 o = make_float4(rtf(a.x + b.x + c.x + d.x),
                               rtf(a.y + b.y + c.y + d.y),
                               rtf(a.z + b.z + c.z + d.z),
                               rtf(a.w + b.w + c.w + d.w));
        kv[i] = o;
    }
}

__global__ void k_max(const float4* __restrict__ d, size_t n4, unsigned* __restrict__ out)
{
    float m = -3.4e38f;
    for (size_t i = (size_t)blockIdx.x * blockDim.x + threadIdx.x; i < n4;
         i += (size_t)gridDim.x * blockDim.x) {
        float4 v = d[i];
        m = fmaxf(m, fmaxf(fmaxf(v.x, v.y), fmaxf(v.z, v.w)));
    }
#pragma unroll
    for (int o = 16; o; o >>= 1) m = fmaxf(m, __shfl_xor_sync(0xffffffffu, m, o));
    __shared__ float sm[8];
    if ((threadIdx.x & 31) == 0) sm[threadIdx.x >> 5] = m;
    __syncthreads();
    if (threadIdx.x == 0) {
        float mm = sm[0];
        for (int i = 1; i < 8; i++) mm = fmaxf(mm, sm[i]);
        unsigned u = __float_as_uint(mm);
        u = (u & 0x80000000u) ? ~u : (u | 0x80000000u);
        atomicMax(out, u);
    }
}

__device__ __forceinline__ float unflip(unsigned u)
{
    return __uint_as_float((u & 0x80000000u) ? (u ^ 0x80000000u) : ~u);
}

__global__ void k_expq(float* __restrict__ dd, const __half* __restrict__ q)
{
    size_t w   = ((size_t)blockIdx.x * blockDim.x + threadIdx.x) >> 5;
    int   lane = threadIdx.x & 31;
    float4* row = (float4*)(dd + w * 256);
    float4 v0 = row[lane];
    float4 v1 = row[lane + 32];
    float m = fmaxf(fmaxf(fmaxf(v0.x, v0.y), fmaxf(v0.z, v0.w)),
                    fmaxf(fmaxf(v1.x, v1.y), fmaxf(v1.z, v1.w)));
#pragma unroll
    for (int o = 16; o; o >>= 1) m = fmaxf(m, __shfl_xor_sync(0xffffffffu, m, o));
    float2 qq = __half22float2(((const __half2*)(q + w * 64))[lane]);
    float ss = qq.x * qq.x + qq.y * qq.y;
#pragma unroll
    for (int o = 16; o; o >>= 1) ss += __shfl_xor_sync(0xffffffffu, ss, o);
    float c = 0.0625f * ss + m;
    v0.x = rtf(0.0625f * (expf(v0.x - c) + 1e-6f));
    v0.y = rtf(0.0625f * (expf(v0.y - c) + 1e-6f));
    v0.z = rtf(0.0625f * (expf(v0.z - c) + 1e-6f));
    v0.w = rtf(0.0625f * (expf(v0.w - c) + 1e-6f));
    v1.x = rtf(0.0625f * (expf(v1.x - c) + 1e-6f));
    v1.y = rtf(0.0625f * (expf(v1.y - c) + 1e-6f));
    v1.z = rtf(0.0625f * (expf(v1.z - c) + 1e-6f));
    v1.w = rtf(0.0625f * (expf(v1.w - c) + 1e-6f));
    row[lane] = v0; row[lane + 32] = v1;
}

__global__ void k_expk(float* __restrict__ dd, const __half* __restrict__ k,
                       const unsigned* __restrict__ gmax)
{
    size_t w   = ((size_t)blockIdx.x * blockDim.x + threadIdx.x) >> 5;
    int   lane = threadIdx.x & 31;
    float4* row = (float4*)(dd + w * 256);
    float4 v0 = row[lane];
    float4 v1 = row[lane + 32];
    float2 kk = __half22float2(((const __half2*)(k + w * 64))[lane]);
    float ss = kk.x * kk.x + kk.y * kk.y;
#pragma unroll
    for (int o = 16; o; o >>= 1) ss += __shfl_xor_sync(0xffffffffu, ss, o);
    float c = 0.0625f * ss + unflip(*gmax);
    v0.x = rtf(0.0625f * (expf(v0.x - c) + 1e-6f));
    v0.y = rtf(0.0625f * (expf(v0.y - c) + 1e-6f));
    v0.z = rtf(0.0625f * (expf(v0.z - c) + 1e-6f));
    v0.w = rtf(0.0625f * (expf(v0.w - c) + 1e-6f));
    v1.x = rtf(0.0625f * (expf(v1.x - c) + 1e-6f));
    v1.y = rtf(0.0625f * (expf(v1.y - c) + 1e-6f));
    v1.z = rtf(0.0625f * (expf(v1.z - c) + 1e-6f));
    v1.w = rtf(0.0625f * (expf(v1.w - c) + 1e-6f));
    row[lane] = v0; row[lane + 32] = v1;
}

__global__ void k_ksum(const float* __restrict__ kp, float* __restrict__ ksum)
{
    int z = blockIdx.y;
    int b = z >> 4, h = z & 15;
    int m = threadIdx.x;
    size_t base = (size_t)b * 16777216 + (size_t)h * 256 + m;
    float s = 0.f;
    int l0 = blockIdx.x * 512;
    for (int l = l0; l < l0 + 512; l++) s += kp[base + (size_t)l * 4096];
    atomicAdd(&ksum[z * 256 + m], s);
}

__global__ void k_denom(const float* __restrict__ qp, const float* __restrict__ ksum,
                        float* __restrict__ den)
{
    size_t w   = ((size_t)blockIdx.x * blockDim.x + threadIdx.x) >> 5;
    int   lane = threadIdx.x & 31;
    int   b    = (int)(w >> 16);
    int   h    = (int)(w & 15);
    const float4* row = (const float4*)(qp + w * 256);
    const float4* ks  = (const float4*)(ksum + ((size_t)b * 16 + h) * 256);
    float4 a0 = row[lane], a1 = row[lane + 32];
    float4 k0 = ks[lane],  k1 = ks[lane + 32];
    float s = a0.x * k0.x + a0.y * k0.y + a0.z * k0.z + a0.w * k0.w
            + a1.x * k1.x + a1.y * k1.y + a1.z * k1.z + a1.w * k1.w;
#pragma unroll
    for (int o = 16; o; o >>= 1) s += __shfl_xor_sync(0xffffffffu, s, o);
    if (lane == 0) den[w] = s;
}

template<bool WRITE_H>
__global__ void k_ln(const float* __restrict__ a, const float* __restrict__ r,
                     const float* __restrict__ g, const float* __restrict__ b,
                     float* __restrict__ out, __half* __restrict__ outh)
{
    const int row = blockIdx.x;
    const int t   = threadIdx.x;
    const size_t base = (size_t)row * 1024;
    float4 xa = *(const float4*)(a + base + t * 4);
    float4 xr = *(const float4*)(r + base + t * 4);
    float4 s  = make_float4(xa.x + xr.x, xa.y + xr.y, xa.z + xr.z, xa.w + xr.w);
    float sum = s.x + s.y + s.z + s.w;
    float sq  = s.x * s.x + s.y * s.y + s.z * s.z + s.w * s.w;
#pragma unroll
    for (int o = 16; o; o >>= 1) {
        sum += __shfl_xor_sync(0xffffffffu, sum, o);
        sq  += __shfl_xor_sync(0xffffffffu, sq,  o);
    }
    __shared__ float ssum[8], ssq[8];
    __shared__ float s_mu, s_inv;
    int w = t >> 5;
    if ((t & 31) == 0) { ssum[w] = sum; ssq[w] = sq; }
    __syncthreads();
    if (t == 0) {
        float ts = 0.f, tq = 0.f;
        for (int i = 0; i < 8; i++) { ts += ssum[i]; tq += ssq[i]; }
        float mu  = ts * (1.f / 1024.f);
        float var = tq * (1.f / 1024.f) - mu * mu;
        s_mu = mu;
        s_inv = rsqrtf(var + 1e-6f);
    }
    __syncthreads();
    float mu = s_mu, inv = s_inv;
    float4 gg = *(const float4*)(g + t * 4);
    float4 bb = *(const float4*)(b + t * 4);
    float4 o = make_float4((s.x - mu) * inv * gg.x + bb.x,
                           (s.y - mu) * inv * gg.y + bb.y,
                           (s.z - mu) * inv * gg.z + bb.z,
                           (s.w - mu) * inv * gg.w + bb.w);
    *(float4*)(out + base + t * 4) = o;
    if (WRITE_H) {
        __half2* oh = (__half2*)(outh + base + t * 4);
        oh[0] = __floats2half2_rn(o.x, o.y);
        oh[1] = __floats2half2_rn(o.z, o.w);
    }
}

// ---------------- driver -----------------------------------------------------
extern "C" void kernel_launch(void* const* d_in, const int* in_sizes, int n_in,
                              void* d_out, int out_size)
{
    const float* x    = (const float*)d_in[0];
    const float* wq   = (const float*)d_in[1];
    const float* wk   = (const float*)d_in[2];
    const float* wv   = (const float*)d_in[3];
    const float* wo   = (const float*)d_in[4];
    const float* proj = (const float*)d_in[5];
    const float* ln1g = (const float*)d_in[6];
    const float* ln1b = (const float*)d_in[7];
    const float* ln2g = (const float*)d_in[8];
    const float* ln2b = (const float*)d_in[9];
    const float* w1   = (const float*)d_in[10];
    const float* b1   = (const float*)d_in[11];
    const float* w2   = (const float*)d_in[12];
    const float* b2   = (const float*)d_in[13];
    float* out = (float*)d_out;

    float *p_v, *p_qp, *p_kp, *p_kv, *p_kvp, *p_ksum, *p_den, *p_tmp, *p_out1;
    __half *p_xh, *p_qh, *p_kh, *p_out1h, *p_attnh, *p_hh, *p_projh;
    __half *p_wqT, *p_wkT, *p_wvT, *p_woT, *p_w1T, *p_w2T;
    unsigned* p_kmax;
    cudaGetSymbolAddress((void**)&p_v,     g_v);
    cudaGetSymbolAddress((void**)&p_qp,    g_qp);
    cudaGetSymbolAddress((void**)&p_kp,    g_kp);
    cudaGetSymbolAddress((void**)&p_kv,    g_kv);
    cudaGetSymbolAddress((void**)&p_kvp,   g_kvp);
    cudaGetSymbolAddress((void**)&p_ksum,  g_ksum);
    cudaGetSymbolAddress((void**)&p_den,   g_den);
    cudaGetSymbolAddress((void**)&p_tmp,   g_tmp);
    cudaGetSymbolAddress((void**)&p_out1,  g_out1);
    cudaGetSymbolAddress((void**)&p_kmax,  g_kmax);
    cudaGetSymbolAddress((void**)&p_xh,    g_xh);
    cudaGetSymbolAddress((void**)&p_qh,    g_qh);
    cudaGetSymbolAddress((void**)&p_kh,    g_kh);
    cudaGetSymbolAddress((void**)&p_out1h, g_out1h);
    cudaGetSymbolAddress((void**)&p_attnh, g_attnh);
    cudaGetSymbolAddress((void**)&p_hh,    g_hh);
    cudaGetSymbolAddress((void**)&p_projh, g_projh);
    cudaGetSymbolAddress((void**)&p_wqT,   g_wqT);
    cudaGetSymbolAddress((void**)&p_wkT,   g_wkT);
    cudaGetSymbolAddress((void**)&p_wvT,   g_wvT);
    cudaGetSymbolAddress((void**)&p_woT,   g_woT);
    cudaGetSymbolAddress((void**)&p_w1T,   g_w1T);
    cudaGetSymbolAddress((void**)&p_w2T,   g_w2T);

    // prep (minimal before first hgemm so ncu -s 5 captures hgemm Q as launch #6)
    k_half4<<<(NT * DD / 4 + 255) / 256, 256>>>((const float4*)x, (__half2*)p_xh, NT * DD / 4);   // 1
    k_transH<<<dim3(32, 32), dim3(32, 8)>>>(wq, p_wqT, DD, DD);                                   // 2
    k_transH<<<dim3(32, 32), dim3(32, 8)>>>(wk, p_wkT, DD, DD);                                   // 3
    k_transH<<<dim3(32, 32), dim3(32, 8)>>>(wv, p_wvT, DD, DD);                                   // 4
    k_projH<<<64, 256>>>(proj, p_projh);                                                          // 5

    // q,k projections -> fp16; v -> fp32 (tf32-rounded)
    hgemm<EPI_NONE, __half, false><<<dim3(8, 128), 256>>>(p_xh, p_wqT, nullptr, p_qh, NT, 1024, 1024);  // 6: captured
    hgemm<EPI_NONE, __half, false><<<dim3(8, 128), 256>>>(p_xh, p_wkT, nullptr, p_kh, NT, 1024, 1024);
    hgemm<EPI_NONE, float,  true ><<<dim3(8, 128), 256>>>(p_xh, p_wvT, nullptr, p_v,  NT, 1024, 1024);

    // remaining prep
    k_transH<<<dim3(32, 32),  dim3(32, 8)>>>(wo, p_woT, DD, DD);
    k_transH<<<dim3(128, 32), dim3(32, 8)>>>(w1, p_w1T, DD, DFF);
    k_transH<<<dim3(32, 128), dim3(32, 8)>>>(w2, p_w2T, DFF, DD);

    // dd = q_resh[NR,64] @ proj^T -> fp32
    hgemm<EPI_NONE, float, false><<<dim3(2, 2048), 256>>>(p_qh, p_projh, nullptr, p_qp, NR, 256, 64);
    hgemm<EPI_NONE, float, false><<<dim3(2, 2048), 256>>>(p_kh, p_projh, nullptr, p_kp, NR, 256, 64);

    cudaMemsetAsync(p_kmax, 0, 4);
    cudaMemsetAsync(p_ksum, 0, BB * HH * MMF * sizeof(float));

    k_max<<<2048, 256>>>((const float4*)p_kp, (size_t)NR * 64, p_kmax);
    k_expq<<<NR / 8, 256>>>(p_qp, p_qh);
    k_expk<<<NR / 8, 256>>>(p_kp, p_kh, p_kmax);

    // kv partials: split-K=4 over K=4096 (each split K=1024), grid z = 4*64
    tgemm_bh<true, false, false, float, 4><<<dim3(1, 2, 256), 256>>>(
        p_kp, (size_t)16777216, (size_t)256, 4096,
        p_v,  (size_t)4194304,  (size_t)64,  1024,
        p_kvp, (size_t)(16 * 16384), (size_t)16384, 64, (size_t)KVN,
        nullptr, 0, 0, 0,
        256, 64, 1024);
    k_kvred<<<(KVN / 4 + 255) / 256, 256>>>((const float4*)p_kvp, (float4*)p_kv);

    k_ksum<<<dim3(8, 64), 256>>>(p_kp, p_ksum);
    k_denom<<<NR / 8, 256>>>(p_qp, p_ksum, p_den);

    // attn = (qp @ kv) / denom : tf32 -> fp16
    tgemm_bh<false, true, false, __half, 1><<<dim3(1, 32, 64), 256>>>(
        p_qp, (size_t)16777216, (size_t)256, 4096,
        p_kv, (size_t)(16 * 16384), (size_t)16384, 64,
        p_attnh, (size_t)4194304, (size_t)64, 1024, (size_t)0,
        p_den,  (size_t)65536,   (size_t)1,  16,
        4096, 64, 256);

    // attn_out = attn @ wo^T -> fp32 tmp
    hgemm<EPI_NONE, float, false><<<dim3(8, 128), 256>>>(p_attnh, p_woT, nullptr, p_tmp, NT, 1024, 1024);

    // out1 = LN(x + attn_out) -> fp32 + fp16
    k_ln<true><<<NT, 256>>>(p_tmp, x, ln1g, ln1b, p_out1, p_out1h);

    // FFN
    hgemm<EPI_BIAS_ELU, __half, false><<<dim3(32, 128), 256>>>(p_out1h, p_w1T, b1, p_hh, NT, DFF, 1024);
    hgemm<EPI_BIAS, float, false><<<dim3(8, 128), 256>>>(p_hh, p_w2T, b2, p_tmp, NT, 1024, DFF);

    // out2 = LN(out1 + ffn)
    k_ln<false><<<NT, 256>>>(p_tmp, p_out1, ln2g, ln2b, out, nullptr);
}

// round 9
// speedup vs baseline: 2.3256x; 1.1319x over previous
#include <cuda_runtime.h>
#include <cuda_fp16.h>
#include <math.h>
#include <stdint.h>

#define BB   4
#define LL   4096
#define DD   1024
#define HH   16
#define DHH  64
#define MMF  256
#define DFF  4096
#define NT   (BB*LL)      /* 16384 tokens  */
#define NR   (NT*HH)      /* 262144 (t,h) rows */
#define KVN  (BB*HH*MMF*DHH)   /* 1048576 */

// ---------------- scratch (device globals; no allocation allowed) ----------
__device__ float  g_v    [(size_t)NT*DD];
__device__ float  g_qp   [(size_t)NR*MMF];
__device__ float  g_kp   [(size_t)NR*MMF];
__device__ float  g_kv   [KVN];
__device__ float  g_kvp  [4*KVN];
__device__ float  g_ksum [BB*HH*MMF];
__device__ float  g_den  [NR];
__device__ float  g_tmp  [(size_t)NT*DD];
__device__ float  g_out1 [(size_t)NT*DD];
__device__ unsigned g_kmax;
// fp16 operand buffers
__device__ __half g_xh   [(size_t)NT*DD];
__device__ __half g_qh   [(size_t)NT*DD];
__device__ __half g_kh   [(size_t)NT*DD];
__device__ __half g_out1h[(size_t)NT*DD];
__device__ __half g_attnh[(size_t)NT*DD];
__device__ __half g_hh   [(size_t)NT*DFF];
__device__ __half g_projh[MMF*DHH];
__device__ __half g_wqT  [DD*DD];
__device__ __half g_wkT  [DD*DD];
__device__ __half g_wvT  [DD*DD];
__device__ __half g_woT  [DD*DD];
__device__ __half g_w1T  [(size_t)DFF*DD];
__device__ __half g_w2T  [(size_t)DD*DFF];

enum { EPI_NONE = 0, EPI_BIAS = 1, EPI_BIAS_ELU = 2 };

// ---------------- helpers ----------------------------------------------------
__device__ __forceinline__ float rtf(float x)
{
    unsigned u;
    asm("cvt.rna.tf32.f32 %0, %1;" : "=r"(u) : "f"(x));
    return __uint_as_float(u);
}

__device__ __forceinline__ void mma_tf32(float* d, const unsigned* a,
                                         const unsigned* b)
{
    asm volatile(
        "mma.sync.aligned.m16n8k8.row.col.f32.tf32.tf32.f32 "
        "{%0,%1,%2,%3}, {%4,%5,%6,%7}, {%8,%9}, {%0,%1,%2,%3};\n"
        : "+f"(d[0]), "+f"(d[1]), "+f"(d[2]), "+f"(d[3])
        : "r"(a[0]), "r"(a[1]), "r"(a[2]), "r"(a[3]),
          "r"(b[0]), "r"(b[1]));
}

__device__ __forceinline__ void mma_f16(float* d, const unsigned* a,
                                        const unsigned* b)
{
    asm volatile(
        "mma.sync.aligned.m16n8k16.row.col.f32.f16.f16.f32 "
        "{%0,%1,%2,%3}, {%4,%5,%6,%7}, {%8,%9}, {%0,%1,%2,%3};\n"
        : "+f"(d[0]), "+f"(d[1]), "+f"(d[2]), "+f"(d[3])
        : "r"(a[0]), "r"(a[1]), "r"(a[2]), "r"(a[3]),
          "r"(b[0]), "r"(b[1]));
}

__device__ __forceinline__ void ldsm_x4(unsigned* r, unsigned addr)
{
    asm volatile("ldmatrix.sync.aligned.m8n8.x4.shared.b16 {%0,%1,%2,%3}, [%4];"
        : "=r"(r[0]), "=r"(r[1]), "=r"(r[2]), "=r"(r[3]) : "r"(addr));
}

// ---------------- fp16 tensor-core GEMM: C[M,N] = A[M,K] @ B^T ----------------
// A: [M][K] fp16 row-major.  B: [N][K] fp16 (pre-transposed).
// 128x128 block tile, BK=32, 256 threads = 8 warps (4m x 2n), warp tile 32x64
// via m16n8k16 + ldmatrix.x4. Double-buffered smem: one __syncthreads per iter.
// MAXRED: reduce max(acc) into *gmax (flipped-uint atomicMax) in the epilogue.
#define HS 40
#define HBUF (128 * HS)            /* halves per buffer */
#define HBUFB (HBUF * 2)           /* bytes per buffer  */

template<int EPI, typename OutT, bool RND, bool MAXRED>
__global__ __launch_bounds__(256, 2)
void hgemm(const __half* __restrict__ A, const __half* __restrict__ B,
           const float* __restrict__ bias, OutT* __restrict__ C,
           int M, int N, int K, unsigned* __restrict__ gmax)
{
    __shared__ __align__(16) __half As[2 * HBUF];
    __shared__ __align__(16) __half Bs[2 * HBUF];

    const int tid  = threadIdx.x;
    const int wid  = tid >> 5;
    const int lane = tid & 31;
    const int wm   = (wid >> 1) * 32;
    const int wn   = (wid & 1)  * 64;
    const size_t m0 = (size_t)blockIdx.y * 128;
    const int    n0 = blockIdx.x * 128;

    const int ar0 = tid >> 2,          aq0 = (tid & 3) << 3;
    const int ar1 = (tid + 256) >> 2,  aq1 = ((tid + 256) & 3) << 3;

    // ldmatrix per-lane base offsets (bytes, buffer 0)
    const int matid = lane >> 3, rowin = lane & 7;
    const unsigned sAb = (unsigned)__cvta_generic_to_shared(As);
    const unsigned sBb = (unsigned)__cvta_generic_to_shared(Bs);
    unsigned aoff[2], boff[4];
#pragma unroll
    for (int mt = 0; mt < 2; mt++)
        aoff[mt] = sAb + (unsigned)(((wm + mt * 16 + rowin + ((matid & 1) << 3)) * HS
                                     + ((matid & 2) << 2)) << 1);
#pragma unroll
    for (int p = 0; p < 4; p++)
        boff[p] = sBb + (unsigned)(((wn + ((p << 1) + ((matid >> 1) & 1)) * 8 + rowin) * HS
                                     + ((matid & 1) << 3)) << 1);

    uint4 ra0, ra1, rb0, rb1;
    float acc[2][8][4];
#pragma unroll
    for (int mt = 0; mt < 2; mt++)
#pragma unroll
        for (int nt = 0; nt < 8; nt++)
#pragma unroll
            for (int i = 0; i < 4; i++) acc[mt][nt][i] = 0.f;

    const int iters = K >> 5;

    // prologue: load + stage buffer 0
    ra0 = *(const uint4*)(A + (m0 + ar0) * K + aq0);
    ra1 = *(const uint4*)(A + (m0 + ar1) * K + aq1);
    rb0 = *(const uint4*)(B + (size_t)(n0 + ar0) * K + aq0);
    rb1 = *(const uint4*)(B + (size_t)(n0 + ar1) * K + aq1);
    *(uint4*)&As[ar0 * HS + aq0] = ra0;
    *(uint4*)&As[ar1 * HS + aq1] = ra1;
    *(uint4*)&Bs[ar0 * HS + aq0] = rb0;
    *(uint4*)&Bs[ar1 * HS + aq1] = rb1;
    __syncthreads();

    for (int it = 0; it < iters; it++) {
        const bool more = (it + 1 < iters);
        if (more) {
            int k0 = (it + 1) << 5;
            ra0 = *(const uint4*)(A + (m0 + ar0) * K + k0 + aq0);
            ra1 = *(const uint4*)(A + (m0 + ar1) * K + k0 + aq1);
            rb0 = *(const uint4*)(B + (size_t)(n0 + ar0) * K + k0 + aq0);
            rb1 = *(const uint4*)(B + (size_t)(n0 + ar1) * K + k0 + aq1);
        }

        const unsigned bo = (unsigned)((it & 1) * HBUFB);
#pragma unroll
        for (int ks = 0; ks < 2; ks++) {
            const unsigned cb = bo + (unsigned)(ks << 5);
            unsigned af[2][4], bf[4][4];
#pragma unroll
            for (int mt = 0; mt < 2; mt++) ldsm_x4(af[mt], aoff[mt] + cb);
#pragma unroll
            for (int p = 0; p < 4; p++)   ldsm_x4(bf[p],  boff[p]  + cb);
#pragma unroll
            for (int mt = 0; mt < 2; mt++)
#pragma unroll
                for (int p = 0; p < 4; p++) {
                    mma_f16(acc[mt][2 * p],     af[mt], &bf[p][0]);
                    mma_f16(acc[mt][2 * p + 1], af[mt], &bf[p][2]);
                }
        }

        if (more) {
            const int s = ((it + 1) & 1) * HBUF;
            *(uint4*)&As[s + ar0 * HS + aq0] = ra0;
            *(uint4*)&As[s + ar1 * HS + aq1] = ra1;
            *(uint4*)&Bs[s + ar0 * HS + aq0] = rb0;
            *(uint4*)&Bs[s + ar1 * HS + aq1] = rb1;
        }
        __syncthreads();
    }

    if (MAXRED) {
        float mx = -3.4e38f;
#pragma unroll
        for (int mt = 0; mt < 2; mt++)
#pragma unroll
            for (int nt = 0; nt < 8; nt++)
#pragma unroll
                for (int i = 0; i < 4; i++) mx = fmaxf(mx, acc[mt][nt][i]);
#pragma unroll
        for (int o = 16; o; o >>= 1) mx = fmaxf(mx, __shfl_xor_sync(0xffffffffu, mx, o));
        if (lane == 0) {
            unsigned u = __float_as_uint(mx);
            u = (u & 0x80000000u) ? ~u : (u | 0x80000000u);
            atomicMax(gmax, u);
        }
    }

#pragma unroll
    for (int mt = 0; mt < 2; mt++) {
#pragma unroll
        for (int nt = 0; nt < 8; nt++) {
            size_t row = m0 + wm + mt * 16 + (lane >> 2);
            int col = n0 + wn + nt * 8 + ((lane & 3) << 1);
            float2 lo = make_float2(acc[mt][nt][0], acc[mt][nt][1]);
            float2 hi = make_float2(acc[mt][nt][2], acc[mt][nt][3]);
            if (EPI == EPI_BIAS || EPI == EPI_BIAS_ELU) {
                float2 bb = *(const float2*)(bias + col);
                lo.x += bb.x; lo.y += bb.y;
                hi.x += bb.x; hi.y += bb.y;
            }
            if (EPI == EPI_BIAS_ELU) {
                lo.x = lo.x > 0.f ? lo.x : expm1f(lo.x);
                lo.y = lo.y > 0.f ? lo.y : expm1f(lo.y);
                hi.x = hi.x > 0.f ? hi.x : expm1f(hi.x);
                hi.y = hi.y > 0.f ? hi.y : expm1f(hi.y);
            }
            if (sizeof(OutT) == 2) {
                *(__half2*)((__half*)C + row * N + col)       = __floats2half2_rn(lo.x, lo.y);
                *(__half2*)((__half*)C + (row + 8) * N + col) = __floats2half2_rn(hi.x, hi.y);
            } else {
                if (RND) {
                    lo.x = rtf(lo.x); lo.y = rtf(lo.y);
                    hi.x = rtf(hi.x); hi.y = rtf(hi.y);
                }
                *(float2*)((float*)C + row * N + col)       = lo;
                *(float2*)((float*)C + (row + 8) * N + col) = hi;
            }
        }
    }
}

// ------------- tf32 batched strided GEMM over (b,h), optional split-K --------
#define APAD 20
#define AT_PAD 136
#define BH_BPAD 72

template<bool TRANSA, bool DIV, bool RND, typename OutT, int NSPLIT>
__global__ __launch_bounds__(256, 2)
void tgemm_bh(const float* __restrict__ A, size_t sAb, size_t sAh, int lda,
              const float* __restrict__ B, size_t sBb, size_t sBh, int ldb,
              OutT* __restrict__ C, size_t sCb, size_t sCh, int ldc, size_t sCsplit,
              const float* __restrict__ aux, size_t sXb, size_t sXh, int ldx,
              int M, int N, int K)
{
    __shared__ float As[128 * APAD];
    __shared__ float Bs[16 * BH_BPAD];

    const int z     = blockIdx.z;
    const int split = (NSPLIT > 1) ? (z >> 6) : 0;
    const int zz    = (NSPLIT > 1) ? (z & 63) : z;
    const int zb = zz >> 4, zh = zz & 15;
    const float* Ab = A + (size_t)zb * sAb + (size_t)zh * sAh;
    const float* Bb = B + (size_t)zb * sBb + (size_t)zh * sBh;
    OutT*        Cb = C + (size_t)zb * sCb + (size_t)zh * sCh
                        + (size_t)split * sCsplit;
    if (NSPLIT > 1) {
        if (TRANSA) Ab += (size_t)split * K * lda;
        else        Ab += (size_t)split * K;
        Bb += (size_t)split * K * ldb;
    }

    const int tid  = threadIdx.x;
    const int wid  = tid >> 5;
    const int lane = tid & 31;
    const int wm   = (wid >> 1) * 32;
    const int wn   = (wid & 1)  * 32;
    const int m0   = blockIdx.y * 128;
    const int n0   = blockIdx.x * 64;

    const int t_kr = tid >> 5;
    const int t_mc = lane << 2;
    const int n_row = tid & 127;
    const int n_kh  = (tid >> 7) << 3;
    const int b_kr = tid >> 4;
    const int b_nc = (tid & 15) << 2;

    float4 ra[2], rb1;
    float acc[2][4][4];
#pragma unroll
    for (int mt = 0; mt < 2; mt++)
#pragma unroll
        for (int nt = 0; nt < 4; nt++)
#pragma unroll
            for (int i = 0; i < 4; i++) acc[mt][nt][i] = 0.f;

    const int iters = K >> 4;

    auto ldA = [&](int k0) {
        if (TRANSA) {
            ra[0] = *(const float4*)(Ab + (size_t)(k0 + t_kr)     * lda + m0 + t_mc);
            ra[1] = *(const float4*)(Ab + (size_t)(k0 + t_kr + 8) * lda + m0 + t_mc);
        } else {
            ra[0] = *(const float4*)(Ab + (size_t)(m0 + n_row) * lda + k0 + n_kh);
            ra[1] = *(const float4*)(Ab + (size_t)(m0 + n_row) * lda + k0 + n_kh + 4);
        }
    };
    auto ldB = [&](int k0) {
        rb1 = *(const float4*)(Bb + (size_t)(k0 + b_kr) * ldb + n0 + b_nc);
    };

    ldA(0); ldB(0);

    for (int it = 0; it < iters; it++) {
        if (TRANSA) {
            *(float4*)&As[t_kr * AT_PAD + t_mc]       = ra[0];
            *(float4*)&As[(t_kr + 8) * AT_PAD + t_mc] = ra[1];
        } else {
            *(float4*)&As[n_row * APAD + n_kh]     = ra[0];
            *(float4*)&As[n_row * APAD + n_kh + 4] = ra[1];
        }
        *(float4*)&Bs[b_kr * BH_BPAD + b_nc] = rb1;
        __syncthreads();

        if (it + 1 < iters) { ldA((it + 1) << 4); ldB((it + 1) << 4); }

#pragma unroll
        for (int ks = 0; ks < 16; ks += 8) {
            unsigned af[2][4], bf[4][2];
#pragma unroll
            for (int mt = 0; mt < 2; mt++) {
                int r = wm + mt * 16 + (lane >> 2);
                int c = ks + (lane & 3);
                if (TRANSA) {
                    af[mt][0] = __float_as_uint(As[c * AT_PAD + r]);
                    af[mt][1] = __float_as_uint(As[c * AT_PAD + r + 8]);
                    af[mt][2] = __float_as_uint(As[(c + 4) * AT_PAD + r]);
                    af[mt][3] = __float_as_uint(As[(c + 4) * AT_PAD + r + 8]);
                } else {
                    af[mt][0] = __float_as_uint(As[r * APAD + c]);
                    af[mt][1] = __float_as_uint(As[(r + 8) * APAD + c]);
                    af[mt][2] = __float_as_uint(As[r * APAD + c + 4]);
                    af[mt][3] = __float_as_uint(As[(r + 8) * APAD + c + 4]);
                }
            }
#pragma unroll
            for (int nt = 0; nt < 4; nt++) {
                int c = wn + nt * 8 + (lane >> 2);
                int r = ks + (lane & 3);
                bf[nt][0] = __float_as_uint(Bs[r * BH_BPAD + c]);
                bf[nt][1] = __float_as_uint(Bs[(r + 4) * BH_BPAD + c]);
            }
#pragma unroll
            for (int mt = 0; mt < 2; mt++)
#pragma unroll
                for (int nt = 0; nt < 4; nt++)
                    mma_tf32(acc[mt][nt], af[mt], bf[nt]);
        }
        __syncthreads();
    }

#pragma unroll
    for (int mt = 0; mt < 2; mt++) {
        int row = m0 + wm + mt * 16 + (lane >> 2);
        float dv0 = 1.f, dv1 = 1.f;
        if (DIV) {
            dv0 = 1.f / aux[(size_t)zb * sXb + (size_t)zh * sXh + (size_t)row * ldx];
            dv1 = 1.f / aux[(size_t)zb * sXb + (size_t)zh * sXh + (size_t)(row + 8) * ldx];
        }
#pragma unroll
        for (int nt = 0; nt < 4; nt++) {
            int col = n0 + wn + nt * 8 + ((lane & 3) << 1);
            float2 lo = make_float2(acc[mt][nt][0] * dv0, acc[mt][nt][1] * dv0);
            float2 hi = make_float2(acc[mt][nt][2] * dv1, acc[mt][nt][3] * dv1);
            if (sizeof(OutT) == 2) {
                *(__half2*)((__half*)Cb + (size_t)row * ldc + col)       = __floats2half2_rn(lo.x, lo.y);
                *(__half2*)((__half*)Cb + (size_t)(row + 8) * ldc + col) = __floats2half2_rn(hi.x, hi.y);
            } else {
                if (RND) {
                    lo.x = rtf(lo.x); lo.y = rtf(lo.y);
                    hi.x = rtf(hi.x); hi.y = rtf(hi.y);
                }
                *(float2*)((float*)Cb + (size_t)row * ldc + col)       = lo;
                *(float2*)((float*)Cb + (size_t)(row + 8) * ldc + col) = hi;
            }
        }
    }
}

// ---------------- small helper kernels --------------------------------------
__global__ void k_half4(const float4* __restrict__ in, __half2* __restrict__ out,
                        int n4)
{
    int i = blockIdx.x * 256 + threadIdx.x;
    if (i < n4) {
        float4 v = in[i];
        out[2 * i]     = __floats2half2_rn(v.x, v.y);
        out[2 * i + 1] = __floats2half2_rn(v.z, v.w);
    }
}

__global__ void k_transH(const float* __restrict__ in, __half* __restrict__ out,
                         int K, int N)
{
    __shared__ float t[32][33];
    const int n0 = blockIdx.x * 32, k0 = blockIdx.y * 32;
#pragma unroll
    for (int i = 0; i < 4; i++) {
        int kk = threadIdx.y + i * 8;
        t[kk][threadIdx.x] = in[(size_t)(k0 + kk) * N + n0 + threadIdx.x];
    }
    __syncthreads();
#pragma unroll
    for (int i = 0; i < 4; i++) {
        int nn = threadIdx.y + i * 8;
        out[(size_t)(n0 + nn) * K + k0 + threadIdx.x] = __float2half(t[threadIdx.x][nn]);
    }
}

__global__ void k_projH(const float* __restrict__ proj, __half* __restrict__ ph)
{
    int i = blockIdx.x * 256 + threadIdx.x;
    if (i < MMF * DHH)
        ph[i] = __float2half(proj[i] * 0.35355339059327373f);
}

__global__ void k_kvred(const float4* __restrict__ part, float4* __restrict__ kv)
{
    int i = blockIdx.x * 256 + threadIdx.x;
    if (i < KVN / 4) {
        float4 a = part[i];
        float4 b = part[i + KVN / 4];
        float4 c = part[i + 2 * (KVN / 4)];
        float4 d = part[i + 3 * (KVN / 4)];
        kv[i] = make_float4(rtf(a.x + b.x + c.x + d.x),
                            rtf(a.y + b.y + c.y + d.y),
                            rtf(a.z + b.z + c.z + d.z),
                            rtf(a.w + b.w + c.w + d.w));
    }
}

__device__ __forceinline__ float unflip(unsigned u)
{
    return __uint_as_float((u & 0x80000000u) ? (u ^ 0x80000000u) : ~u);
}

__global__ void k_expq(float* __restrict__ dd, const __half* __restrict__ q)
{
    size_t w   = ((size_t)blockIdx.x * blockDim.x + threadIdx.x) >> 5;
    int   lane = threadIdx.x & 31;
    float4* row = (float4*)(dd + w * 256);
    float4 v0 = row[lane];
    float4 v1 = row[lane + 32];
    float m = fmaxf(fmaxf(fmaxf(v0.x, v0.y), fmaxf(v0.z, v0.w)),
                    fmaxf(fmaxf(v1.x, v1.y), fmaxf(v1.z, v1.w)));
#pragma unroll
    for (int o = 16; o; o >>= 1) m = fmaxf(m, __shfl_xor_sync(0xffffffffu, m, o));
    float2 qq = __half22float2(((const __half2*)(q + w * 64))[lane]);
    float ss = qq.x * qq.x + qq.y * qq.y;
#pragma unroll
    for (int o = 16; o; o >>= 1) ss += __shfl_xor_sync(0xffffffffu, ss, o);
    float c = 0.0625f * ss + m;
    v0.x = rtf(0.0625f * (expf(v0.x - c) + 1e-6f));
    v0.y = rtf(0.0625f * (expf(v0.y - c) + 1e-6f));
    v0.z = rtf(0.0625f * (expf(v0.z - c) + 1e-6f));
    v0.w = rtf(0.0625f * (expf(v0.w - c) + 1e-6f));
    v1.x = rtf(0.0625f * (expf(v1.x - c) + 1e-6f));
    v1.y = rtf(0.0625f * (expf(v1.y - c) + 1e-6f));
    v1.z = rtf(0.0625f * (expf(v1.z - c) + 1e-6f));
    v1.w = rtf(0.0625f * (expf(v1.w - c) + 1e-6f));
    row[lane] = v0; row[lane + 32] = v1;
}

__global__ void k_expk(float* __restrict__ dd, const __half* __restrict__ k,
                       const unsigned* __restrict__ gmax)
{
    size_t w   = ((size_t)blockIdx.x * blockDim.x + threadIdx.x) >> 5;
    int   lane = threadIdx.x & 31;
    float4* row = (float4*)(dd + w * 256);
    float4 v0 = row[lane];
    float4 v1 = row[lane + 32];
    float2 kk = __half22float2(((const __half2*)(k + w * 64))[lane]);
    float ss = kk.x * kk.x + kk.y * kk.y;
#pragma unroll
    for (int o = 16; o; o >>= 1) ss += __shfl_xor_sync(0xffffffffu, ss, o);
    float c = 0.0625f * ss + unflip(*gmax);
    v0.x = rtf(0.0625f * (expf(v0.x - c) + 1e-6f));
    v0.y = rtf(0.0625f * (expf(v0.y - c) + 1e-6f));
    v0.z = rtf(0.0625f * (expf(v0.z - c) + 1e-6f));
    v0.w = rtf(0.0625f * (expf(v0.w - c) + 1e-6f));
    v1.x = rtf(0.0625f * (expf(v1.x - c) + 1e-6f));
    v1.y = rtf(0.0625f * (expf(v1.y - c) + 1e-6f));
    v1.z = rtf(0.0625f * (expf(v1.z - c) + 1e-6f));
    v1.w = rtf(0.0625f * (expf(v1.w - c) + 1e-6f));
    row[lane] = v0; row[lane + 32] = v1;
}

__global__ void k_ksum(const float* __restrict__ kp, float* __restrict__ ksum)
{
    int z = blockIdx.y;
    int b = z >> 4, h = z & 15;
    int m = threadIdx.x;
    size_t base = (size_t)b * 16777216 + (size_t)h * 256 + m;
    float s = 0.f;
    int l0 = blockIdx.x * 512;
    for (int l = l0; l < l0 + 512; l++) s += kp[base + (size_t)l * 4096];
    atomicAdd(&ksum[z * 256 + m], s);
}

__global__ void k_denom(const float* __restrict__ qp, const float* __restrict__ ksum,
                        float* __restrict__ den)
{
    size_t w   = ((size_t)blockIdx.x * blockDim.x + threadIdx.x) >> 5;
    int   lane = threadIdx.x & 31;
    int   b    = (int)(w >> 16);
    int   h    = (int)(w & 15);
    const float4* row = (const float4*)(qp + w * 256);
    const float4* ks  = (const float4*)(ksum + ((size_t)b * 16 + h) * 256);
    float4 a0 = row[lane], a1 = row[lane + 32];
    float4 k0 = ks[lane],  k1 = ks[lane + 32];
    float s = a0.x * k0.x + a0.y * k0.y + a0.z * k0.z + a0.w * k0.w
            + a1.x * k1.x + a1.y * k1.y + a1.z * k1.z + a1.w * k1.w;
#pragma unroll
    for (int o = 16; o; o >>= 1) s += __shfl_xor_sync(0xffffffffu, s, o);
    if (lane == 0) den[w] = s;
}

template<bool WRITE_H>
__global__ void k_ln(const float* __restrict__ a, const float* __restrict__ r,
                     const float* __restrict__ g, const float* __restrict__ b,
                     float* __restrict__ out, __half* __restrict__ outh)
{
    const int row = blockIdx.x;
    const int t   = threadIdx.x;
    const size_t base = (size_t)row * 1024;
    float4 xa = *(const float4*)(a + base + t * 4);
    float4 xr = *(const float4*)(r + base + t * 4);
    float4 s  = make_float4(xa.x + xr.x, xa.y + xr.y, xa.z + xr.z, xa.w + xr.w);
    float sum = s.x + s.y + s.z + s.w;
    float sq  = s.x * s.x + s.y * s.y + s.z * s.z + s.w * s.w;
#pragma unroll
    for (int o = 16; o; o >>= 1) {
        sum += __shfl_xor_sync(0xffffffffu, sum, o);
        sq  += __shfl_xor_sync(0xffffffffu, sq,  o);
    }
    __shared__ float ssum[8], ssq[8];
    __shared__ float s_mu, s_inv;
    int w = t >> 5;
    if ((t & 31) == 0) { ssum[w] = sum; ssq[w] = sq; }
    __syncthreads();
    if (t == 0) {
        float ts = 0.f, tq = 0.f;
        for (int i = 0; i < 8; i++) { ts += ssum[i]; tq += ssq[i]; }
        float mu  = ts * (1.f / 1024.f);
        float var = tq * (1.f / 1024.f) - mu * mu;
        s_mu = mu;
        s_inv = rsqrtf(var + 1e-6f);
    }
    __syncthreads();
    float mu = s_mu, inv = s_inv;
    float4 gg = *(const float4*)(g + t * 4);
    float4 bb = *(const float4*)(b + t * 4);
    float4 o = make_float4((s.x - mu) * inv * gg.x + bb.x,
                           (s.y - mu) * inv * gg.y + bb.y,
                           (s.z - mu) * inv * gg.z + bb.z,
                           (s.w - mu) * inv * gg.w + bb.w);
    *(float4*)(out + base + t * 4) = o;
    if (WRITE_H) {
        __half2* oh = (__half2*)(outh + base + t * 4);
        oh[0] = __floats2half2_rn(o.x, o.y);
        oh[1] = __floats2half2_rn(o.z, o.w);
    }
}

// ---------------- driver -----------------------------------------------------
extern "C" void kernel_launch(void* const* d_in, const int* in_sizes, int n_in,
                              void* d_out, int out_size)
{
    const float* x    = (const float*)d_in[0];
    const float* wq   = (const float*)d_in[1];
    const float* wk   = (const float*)d_in[2];
    const float* wv   = (const float*)d_in[3];
    const float* wo   = (const float*)d_in[4];
    const float* proj = (const float*)d_in[5];
    const float* ln1g = (const float*)d_in[6];
    const float* ln1b = (const float*)d_in[7];
    const float* ln2g = (const float*)d_in[8];
    const float* ln2b = (const float*)d_in[9];
    const float* w1   = (const float*)d_in[10];
    const float* b1   = (const float*)d_in[11];
    const float* w2   = (const float*)d_in[12];
    const float* b2   = (const float*)d_in[13];
    float* out = (float*)d_out;

    float *p_v, *p_qp, *p_kp, *p_kv, *p_kvp, *p_ksum, *p_den, *p_tmp, *p_out1;
    __half *p_xh, *p_qh, *p_kh, *p_out1h, *p_attnh, *p_hh, *p_projh;
    __half *p_wqT, *p_wkT, *p_wvT, *p_woT, *p_w1T, *p_w2T;
    unsigned* p_kmax;
    cudaGetSymbolAddress((void**)&p_v,     g_v);
    cudaGetSymbolAddress((void**)&p_qp,    g_qp);
    cudaGetSymbolAddress((void**)&p_kp,    g_kp);
    cudaGetSymbolAddress((void**)&p_kv,    g_kv);
    cudaGetSymbolAddress((void**)&p_kvp,   g_kvp);
    cudaGetSymbolAddress((void**)&p_ksum,  g_ksum);
    cudaGetSymbolAddress((void**)&p_den,   g_den);
    cudaGetSymbolAddress((void**)&p_tmp,   g_tmp);
    cudaGetSymbolAddress((void**)&p_out1,  g_out1);
    cudaGetSymbolAddress((void**)&p_kmax,  g_kmax);
    cudaGetSymbolAddress((void**)&p_xh,    g_xh);
    cudaGetSymbolAddress((void**)&p_qh,    g_qh);
    cudaGetSymbolAddress((void**)&p_kh,    g_kh);
    cudaGetSymbolAddress((void**)&p_out1h, g_out1h);
    cudaGetSymbolAddress((void**)&p_attnh, g_attnh);
    cudaGetSymbolAddress((void**)&p_hh,    g_hh);
    cudaGetSymbolAddress((void**)&p_projh, g_projh);
    cudaGetSymbolAddress((void**)&p_wqT,   g_wqT);
    cudaGetSymbolAddress((void**)&p_wkT,   g_wkT);
    cudaGetSymbolAddress((void**)&p_wvT,   g_wvT);
    cudaGetSymbolAddress((void**)&p_woT,   g_woT);
    cudaGetSymbolAddress((void**)&p_w1T,   g_w1T);
    cudaGetSymbolAddress((void**)&p_w2T,   g_w2T);

    // prep
    k_half4<<<(NT * DD / 4 + 255) / 256, 256>>>((const float4*)x, (__half2*)p_xh, NT * DD / 4);
    k_transH<<<dim3(32, 32), dim3(32, 8)>>>(wq, p_wqT, DD, DD);
    k_transH<<<dim3(32, 32), dim3(32, 8)>>>(wk, p_wkT, DD, DD);
    k_transH<<<dim3(32, 32), dim3(32, 8)>>>(wv, p_wvT, DD, DD);
    k_projH<<<64, 256>>>(proj, p_projh);

    // q,k projections -> fp16; v -> fp32 (tf32-rounded)
    hgemm<EPI_NONE, __half, false, false><<<dim3(8, 128), 256>>>(p_xh, p_wqT, nullptr, p_qh, NT, 1024, 1024, nullptr);
    hgemm<EPI_NONE, __half, false, false><<<dim3(8, 128), 256>>>(p_xh, p_wkT, nullptr, p_kh, NT, 1024, 1024, nullptr);
    hgemm<EPI_NONE, float,  true,  false><<<dim3(8, 128), 256>>>(p_xh, p_wvT, nullptr, p_v,  NT, 1024, 1024, nullptr);

    // remaining prep
    k_transH<<<dim3(32, 32),  dim3(32, 8)>>>(wo, p_woT, DD, DD);
    k_transH<<<dim3(128, 32), dim3(32, 8)>>>(w1, p_w1T, DD, DFF);
    k_transH<<<dim3(32, 128), dim3(32, 8)>>>(w2, p_w2T, DFF, DD);

    cudaMemsetAsync(p_kmax, 0, 4);
    cudaMemsetAsync(p_ksum, 0, BB * HH * MMF * sizeof(float));

    // dd = q_resh[NR,64] @ proj^T -> fp32 ; dd_k also reduces global max
    hgemm<EPI_NONE, float, false, false><<<dim3(2, 2048), 256>>>(p_qh, p_projh, nullptr, p_qp, NR, 256, 64, nullptr);
    hgemm<EPI_NONE, float, false, true ><<<dim3(2, 2048), 256>>>(p_kh, p_projh, nullptr, p_kp, NR, 256, 64, p_kmax);

    k_expq<<<NR / 8, 256>>>(p_qp, p_qh);
    k_expk<<<NR / 8, 256>>>(p_kp, p_kh, p_kmax);

    // kv partials: split-K=4 over K=4096
    tgemm_bh<true, false, false, float, 4><<<dim3(1, 2, 256), 256>>>(
        p_kp, (size_t)16777216, (size_t)256, 4096,
        p_v,  (size_t)4194304,  (size_t)64,  1024,
        p_kvp, (size_t)(16 * 16384), (size_t)16384, 64, (size_t)KVN,
        nullptr, 0, 0, 0,
        256, 64, 1024);
    k_kvred<<<(KVN / 4 + 255) / 256, 256>>>((const float4*)p_kvp, (float4*)p_kv);

    k_ksum<<<dim3(8, 64), 256>>>(p_kp, p_ksum);
    k_denom<<<NR / 8, 256>>>(p_qp, p_ksum, p_den);

    // attn = (qp @ kv) / denom : tf32 -> fp16
    tgemm_bh<false, true, false, __half, 1><<<dim3(1, 32, 64), 256>>>(
        p_qp, (size_t)16777216, (size_t)256, 4096,
        p_kv, (size_t)(16 * 16384), (size_t)16384, 64,
        p_attnh, (size_t)4194304, (size_t)64, 1024, (size_t)0,
        p_den,  (size_t)65536,   (size_t)1,  16,
        4096, 64, 256);

    // attn_out = attn @ wo^T -> fp32 tmp
    hgemm<EPI_NONE, float, false, false><<<dim3(8, 128), 256>>>(p_attnh, p_woT, nullptr, p_tmp, NT, 1024, 1024, nullptr);

    // out1 = LN(x + attn_out) -> fp32 + fp16
    k_ln<true><<<NT, 256>>>(p_tmp, x, ln1g, ln1b, p_out1, p_out1h);

    // FFN
    hgemm<EPI_BIAS_ELU, __half, false, false><<<dim3(32, 128), 256>>>(p_out1h, p_w1T, b1, p_hh, NT, DFF, 1024, nullptr);
    hgemm<EPI_BIAS, float, false, false><<<dim3(8, 128), 256>>>(p_hh, p_w2T, b2, p_tmp, NT, 1024, DFF, nullptr);

    // out2 = LN(out1 + ffn)
    k_ln<false><<<NT, 256>>>(p_tmp, p_out1, ln2g, ln2b, out, nullptr);
}

// round 10
// speedup vs baseline: 2.5333x; 1.0893x over previous
#include <cuda_runtime.h>
#include <cuda_fp16.h>
#include <math.h>
#include <stdint.h>

#define BB   4
#define LL   4096
#define DD   1024
#define HH   16
#define DHH  64
#define MMF  256
#define DFF  4096
#define NT   (BB*LL)      /* 16384 tokens  */
#define NR   (NT*HH)      /* 262144 (t,h) rows */
#define KVN  (BB*HH*MMF*DHH)   /* 1048576 */

// ---------------- scratch (device globals; no allocation allowed) ----------
__device__ float  g_qp   [(size_t)NR*MMF];      // dd_q (fp32)
__device__ float  g_kp   [(size_t)NR*MMF];      // dd_k (fp32)
__device__ float  g_kvp  [4*KVN];               // split-K partials (fp32)
__device__ float  g_ksum [BB*HH*MMF];
__device__ float  g_den  [NR];
__device__ float  g_tmp  [(size_t)NT*DD];
__device__ float  g_out1 [(size_t)NT*DD];
__device__ unsigned g_kmax;
// fp16 buffers
__device__ __half g_xh   [(size_t)NT*DD];
__device__ __half g_qh   [(size_t)NT*DD];
__device__ __half g_kh   [(size_t)NT*DD];
__device__ __half g_vh   [(size_t)NT*DD];
__device__ __half g_qph  [(size_t)NR*MMF];
__device__ __half g_kph  [(size_t)NR*MMF];
__device__ __half g_kvh  [KVN];
__device__ __half g_out1h[(size_t)NT*DD];
__device__ __half g_attnh[(size_t)NT*DD];
__device__ __half g_hh   [(size_t)NT*DFF];
__device__ __half g_projh[MMF*DHH];
__device__ __half g_wqT  [DD*DD];
__device__ __half g_wkT  [DD*DD];
__device__ __half g_wvT  [DD*DD];
__device__ __half g_woT  [DD*DD];
__device__ __half g_w1T  [(size_t)DFF*DD];
__device__ __half g_w2T  [(size_t)DD*DFF];

enum { EPI_NONE = 0, EPI_BIAS = 1, EPI_BIAS_ELU = 2 };

// ---------------- helpers ----------------------------------------------------
__device__ __forceinline__ float rtf(float x)
{
    unsigned u;
    asm("cvt.rna.tf32.f32 %0, %1;" : "=r"(u) : "f"(x));
    return __uint_as_float(u);
}

__device__ __forceinline__ void mma_f16(float* d, const unsigned* a,
                                        const unsigned* b)
{
    asm volatile(
        "mma.sync.aligned.m16n8k16.row.col.f32.f16.f16.f32 "
        "{%0,%1,%2,%3}, {%4,%5,%6,%7}, {%8,%9}, {%0,%1,%2,%3};\n"
        : "+f"(d[0]), "+f"(d[1]), "+f"(d[2]), "+f"(d[3])
        : "r"(a[0]), "r"(a[1]), "r"(a[2]), "r"(a[3]),
          "r"(b[0]), "r"(b[1]));
}

__device__ __forceinline__ void ldsm_x4(unsigned* r, unsigned addr)
{
    asm volatile("ldmatrix.sync.aligned.m8n8.x4.shared.b16 {%0,%1,%2,%3}, [%4];"
        : "=r"(r[0]), "=r"(r[1]), "=r"(r[2]), "=r"(r[3]) : "r"(addr));
}

__device__ __forceinline__ void ldsm_x4t(unsigned* r, unsigned addr)
{
    asm volatile("ldmatrix.sync.aligned.m8n8.x4.trans.shared.b16 {%0,%1,%2,%3}, [%4];"
        : "=r"(r[0]), "=r"(r[1]), "=r"(r[2]), "=r"(r[3]) : "r"(addr));
}

// ---------------- fp16 tensor-core GEMM: C[M,N] = A[M,K] @ B^T ----------------
// (unchanged from R9 — proven) double-buffered, ldmatrix, 8 warps 32x64.
#define HS 40
#define HBUF (128 * HS)
#define HBUFB (HBUF * 2)

template<int EPI, typename OutT, bool RND, bool MAXRED>
__global__ __launch_bounds__(256, 2)
void hgemm(const __half* __restrict__ A, const __half* __restrict__ B,
           const float* __restrict__ bias, OutT* __restrict__ C,
           int M, int N, int K, unsigned* __restrict__ gmax)
{
    __shared__ __align__(16) __half As[2 * HBUF];
    __shared__ __align__(16) __half Bs[2 * HBUF];

    const int tid  = threadIdx.x;
    const int wid  = tid >> 5;
    const int lane = tid & 31;
    const int wm   = (wid >> 1) * 32;
    const int wn   = (wid & 1)  * 64;
    const size_t m0 = (size_t)blockIdx.y * 128;
    const int    n0 = blockIdx.x * 128;

    const int ar0 = tid >> 2,          aq0 = (tid & 3) << 3;
    const int ar1 = (tid + 256) >> 2,  aq1 = ((tid + 256) & 3) << 3;

    const int matid = lane >> 3, rowin = lane & 7;
    const unsigned sAb = (unsigned)__cvta_generic_to_shared(As);
    const unsigned sBb = (unsigned)__cvta_generic_to_shared(Bs);
    unsigned aoff[2], boff[4];
#pragma unroll
    for (int mt = 0; mt < 2; mt++)
        aoff[mt] = sAb + (unsigned)(((wm + mt * 16 + rowin + ((matid & 1) << 3)) * HS
                                     + ((matid & 2) << 2)) << 1);
#pragma unroll
    for (int p = 0; p < 4; p++)
        boff[p] = sBb + (unsigned)(((wn + ((p << 1) + ((matid >> 1) & 1)) * 8 + rowin) * HS
                                     + ((matid & 1) << 3)) << 1);

    uint4 ra0, ra1, rb0, rb1;
    float acc[2][8][4];
#pragma unroll
    for (int mt = 0; mt < 2; mt++)
#pragma unroll
        for (int nt = 0; nt < 8; nt++)
#pragma unroll
            for (int i = 0; i < 4; i++) acc[mt][nt][i] = 0.f;

    const int iters = K >> 5;

    ra0 = *(const uint4*)(A + (m0 + ar0) * K + aq0);
    ra1 = *(const uint4*)(A + (m0 + ar1) * K + aq1);
    rb0 = *(const uint4*)(B + (size_t)(n0 + ar0) * K + aq0);
    rb1 = *(const uint4*)(B + (size_t)(n0 + ar1) * K + aq1);
    *(uint4*)&As[ar0 * HS + aq0] = ra0;
    *(uint4*)&As[ar1 * HS + aq1] = ra1;
    *(uint4*)&Bs[ar0 * HS + aq0] = rb0;
    *(uint4*)&Bs[ar1 * HS + aq1] = rb1;
    __syncthreads();

    for (int it = 0; it < iters; it++) {
        const bool more = (it + 1 < iters);
        if (more) {
            int k0 = (it + 1) << 5;
            ra0 = *(const uint4*)(A + (m0 + ar0) * K + k0 + aq0);
            ra1 = *(const uint4*)(A + (m0 + ar1) * K + k0 + aq1);
            rb0 = *(const uint4*)(B + (size_t)(n0 + ar0) * K + k0 + aq0);
            rb1 = *(const uint4*)(B + (size_t)(n0 + ar1) * K + k0 + aq1);
        }

        const unsigned bo = (unsigned)((it & 1) * HBUFB);
#pragma unroll
        for (int ks = 0; ks < 2; ks++) {
            const unsigned cb = bo + (unsigned)(ks << 5);
            unsigned af[2][4], bf[4][4];
#pragma unroll
            for (int mt = 0; mt < 2; mt++) ldsm_x4(af[mt], aoff[mt] + cb);
#pragma unroll
            for (int p = 0; p < 4; p++)   ldsm_x4(bf[p],  boff[p]  + cb);
#pragma unroll
            for (int mt = 0; mt < 2; mt++)
#pragma unroll
                for (int p = 0; p < 4; p++) {
                    mma_f16(acc[mt][2 * p],     af[mt], &bf[p][0]);
                    mma_f16(acc[mt][2 * p + 1], af[mt], &bf[p][2]);
                }
        }

        if (more) {
            const int s = ((it + 1) & 1) * HBUF;
            *(uint4*)&As[s + ar0 * HS + aq0] = ra0;
            *(uint4*)&As[s + ar1 * HS + aq1] = ra1;
            *(uint4*)&Bs[s + ar0 * HS + aq0] = rb0;
            *(uint4*)&Bs[s + ar1 * HS + aq1] = rb1;
        }
        __syncthreads();
    }

    if (MAXRED) {
        float mx = -3.4e38f;
#pragma unroll
        for (int mt = 0; mt < 2; mt++)
#pragma unroll
            for (int nt = 0; nt < 8; nt++)
#pragma unroll
                for (int i = 0; i < 4; i++) mx = fmaxf(mx, acc[mt][nt][i]);
#pragma unroll
        for (int o = 16; o; o >>= 1) mx = fmaxf(mx, __shfl_xor_sync(0xffffffffu, mx, o));
        if (lane == 0) {
            unsigned u = __float_as_uint(mx);
            u = (u & 0x80000000u) ? ~u : (u | 0x80000000u);
            atomicMax(gmax, u);
        }
    }

#pragma unroll
    for (int mt = 0; mt < 2; mt++) {
#pragma unroll
        for (int nt = 0; nt < 8; nt++) {
            size_t row = m0 + wm + mt * 16 + (lane >> 2);
            int col = n0 + wn + nt * 8 + ((lane & 3) << 1);
            float2 lo = make_float2(acc[mt][nt][0], acc[mt][nt][1]);
            float2 hi = make_float2(acc[mt][nt][2], acc[mt][nt][3]);
            if (EPI == EPI_BIAS || EPI == EPI_BIAS_ELU) {
                float2 bb = *(const float2*)(bias + col);
                lo.x += bb.x; lo.y += bb.y;
                hi.x += bb.x; hi.y += bb.y;
            }
            if (EPI == EPI_BIAS_ELU) {
                lo.x = lo.x > 0.f ? lo.x : expm1f(lo.x);
                lo.y = lo.y > 0.f ? lo.y : expm1f(lo.y);
                hi.x = hi.x > 0.f ? hi.x : expm1f(hi.x);
                hi.y = hi.y > 0.f ? hi.y : expm1f(hi.y);
            }
            if (sizeof(OutT) == 2) {
                *(__half2*)((__half*)C + row * N + col)       = __floats2half2_rn(lo.x, lo.y);
                *(__half2*)((__half*)C + (row + 8) * N + col) = __floats2half2_rn(hi.x, hi.y);
            } else {
                if (RND) {
                    lo.x = rtf(lo.x); lo.y = rtf(lo.y);
                    hi.x = rtf(hi.x); hi.y = rtf(hi.y);
                }
                *(float2*)((float*)C + row * N + col)       = lo;
                *(float2*)((float*)C + (row + 8) * N + col) = hi;
            }
        }
    }
}

// ------------- fp16 batched strided GEMM over (b,h), optional split-K --------
// TRANSA: A stored [k][m] (kp: rows l, cols m) -> .trans ldmatrix.
// B always stored [k][n] -> .trans ldmatrix.
// BM=128, BN=64, BK=32, 8 warps (4m x 2n), warp tile 32x32, double-buffered.
#define BAS 136    /* TRANSA A smem row stride (halves), rows = k */
#define NAS 40     /* !TRANSA A smem row stride (halves), rows = m */
#define BBS 72     /* B smem row stride (halves), rows = k */

template<bool TRANSA, bool DIV, typename OutT, int NSPLIT>
__global__ __launch_bounds__(256, 2)
void hgemm_bh(const __half* __restrict__ A, size_t sAb, size_t sAh, int lda,
              const __half* __restrict__ B, size_t sBb, size_t sBh, int ldb,
              OutT* __restrict__ C, size_t sCb, size_t sCh, int ldc, size_t sCsplit,
              const float* __restrict__ aux, size_t sXb, size_t sXh, int ldx,
              int M, int N, int K)
{
    constexpr int ABUFH = TRANSA ? (32 * BAS) : (128 * NAS);
    constexpr int BBUFH = 32 * BBS;
    __shared__ __align__(16) __half As[2 * ABUFH];
    __shared__ __align__(16) __half Bs[2 * BBUFH];

    const int z     = blockIdx.z;
    const int split = (NSPLIT > 1) ? (z >> 6) : 0;
    const int zz    = (NSPLIT > 1) ? (z & 63) : z;
    const int zb = zz >> 4, zh = zz & 15;
    const __half* Ab = A + (size_t)zb * sAb + (size_t)zh * sAh;
    const __half* Bb = B + (size_t)zb * sBb + (size_t)zh * sBh;
    OutT*         Cb = C + (size_t)zb * sCb + (size_t)zh * sCh
                         + (size_t)split * sCsplit;
    if (NSPLIT > 1) {
        Ab += (size_t)split * K * lda;       // TRANSA only used with split
        Bb += (size_t)split * K * ldb;
    }

    const int tid  = threadIdx.x;
    const int wid  = tid >> 5;
    const int lane = tid & 31;
    const int wm   = (wid >> 1) * 32;
    const int wn   = (wid & 1)  * 32;
    const int m0   = blockIdx.y * 128;

    const int matid = lane >> 3, rowin = lane & 7;
    const unsigned sAs = (unsigned)__cvta_generic_to_shared(As);
    const unsigned sBs = (unsigned)__cvta_generic_to_shared(Bs);

    // fragment base offsets (bytes, buffer 0, ks=0)
    unsigned aoff[2], boff[2];
#pragma unroll
    for (int mt = 0; mt < 2; mt++) {
        if (TRANSA)
            aoff[mt] = sAs + (unsigned)(((rowin + ((matid >> 1) << 3)) * BAS
                                         + wm + mt * 16 + ((matid & 1) << 3)) << 1);
        else
            aoff[mt] = sAs + (unsigned)(((wm + mt * 16 + rowin + ((matid & 1) << 3)) * NAS
                                         + ((matid & 2) << 2)) << 1);
    }
#pragma unroll
    for (int p = 0; p < 2; p++)
        boff[p] = sBs + (unsigned)(((rowin + ((matid & 1) << 3)) * BBS
                                    + wn + (p << 4) + ((matid >> 1) << 3)) << 1);

    // staging indices
    const int ta_kr = tid >> 4, ta_mc = (tid & 15) << 3;   // TRANSA A: 2 passes (+16 rows)
    const int na_r0 = tid >> 2, na_k0 = (tid & 3) << 3;    // !TRANSA A: 2 passes (+64 rows)
    const int b_kr  = tid >> 3, b_nc  = (tid & 7) << 3;    // B: 1 pass

    uint4 ra0, ra1, rb;
    float acc[2][4][4];
#pragma unroll
    for (int mt = 0; mt < 2; mt++)
#pragma unroll
        for (int nt = 0; nt < 4; nt++)
#pragma unroll
            for (int i = 0; i < 4; i++) acc[mt][nt][i] = 0.f;

    const int iters = K >> 5;

    auto ld = [&](int k0) {
        if (TRANSA) {
            ra0 = *(const uint4*)(Ab + (size_t)(k0 + ta_kr)      * lda + m0 + ta_mc);
            ra1 = *(const uint4*)(Ab + (size_t)(k0 + ta_kr + 16) * lda + m0 + ta_mc);
        } else {
            ra0 = *(const uint4*)(Ab + (size_t)(m0 + na_r0)      * lda + k0 + na_k0);
            ra1 = *(const uint4*)(Ab + (size_t)(m0 + na_r0 + 64) * lda + k0 + na_k0);
        }
        rb = *(const uint4*)(Bb + (size_t)(k0 + b_kr) * ldb + b_nc);
    };
    auto st = [&](int s) {
        __half* as = As + s * ABUFH;
        __half* bs = Bs + s * BBUFH;
        if (TRANSA) {
            *(uint4*)&as[ta_kr * BAS + ta_mc]        = ra0;
            *(uint4*)&as[(ta_kr + 16) * BAS + ta_mc] = ra1;
        } else {
            *(uint4*)&as[na_r0 * NAS + na_k0]        = ra0;
            *(uint4*)&as[(na_r0 + 64) * NAS + na_k0] = ra1;
        }
        *(uint4*)&bs[b_kr * BBS + b_nc] = rb;
    };

    ld(0); st(0);
    __syncthreads();

    for (int it = 0; it < iters; it++) {
        const bool more = (it + 1 < iters);
        if (more) ld((it + 1) << 5);

        const unsigned ab = (unsigned)((it & 1) * (ABUFH * 2));
        const unsigned bb = (unsigned)((it & 1) * (BBUFH * 2));
#pragma unroll
        for (int ks = 0; ks < 2; ks++) {
            const unsigned aks = TRANSA ? (unsigned)(ks * 16 * BAS * 2) : (unsigned)(ks << 5);
            const unsigned bks = (unsigned)(ks * 16 * BBS * 2);
            unsigned af[2][4], bf[2][4];
#pragma unroll
            for (int mt = 0; mt < 2; mt++) {
                if (TRANSA) ldsm_x4t(af[mt], aoff[mt] + ab + aks);
                else        ldsm_x4 (af[mt], aoff[mt] + ab + aks);
            }
#pragma unroll
            for (int p = 0; p < 2; p++) ldsm_x4t(bf[p], boff[p] + bb + bks);
#pragma unroll
            for (int mt = 0; mt < 2; mt++)
#pragma unroll
                for (int p = 0; p < 2; p++) {
                    mma_f16(acc[mt][2 * p],     af[mt], &bf[p][0]);
                    mma_f16(acc[mt][2 * p + 1], af[mt], &bf[p][2]);
                }
        }

        if (more) st((it + 1) & 1);
        __syncthreads();
    }

#pragma unroll
    for (int mt = 0; mt < 2; mt++) {
        int row = m0 + wm + mt * 16 + (lane >> 2);
        float dv0 = 1.f, dv1 = 1.f;
        if (DIV) {
            dv0 = 1.f / aux[(size_t)zb * sXb + (size_t)zh * sXh + (size_t)row * ldx];
            dv1 = 1.f / aux[(size_t)zb * sXb + (size_t)zh * sXh + (size_t)(row + 8) * ldx];
        }
#pragma unroll
        for (int nt = 0; nt < 4; nt++) {
            int col = wn + nt * 8 + ((lane & 3) << 1);
            float2 lo = make_float2(acc[mt][nt][0] * dv0, acc[mt][nt][1] * dv0);
            float2 hi = make_float2(acc[mt][nt][2] * dv1, acc[mt][nt][3] * dv1);
            if (sizeof(OutT) == 2) {
                *(__half2*)((__half*)Cb + (size_t)row * ldc + col)       = __floats2half2_rn(lo.x, lo.y);
                *(__half2*)((__half*)Cb + (size_t)(row + 8) * ldc + col) = __floats2half2_rn(hi.x, hi.y);
            } else {
                *(float2*)((float*)Cb + (size_t)row * ldc + col)       = lo;
                *(float2*)((float*)Cb + (size_t)(row + 8) * ldc + col) = hi;
            }
        }
    }
}

// ---------------- small helper kernels --------------------------------------
__global__ void k_half4(const float4* __restrict__ in, __half2* __restrict__ out,
                        int n4)
{
    int i = blockIdx.x * 256 + threadIdx.x;
    if (i < n4) {
        float4 v = in[i];
        out[2 * i]     = __floats2half2_rn(v.x, v.y);
        out[2 * i + 1] = __floats2half2_rn(v.z, v.w);
    }
}

__global__ void k_transH(const float* __restrict__ in, __half* __restrict__ out,
                         int K, int N)
{
    __shared__ float t[32][33];
    const int n0 = blockIdx.x * 32, k0 = blockIdx.y * 32;
#pragma unroll
    for (int i = 0; i < 4; i++) {
        int kk = threadIdx.y + i * 8;
        t[kk][threadIdx.x] = in[(size_t)(k0 + kk) * N + n0 + threadIdx.x];
    }
    __syncthreads();
#pragma unroll
    for (int i = 0; i < 4; i++) {
        int nn = threadIdx.y + i * 8;
        out[(size_t)(n0 + nn) * K + k0 + threadIdx.x] = __float2half(t[threadIdx.x][nn]);
    }
}

__global__ void k_projH(const float* __restrict__ proj, __half* __restrict__ ph)
{
    int i = blockIdx.x * 256 + threadIdx.x;
    if (i < MMF * DHH)
        ph[i] = __float2half(proj[i] * 0.35355339059327373f);
}

// kv = fp16(sum of 4 split-K partials)
__global__ void k_kvred(const float4* __restrict__ part, __half2* __restrict__ kv)
{
    int i = blockIdx.x * 256 + threadIdx.x;
    if (i < KVN / 4) {
        float4 a = part[i];
        float4 b = part[i + KVN / 4];
        float4 c = part[i + 2 * (KVN / 4)];
        float4 d = part[i + 3 * (KVN / 4)];
        kv[2 * i]     = __floats2half2_rn(a.x + b.x + c.x + d.x, a.y + b.y + c.y + d.y);
        kv[2 * i + 1] = __floats2half2_rn(a.z + b.z + c.z + d.z, a.w + b.w + c.w + d.w);
    }
}

__device__ __forceinline__ float unflip(unsigned u)
{
    return __uint_as_float((u & 0x80000000u) ? (u ^ 0x80000000u) : ~u);
}

// qp(fp16) = ratio*(exp(dd - diag - rowmax) + eps); dd fp32 in, fp16 out
__global__ void k_expq(const float* __restrict__ dd, const __half* __restrict__ q,
                       __half* __restrict__ outp)
{
    size_t w   = ((size_t)blockIdx.x * blockDim.x + threadIdx.x) >> 5;
    int   lane = threadIdx.x & 31;
    const float4* row = (const float4*)(dd + w * 256);
    float4 v0 = row[lane];
    float4 v1 = row[lane + 32];
    float m = fmaxf(fmaxf(fmaxf(v0.x, v0.y), fmaxf(v0.z, v0.w)),
                    fmaxf(fmaxf(v1.x, v1.y), fmaxf(v1.z, v1.w)));
#pragma unroll
    for (int o = 16; o; o >>= 1) m = fmaxf(m, __shfl_xor_sync(0xffffffffu, m, o));
    float2 qq = __half22float2(((const __half2*)(q + w * 64))[lane]);
    float ss = qq.x * qq.x + qq.y * qq.y;
#pragma unroll
    for (int o = 16; o; o >>= 1) ss += __shfl_xor_sync(0xffffffffu, ss, o);
    float c = 0.0625f * ss + m;
    __half2* oh = (__half2*)(outp + w * 256);
    oh[lane * 2]      = __floats2half2_rn(0.0625f * (expf(v0.x - c) + 1e-6f),
                                          0.0625f * (expf(v0.y - c) + 1e-6f));
    oh[lane * 2 + 1]  = __floats2half2_rn(0.0625f * (expf(v0.z - c) + 1e-6f),
                                          0.0625f * (expf(v0.w - c) + 1e-6f));
    oh[64 + lane * 2] = __floats2half2_rn(0.0625f * (expf(v1.x - c) + 1e-6f),
                                          0.0625f * (expf(v1.y - c) + 1e-6f));
    oh[65 + lane * 2] = __floats2half2_rn(0.0625f * (expf(v1.z - c) + 1e-6f),
                                          0.0625f * (expf(v1.w - c) + 1e-6f));
}

__global__ void k_expk(const float* __restrict__ dd, const __half* __restrict__ k,
                       const unsigned* __restrict__ gmax, __half* __restrict__ outp)
{
    size_t w   = ((size_t)blockIdx.x * blockDim.x + threadIdx.x) >> 5;
    int   lane = threadIdx.x & 31;
    const float4* row = (const float4*)(dd + w * 256);
    float4 v0 = row[lane];
    float4 v1 = row[lane + 32];
    float2 kk = __half22float2(((const __half2*)(k + w * 64))[lane]);
    float ss = kk.x * kk.x + kk.y * kk.y;
#pragma unroll
    for (int o = 16; o; o >>= 1) ss += __shfl_xor_sync(0xffffffffu, ss, o);
    float c = 0.0625f * ss + unflip(*gmax);
    __half2* oh = (__half2*)(outp + w * 256);
    oh[lane * 2]      = __floats2half2_rn(0.0625f * (expf(v0.x - c) + 1e-6f),
                                          0.0625f * (expf(v0.y - c) + 1e-6f));
    oh[lane * 2 + 1]  = __floats2half2_rn(0.0625f * (expf(v0.z - c) + 1e-6f),
                                          0.0625f * (expf(v0.w - c) + 1e-6f));
    oh[64 + lane * 2] = __floats2half2_rn(0.0625f * (expf(v1.x - c) + 1e-6f),
                                          0.0625f * (expf(v1.y - c) + 1e-6f));
    oh[65 + lane * 2] = __floats2half2_rn(0.0625f * (expf(v1.z - c) + 1e-6f),
                                          0.0625f * (expf(v1.w - c) + 1e-6f));
}

// ksum[b,h,m] = sum_l kp[b,l,h,m] (fp16 in, fp32 atomics out)
__global__ void k_ksum(const __half* __restrict__ kp, float* __restrict__ ksum)
{
    int z = blockIdx.y;
    int b = z >> 4, h = z & 15;
    int m = threadIdx.x;
    size_t base = (size_t)b * 16777216 + (size_t)h * 256 + m;
    float s = 0.f;
    int l0 = blockIdx.x * 512;
    for (int l = l0; l < l0 + 512; l++) s += __half2float(kp[base + (size_t)l * 4096]);
    atomicAdd(&ksum[z * 256 + m], s);
}

// denom[r] = dot(qp_fp16[r,:], ksum[b,h,:]); warp per row
__global__ void k_denom(const __half* __restrict__ qp, const float* __restrict__ ksum,
                        float* __restrict__ den)
{
    size_t w   = ((size_t)blockIdx.x * blockDim.x + threadIdx.x) >> 5;
    int   lane = threadIdx.x & 31;
    int   b    = (int)(w >> 16);
    int   h    = (int)(w & 15);
    const __half2* row = (const __half2*)(qp + w * 256);
    const float4*  ks  = (const float4*)(ksum + ((size_t)b * 16 + h) * 256);
    float s = 0.f;
    float4 k0 = ks[lane * 2], k1 = ks[lane * 2 + 1];
    float2 a0 = __half22float2(row[lane * 4]);
    float2 a1 = __half22float2(row[lane * 4 + 1]);
    float2 a2 = __half22float2(row[lane * 4 + 2]);
    float2 a3 = __half22float2(row[lane * 4 + 3]);
    s = a0.x * k0.x + a0.y * k0.y + a1.x * k0.z + a1.y * k0.w
      + a2.x * k1.x + a2.y * k1.y + a3.x * k1.z + a3.y * k1.w;
#pragma unroll
    for (int o = 16; o; o >>= 1) s += __shfl_xor_sync(0xffffffffu, s, o);
    if (lane == 0) den[w] = s;
}

template<bool WRITE_H>
__global__ void k_ln(const float* __restrict__ a, const float* __restrict__ r,
                     const float* __restrict__ g, const float* __restrict__ b,
                     float* __restrict__ out, __half* __restrict__ outh)
{
    const int row = blockIdx.x;
    const int t   = threadIdx.x;
    const size_t base = (size_t)row * 1024;
    float4 xa = *(const float4*)(a + base + t * 4);
    float4 xr = *(const float4*)(r + base + t * 4);
    float4 s  = make_float4(xa.x + xr.x, xa.y + xr.y, xa.z + xr.z, xa.w + xr.w);
    float sum = s.x + s.y + s.z + s.w;
    float sq  = s.x * s.x + s.y * s.y + s.z * s.z + s.w * s.w;
#pragma unroll
    for (int o = 16; o; o >>= 1) {
        sum += __shfl_xor_sync(0xffffffffu, sum, o);
        sq  += __shfl_xor_sync(0xffffffffu, sq,  o);
    }
    __shared__ float ssum[8], ssq[8];
    __shared__ float s_mu, s_inv;
    int w = t >> 5;
    if ((t & 31) == 0) { ssum[w] = sum; ssq[w] = sq; }
    __syncthreads();
    if (t == 0) {
        float ts = 0.f, tq = 0.f;
        for (int i = 0; i < 8; i++) { ts += ssum[i]; tq += ssq[i]; }
        float mu  = ts * (1.f / 1024.f);
        float var = tq * (1.f / 1024.f) - mu * mu;
        s_mu = mu;
        s_inv = rsqrtf(var + 1e-6f);
    }
    __syncthreads();
    float mu = s_mu, inv = s_inv;
    float4 gg = *(const float4*)(g + t * 4);
    float4 bb = *(const float4*)(b + t * 4);
    float4 o = make_float4((s.x - mu) * inv * gg.x + bb.x,
                           (s.y - mu) * inv * gg.y + bb.y,
                           (s.z - mu) * inv * gg.z + bb.z,
                           (s.w - mu) * inv * gg.w + bb.w);
    *(float4*)(out + base + t * 4) = o;
    if (WRITE_H) {
        __half2* oh = (__half2*)(outh + base + t * 4);
        oh[0] = __floats2half2_rn(o.x, o.y);
        oh[1] = __floats2half2_rn(o.z, o.w);
    }
}

// ---------------- driver -----------------------------------------------------
extern "C" void kernel_launch(void* const* d_in, const int* in_sizes, int n_in,
                              void* d_out, int out_size)
{
    const float* x    = (const float*)d_in[0];
    const float* wq   = (const float*)d_in[1];
    const float* wk   = (const float*)d_in[2];
    const float* wv   = (const float*)d_in[3];
    const float* wo   = (const float*)d_in[4];
    const float* proj = (const float*)d_in[5];
    const float* ln1g = (const float*)d_in[6];
    const float* ln1b = (const float*)d_in[7];
    const float* ln2g = (const float*)d_in[8];
    const float* ln2b = (const float*)d_in[9];
    const float* w1   = (const float*)d_in[10];
    const float* b1   = (const float*)d_in[11];
    const float* w2   = (const float*)d_in[12];
    const float* b2   = (const float*)d_in[13];
    float* out = (float*)d_out;

    float *p_qp, *p_kp, *p_kvp, *p_ksum, *p_den, *p_tmp, *p_out1;
    __half *p_xh, *p_qh, *p_kh, *p_vh, *p_qph, *p_kph, *p_kvh;
    __half *p_out1h, *p_attnh, *p_hh, *p_projh;
    __half *p_wqT, *p_wkT, *p_wvT, *p_woT, *p_w1T, *p_w2T;
    unsigned* p_kmax;
    cudaGetSymbolAddress((void**)&p_qp,    g_qp);
    cudaGetSymbolAddress((void**)&p_kp,    g_kp);
    cudaGetSymbolAddress((void**)&p_kvp,   g_kvp);
    cudaGetSymbolAddress((void**)&p_ksum,  g_ksum);
    cudaGetSymbolAddress((void**)&p_den,   g_den);
    cudaGetSymbolAddress((void**)&p_tmp,   g_tmp);
    cudaGetSymbolAddress((void**)&p_out1,  g_out1);
    cudaGetSymbolAddress((void**)&p_kmax,  g_kmax);
    cudaGetSymbolAddress((void**)&p_xh,    g_xh);
    cudaGetSymbolAddress((void**)&p_qh,    g_qh);
    cudaGetSymbolAddress((void**)&p_kh,    g_kh);
    cudaGetSymbolAddress((void**)&p_vh,    g_vh);
    cudaGetSymbolAddress((void**)&p_qph,   g_qph);
    cudaGetSymbolAddress((void**)&p_kph,   g_kph);
    cudaGetSymbolAddress((void**)&p_kvh,   g_kvh);
    cudaGetSymbolAddress((void**)&p_out1h, g_out1h);
    cudaGetSymbolAddress((void**)&p_attnh, g_attnh);
    cudaGetSymbolAddress((void**)&p_hh,    g_hh);
    cudaGetSymbolAddress((void**)&p_projh, g_projh);
    cudaGetSymbolAddress((void**)&p_wqT,   g_wqT);
    cudaGetSymbolAddress((void**)&p_wkT,   g_wkT);
    cudaGetSymbolAddress((void**)&p_wvT,   g_wvT);
    cudaGetSymbolAddress((void**)&p_woT,   g_woT);
    cudaGetSymbolAddress((void**)&p_w1T,   g_w1T);
    cudaGetSymbolAddress((void**)&p_w2T,   g_w2T);

    // prep
    k_half4<<<(NT * DD / 4 + 255) / 256, 256>>>((const float4*)x, (__half2*)p_xh, NT * DD / 4);
    k_transH<<<dim3(32, 32), dim3(32, 8)>>>(wq, p_wqT, DD, DD);
    k_transH<<<dim3(32, 32), dim3(32, 8)>>>(wk, p_wkT, DD, DD);
    k_transH<<<dim3(32, 32), dim3(32, 8)>>>(wv, p_wvT, DD, DD);
    k_projH<<<64, 256>>>(proj, p_projh);

    // q,k,v projections -> fp16
    hgemm<EPI_NONE, __half, false, false><<<dim3(8, 128), 256>>>(p_xh, p_wqT, nullptr, p_qh, NT, 1024, 1024, nullptr);
    hgemm<EPI_NONE, __half, false, false><<<dim3(8, 128), 256>>>(p_xh, p_wkT, nullptr, p_kh, NT, 1024, 1024, nullptr);
    hgemm<EPI_NONE, __half, false, false><<<dim3(8, 128), 256>>>(p_xh, p_wvT, nullptr, p_vh, NT, 1024, 1024, nullptr);

    // remaining prep
    k_transH<<<dim3(32, 32),  dim3(32, 8)>>>(wo, p_woT, DD, DD);
    k_transH<<<dim3(128, 32), dim3(32, 8)>>>(w1, p_w1T, DD, DFF);
    k_transH<<<dim3(32, 128), dim3(32, 8)>>>(w2, p_w2T, DFF, DD);

    cudaMemsetAsync(p_kmax, 0, 4);
    cudaMemsetAsync(p_ksum, 0, BB * HH * MMF * sizeof(float));

    // dd -> fp32; dd_k also reduces global max
    hgemm<EPI_NONE, float, false, false><<<dim3(2, 2048), 256>>>(p_qh, p_projh, nullptr, p_qp, NR, 256, 64, nullptr);
    hgemm<EPI_NONE, float, false, true ><<<dim3(2, 2048), 256>>>(p_kh, p_projh, nullptr, p_kp, NR, 256, 64, p_kmax);

    // feature maps -> fp16
    k_expq<<<NR / 8, 256>>>(p_qp, p_qh, p_qph);
    k_expk<<<NR / 8, 256>>>(p_kp, p_kh, p_kmax, p_kph);

    // kv partials: fp16 split-K=4 over K=4096 (each 1024)
    hgemm_bh<true, false, float, 4><<<dim3(1, 2, 256), 256>>>(
        p_kph, (size_t)16777216, (size_t)256, 4096,
        p_vh,  (size_t)4194304,  (size_t)64,  1024,
        p_kvp, (size_t)(16 * 16384), (size_t)16384, 64, (size_t)KVN,
        nullptr, 0, 0, 0,
        256, 64, 1024);
    k_kvred<<<(KVN / 4 + 255) / 256, 256>>>((const float4*)p_kvp, (__half2*)p_kvh);

    k_ksum<<<dim3(8, 64), 256>>>(p_kph, p_ksum);
    k_denom<<<NR / 8, 256>>>(p_qph, p_ksum, p_den);

    // attn = (qp @ kv) / denom : fp16 -> fp16
    hgemm_bh<false, true, __half, 1><<<dim3(1, 32, 64), 256>>>(
        p_qph, (size_t)16777216, (size_t)256, 4096,
        p_kvh, (size_t)(16 * 16384), (size_t)16384, 64,
        p_attnh, (size_t)4194304, (size_t)64, 1024, (size_t)0,
        p_den,  (size_t)65536,   (size_t)1,  16,
        4096, 64, 256);

    // attn_out = attn @ wo^T -> fp32 tmp
    hgemm<EPI_NONE, float, false, false><<<dim3(8, 128), 256>>>(p_attnh, p_woT, nullptr, p_tmp, NT, 1024, 1024, nullptr);

    // out1 = LN(x + attn_out) -> fp32 + fp16
    k_ln<true><<<NT, 256>>>(p_tmp, x, ln1g, ln1b, p_out1, p_out1h);

    // FFN
    hgemm<EPI_BIAS_ELU, __half, false, false><<<dim3(32, 128), 256>>>(p_out1h, p_w1T, b1, p_hh, NT, DFF, 1024, nullptr);
    hgemm<EPI_BIAS, float, false, false><<<dim3(8, 128), 256>>>(p_hh, p_w2T, b2, p_tmp, NT, 1024, DFF, nullptr);

    // out2 = LN(out1 + ffn)
    k_ln<false><<<NT, 256>>>(p_tmp, p_out1, ln2g, ln2b, out, nullptr);
}

// round 11
// speedup vs baseline: 2.6829x; 1.0591x over previous
#include <cuda_runtime.h>
#include <cuda_fp16.h>
#include <math.h>
#include <stdint.h>

#define BB   4
#define LL   4096
#define DD   1024
#define HH   16
#define DHH  64
#define MMF  256
#define DFF  4096
#define NT   (BB*LL)      /* 16384 tokens  */
#define NR   (NT*HH)      /* 262144 (t,h) rows */
#define KVN  (BB*HH*MMF*DHH)   /* 1048576 */

// ---------------- scratch (device globals; no allocation allowed) ----------
__device__ float  g_kvp  [4*KVN];
__device__ float  g_ksum [BB*HH*MMF];
__device__ float  g_den  [NR];
__device__ float  g_tmp  [(size_t)NT*DD];
__device__ float  g_out1 [(size_t)NT*DD];
__device__ unsigned g_kmax;
// fp16 buffers
__device__ __half g_xh   [(size_t)NT*DD];
__device__ __half g_qh   [(size_t)NT*DD];
__device__ __half g_kh   [(size_t)NT*DD];
__device__ __half g_vh   [(size_t)NT*DD];
__device__ __half g_qph  [(size_t)NR*MMF];
__device__ __half g_kph  [(size_t)NR*MMF];
__device__ __half g_kvh  [KVN];
__device__ __half g_out1h[(size_t)NT*DD];
__device__ __half g_attnh[(size_t)NT*DD];
__device__ __half g_hh   [(size_t)NT*DFF];
__device__ __half g_projh[MMF*DHH];
__device__ __half g_wqT  [DD*DD];
__device__ __half g_wkT  [DD*DD];
__device__ __half g_wvT  [DD*DD];
__device__ __half g_woT  [DD*DD];
__device__ __half g_w1T  [(size_t)DFF*DD];
__device__ __half g_w2T  [(size_t)DD*DFF];

enum { EPI_NONE = 0, EPI_BIAS = 1, EPI_BIAS_ELU = 2 };
enum { DD_Q = 0, DD_KMAX = 1, DD_KEXP = 2 };

// ---------------- helpers ----------------------------------------------------
__device__ __forceinline__ float rtf(float x)
{
    unsigned u;
    asm("cvt.rna.tf32.f32 %0, %1;" : "=r"(u) : "f"(x));
    return __uint_as_float(u);
}

__device__ __forceinline__ void mma_f16(float* d, const unsigned* a,
                                        const unsigned* b)
{
    asm volatile(
        "mma.sync.aligned.m16n8k16.row.col.f32.f16.f16.f32 "
        "{%0,%1,%2,%3}, {%4,%5,%6,%7}, {%8,%9}, {%0,%1,%2,%3};\n"
        : "+f"(d[0]), "+f"(d[1]), "+f"(d[2]), "+f"(d[3])
        : "r"(a[0]), "r"(a[1]), "r"(a[2]), "r"(a[3]),
          "r"(b[0]), "r"(b[1]));
}

__device__ __forceinline__ void ldsm_x4(unsigned* r, unsigned addr)
{
    asm volatile("ldmatrix.sync.aligned.m8n8.x4.shared.b16 {%0,%1,%2,%3}, [%4];"
        : "=r"(r[0]), "=r"(r[1]), "=r"(r[2]), "=r"(r[3]) : "r"(addr));
}

__device__ __forceinline__ void ldsm_x4t(unsigned* r, unsigned addr)
{
    asm volatile("ldmatrix.sync.aligned.m8n8.x4.trans.shared.b16 {%0,%1,%2,%3}, [%4];"
        : "=r"(r[0]), "=r"(r[1]), "=r"(r[2]), "=r"(r[3]) : "r"(addr));
}

__device__ __forceinline__ float unflip(unsigned u)
{
    return __uint_as_float((u & 0x80000000u) ? (u ^ 0x80000000u) : ~u);
}

// ---------------- fp16 tensor-core GEMM: C[M,N] = A[M,K] @ B^T ----------------
// (unchanged from R10 — proven) double-buffered, ldmatrix, 8 warps 32x64.
#define HS 40
#define HBUF (128 * HS)
#define HBUFB (HBUF * 2)

template<int EPI, typename OutT, bool RND>
__global__ __launch_bounds__(256, 2)
void hgemm(const __half* __restrict__ A, const __half* __restrict__ B,
           const float* __restrict__ bias, OutT* __restrict__ C,
           int M, int N, int K)
{
    __shared__ __align__(16) __half As[2 * HBUF];
    __shared__ __align__(16) __half Bs[2 * HBUF];

    const int tid  = threadIdx.x;
    const int wid  = tid >> 5;
    const int lane = tid & 31;
    const int wm   = (wid >> 1) * 32;
    const int wn   = (wid & 1)  * 64;
    const size_t m0 = (size_t)blockIdx.y * 128;
    const int    n0 = blockIdx.x * 128;

    const int ar0 = tid >> 2,          aq0 = (tid & 3) << 3;
    const int ar1 = (tid + 256) >> 2,  aq1 = ((tid + 256) & 3) << 3;

    const int matid = lane >> 3, rowin = lane & 7;
    const unsigned sAb = (unsigned)__cvta_generic_to_shared(As);
    const unsigned sBb = (unsigned)__cvta_generic_to_shared(Bs);
    unsigned aoff[2], boff[4];
#pragma unroll
    for (int mt = 0; mt < 2; mt++)
        aoff[mt] = sAb + (unsigned)(((wm + mt * 16 + rowin + ((matid & 1) << 3)) * HS
                                     + ((matid & 2) << 2)) << 1);
#pragma unroll
    for (int p = 0; p < 4; p++)
        boff[p] = sBb + (unsigned)(((wn + ((p << 1) + ((matid >> 1) & 1)) * 8 + rowin) * HS
                                     + ((matid & 1) << 3)) << 1);

    uint4 ra0, ra1, rb0, rb1;
    float acc[2][8][4];
#pragma unroll
    for (int mt = 0; mt < 2; mt++)
#pragma unroll
        for (int nt = 0; nt < 8; nt++)
#pragma unroll
            for (int i = 0; i < 4; i++) acc[mt][nt][i] = 0.f;

    const int iters = K >> 5;

    ra0 = *(const uint4*)(A + (m0 + ar0) * K + aq0);
    ra1 = *(const uint4*)(A + (m0 + ar1) * K + aq1);
    rb0 = *(const uint4*)(B + (size_t)(n0 + ar0) * K + aq0);
    rb1 = *(const uint4*)(B + (size_t)(n0 + ar1) * K + aq1);
    *(uint4*)&As[ar0 * HS + aq0] = ra0;
    *(uint4*)&As[ar1 * HS + aq1] = ra1;
    *(uint4*)&Bs[ar0 * HS + aq0] = rb0;
    *(uint4*)&Bs[ar1 * HS + aq1] = rb1;
    __syncthreads();

    for (int it = 0; it < iters; it++) {
        const bool more = (it + 1 < iters);
        if (more) {
            int k0 = (it + 1) << 5;
            ra0 = *(const uint4*)(A + (m0 + ar0) * K + k0 + aq0);
            ra1 = *(const uint4*)(A + (m0 + ar1) * K + k0 + aq1);
            rb0 = *(const uint4*)(B + (size_t)(n0 + ar0) * K + k0 + aq0);
            rb1 = *(const uint4*)(B + (size_t)(n0 + ar1) * K + k0 + aq1);
        }

        const unsigned bo = (unsigned)((it & 1) * HBUFB);
#pragma unroll
        for (int ks = 0; ks < 2; ks++) {
            const unsigned cb = bo + (unsigned)(ks << 5);
            unsigned af[2][4], bf[4][4];
#pragma unroll
            for (int mt = 0; mt < 2; mt++) ldsm_x4(af[mt], aoff[mt] + cb);
#pragma unroll
            for (int p = 0; p < 4; p++)   ldsm_x4(bf[p],  boff[p]  + cb);
#pragma unroll
            for (int mt = 0; mt < 2; mt++)
#pragma unroll
                for (int p = 0; p < 4; p++) {
                    mma_f16(acc[mt][2 * p],     af[mt], &bf[p][0]);
                    mma_f16(acc[mt][2 * p + 1], af[mt], &bf[p][2]);
                }
        }

        if (more) {
            const int s = ((it + 1) & 1) * HBUF;
            *(uint4*)&As[s + ar0 * HS + aq0] = ra0;
            *(uint4*)&As[s + ar1 * HS + aq1] = ra1;
            *(uint4*)&Bs[s + ar0 * HS + aq0] = rb0;
            *(uint4*)&Bs[s + ar1 * HS + aq1] = rb1;
        }
        __syncthreads();
    }

#pragma unroll
    for (int mt = 0; mt < 2; mt++) {
#pragma unroll
        for (int nt = 0; nt < 8; nt++) {
            size_t row = m0 + wm + mt * 16 + (lane >> 2);
            int col = n0 + wn + nt * 8 + ((lane & 3) << 1);
            float2 lo = make_float2(acc[mt][nt][0], acc[mt][nt][1]);
            float2 hi = make_float2(acc[mt][nt][2], acc[mt][nt][3]);
            if (EPI == EPI_BIAS || EPI == EPI_BIAS_ELU) {
                float2 bb = *(const float2*)(bias + col);
                lo.x += bb.x; lo.y += bb.y;
                hi.x += bb.x; hi.y += bb.y;
            }
            if (EPI == EPI_BIAS_ELU) {
                lo.x = lo.x > 0.f ? lo.x : expm1f(lo.x);
                lo.y = lo.y > 0.f ? lo.y : expm1f(lo.y);
                hi.x = hi.x > 0.f ? hi.x : expm1f(hi.x);
                hi.y = hi.y > 0.f ? hi.y : expm1f(hi.y);
            }
            if (sizeof(OutT) == 2) {
                *(__half2*)((__half*)C + row * N + col)       = __floats2half2_rn(lo.x, lo.y);
                *(__half2*)((__half*)C + (row + 8) * N + col) = __floats2half2_rn(hi.x, hi.y);
            } else {
                if (RND) {
                    lo.x = rtf(lo.x); lo.y = rtf(lo.y);
                    hi.x = rtf(hi.x); hi.y = rtf(hi.y);
                }
                *(float2*)((float*)C + row * N + col)       = lo;
                *(float2*)((float*)C + (row + 8) * N + col) = hi;
            }
        }
    }
}

// ---------------- fused dd GEMM + Performer feature map -----------------------
// dd[M,256] = A[M,64] @ projh^T, CTA tile 64x256 (full N per CTA), K=64 single
// stage. 8 warps: wm=(wid>>2)*32, wn=(wid&3)*64, warp tile 32x64.
// DD_Q   : per-row max (smem cross-warp) + diag -> qph = ratio*(exp(..)+eps)
// DD_KMAX: global max only (flipped-uint atomicMax), no store
// DD_KEXP: diag + *gmax -> kph
#define DS 72

template<int MODE>
__global__ __launch_bounds__(256, 2)
void ddexp(const __half* __restrict__ A, const __half* __restrict__ Bp,
           __half* __restrict__ outp, unsigned* __restrict__ gmax)
{
    __shared__ __align__(16) __half As[64 * DS];
    __shared__ __align__(16) __half Bs[256 * DS];
    __shared__ float sdiag[64];
    __shared__ float srmax[4][64];

    const int tid  = threadIdx.x;
    const int wid  = tid >> 5;
    const int lane = tid & 31;
    const int wm   = (wid >> 2) * 32;
    const int wn   = (wid & 3)  * 64;
    const size_t m0 = (size_t)blockIdx.x * 64;

    // stage A (64x64) and B (256x64)
#pragma unroll
    for (int i = 0; i < 2; i++) {
        int c = tid + i * 256;
        int r = c >> 3, cc = (c & 7) << 3;
        *(uint4*)&As[r * DS + cc] = *(const uint4*)(A + (m0 + r) * 64 + cc);
    }
#pragma unroll
    for (int i = 0; i < 8; i++) {
        int c = tid + i * 256;
        int r = c >> 3, cc = (c & 7) << 3;
        *(uint4*)&Bs[r * DS + cc] = *(const uint4*)(Bp + (size_t)r * 64 + cc);
    }
    __syncthreads();

    // per-row diag = sum(a^2) (fp16 in, fp32 accum) — matches old k_exp path
    if (MODE != DD_KMAX && tid < 64) {
        const __half2* row = (const __half2*)&As[tid * DS];
        float ss = 0.f;
#pragma unroll
        for (int i = 0; i < 32; i++) {
            float2 v = __half22float2(row[i]);
            ss += v.x * v.x + v.y * v.y;
        }
        sdiag[tid] = ss;
    }

    const int matid = lane >> 3, rowin = lane & 7;
    const unsigned sA = (unsigned)__cvta_generic_to_shared(As);
    const unsigned sB = (unsigned)__cvta_generic_to_shared(Bs);
    unsigned aoff[2], boff[4];
#pragma unroll
    for (int mt = 0; mt < 2; mt++)
        aoff[mt] = sA + (unsigned)(((wm + mt * 16 + rowin + ((matid & 1) << 3)) * DS
                                    + ((matid & 2) << 2)) << 1);
#pragma unroll
    for (int p = 0; p < 4; p++)
        boff[p] = sB + (unsigned)(((wn + ((p << 1) + ((matid >> 1) & 1)) * 8 + rowin) * DS
                                    + ((matid & 1) << 3)) << 1);

    float acc[2][8][4];
#pragma unroll
    for (int mt = 0; mt < 2; mt++)
#pragma unroll
        for (int nt = 0; nt < 8; nt++)
#pragma unroll
            for (int i = 0; i < 4; i++) acc[mt][nt][i] = 0.f;

#pragma unroll
    for (int ks = 0; ks < 4; ks++) {
        const unsigned cb = (unsigned)(ks << 5);       // 16 halves
        unsigned af[2][4], bf[4][4];
#pragma unroll
        for (int mt = 0; mt < 2; mt++) ldsm_x4(af[mt], aoff[mt] + cb);
#pragma unroll
        for (int p = 0; p < 4; p++)   ldsm_x4(bf[p],  boff[p]  + cb);
#pragma unroll
        for (int mt = 0; mt < 2; mt++)
#pragma unroll
            for (int p = 0; p < 4; p++) {
                mma_f16(acc[mt][2 * p],     af[mt], &bf[p][0]);
                mma_f16(acc[mt][2 * p + 1], af[mt], &bf[p][2]);
            }
    }

    if (MODE == DD_KMAX) {
        float mx = -3.4e38f;
#pragma unroll
        for (int mt = 0; mt < 2; mt++)
#pragma unroll
            for (int nt = 0; nt < 8; nt++)
#pragma unroll
                for (int i = 0; i < 4; i++) mx = fmaxf(mx, acc[mt][nt][i]);
#pragma unroll
        for (int o = 16; o; o >>= 1) mx = fmaxf(mx, __shfl_xor_sync(0xffffffffu, mx, o));
        if (lane == 0) {
            unsigned u = __float_as_uint(mx);
            u = (u & 0x80000000u) ? ~u : (u | 0x80000000u);
            atomicMax(gmax, u);
        }
        return;
    }

    if (MODE == DD_Q) {
        // per-row max across the warp's 64 cols, then across the 4 n-warps
#pragma unroll
        for (int mt = 0; mt < 2; mt++) {
            float m0v = -3.4e38f, m1v = -3.4e38f;
#pragma unroll
            for (int nt = 0; nt < 8; nt++) {
                m0v = fmaxf(m0v, fmaxf(acc[mt][nt][0], acc[mt][nt][1]));
                m1v = fmaxf(m1v, fmaxf(acc[mt][nt][2], acc[mt][nt][3]));
            }
#pragma unroll
            for (int o = 1; o <= 2; o <<= 1) {
                m0v = fmaxf(m0v, __shfl_xor_sync(0xffffffffu, m0v, o));
                m1v = fmaxf(m1v, __shfl_xor_sync(0xffffffffu, m1v, o));
            }
            if ((lane & 3) == 0) {
                srmax[wid & 3][wm + mt * 16 + (lane >> 2)]     = m0v;
                srmax[wid & 3][wm + mt * 16 + 8 + (lane >> 2)] = m1v;
            }
        }
    }
    __syncthreads();

    const float gm = (MODE == DD_KEXP) ? unflip(*gmax) : 0.f;

#pragma unroll
    for (int mt = 0; mt < 2; mt++) {
        const int r0 = wm + mt * 16 + (lane >> 2);
        const int r1 = r0 + 8;
        float c0, c1;
        if (MODE == DD_Q) {
            float rm0 = fmaxf(fmaxf(srmax[0][r0], srmax[1][r0]),
                              fmaxf(srmax[2][r0], srmax[3][r0]));
            float rm1 = fmaxf(fmaxf(srmax[0][r1], srmax[1][r1]),
                              fmaxf(srmax[2][r1], srmax[3][r1]));
            c0 = 0.0625f * sdiag[r0] + rm0;
            c1 = 0.0625f * sdiag[r1] + rm1;
        } else {
            c0 = 0.0625f * sdiag[r0] + gm;
            c1 = 0.0625f * sdiag[r1] + gm;
        }
#pragma unroll
        for (int nt = 0; nt < 8; nt++) {
            const int col = wn + nt * 8 + ((lane & 3) << 1);
            float e0 = 0.0625f * (expf(acc[mt][nt][0] - c0) + 1e-6f);
            float e1 = 0.0625f * (expf(acc[mt][nt][1] - c0) + 1e-6f);
            float e2 = 0.0625f * (expf(acc[mt][nt][2] - c1) + 1e-6f);
            float e3 = 0.0625f * (expf(acc[mt][nt][3] - c1) + 1e-6f);
            *(__half2*)(outp + (m0 + r0) * 256 + col) = __floats2half2_rn(e0, e1);
            *(__half2*)(outp + (m0 + r1) * 256 + col) = __floats2half2_rn(e2, e3);
        }
    }
}

// ------------- fp16 batched strided GEMM over (b,h), optional split-K --------
// (unchanged from R10 — proven)
#define BAS 136
#define NAS 40
#define BBS 72

template<bool TRANSA, bool DIV, typename OutT, int NSPLIT>
__global__ __launch_bounds__(256, 2)
void hgemm_bh(const __half* __restrict__ A, size_t sAb, size_t sAh, int lda,
              const __half* __restrict__ B, size_t sBb, size_t sBh, int ldb,
              OutT* __restrict__ C, size_t sCb, size_t sCh, int ldc, size_t sCsplit,
              const float* __restrict__ aux, size_t sXb, size_t sXh, int ldx,
              int M, int N, int K)
{
    constexpr int ABUFH = TRANSA ? (32 * BAS) : (128 * NAS);
    constexpr int BBUFH = 32 * BBS;
    __shared__ __align__(16) __half As[2 * ABUFH];
    __shared__ __align__(16) __half Bs[2 * BBUFH];

    const int z     = blockIdx.z;
    const int split = (NSPLIT > 1) ? (z >> 6) : 0;
    const int zz    = (NSPLIT > 1) ? (z & 63) : z;
    const int zb = zz >> 4, zh = zz & 15;
    const __half* Ab = A + (size_t)zb * sAb + (size_t)zh * sAh;
    const __half* Bb = B + (size_t)zb * sBb + (size_t)zh * sBh;
    OutT*         Cb = C + (size_t)zb * sCb + (size_t)zh * sCh
                         + (size_t)split * sCsplit;
    if (NSPLIT > 1) {
        Ab += (size_t)split * K * lda;
        Bb += (size_t)split * K * ldb;
    }

    const int tid  = threadIdx.x;
    const int wid  = tid >> 5;
    const int lane = tid & 31;
    const int wm   = (wid >> 1) * 32;
    const int wn   = (wid & 1)  * 32;
    const int m0   = blockIdx.y * 128;

    const int matid = lane >> 3, rowin = lane & 7;
    const unsigned sAs = (unsigned)__cvta_generic_to_shared(As);
    const unsigned sBs = (unsigned)__cvta_generic_to_shared(Bs);

    unsigned aoff[2], boff[2];
#pragma unroll
    for (int mt = 0; mt < 2; mt++) {
        if (TRANSA)
            aoff[mt] = sAs + (unsigned)(((rowin + ((matid >> 1) << 3)) * BAS
                                         + wm + mt * 16 + ((matid & 1) << 3)) << 1);
        else
            aoff[mt] = sAs + (unsigned)(((wm + mt * 16 + rowin + ((matid & 1) << 3)) * NAS
                                         + ((matid & 2) << 2)) << 1);
    }
#pragma unroll
    for (int p = 0; p < 2; p++)
        boff[p] = sBs + (unsigned)(((rowin + ((matid & 1) << 3)) * BBS
                                    + wn + (p << 4) + ((matid >> 1) << 3)) << 1);

    const int ta_kr = tid >> 4, ta_mc = (tid & 15) << 3;
    const int na_r0 = tid >> 2, na_k0 = (tid & 3) << 3;
    const int b_kr  = tid >> 3, b_nc  = (tid & 7) << 3;

    uint4 ra0, ra1, rb;
    float acc[2][4][4];
#pragma unroll
    for (int mt = 0; mt < 2; mt++)
#pragma unroll
        for (int nt = 0; nt < 4; nt++)
#pragma unroll
            for (int i = 0; i < 4; i++) acc[mt][nt][i] = 0.f;

    const int iters = K >> 5;

    auto ld = [&](int k0) {
        if (TRANSA) {
            ra0 = *(const uint4*)(Ab + (size_t)(k0 + ta_kr)      * lda + m0 + ta_mc);
            ra1 = *(const uint4*)(Ab + (size_t)(k0 + ta_kr + 16) * lda + m0 + ta_mc);
        } else {
            ra0 = *(const uint4*)(Ab + (size_t)(m0 + na_r0)      * lda + k0 + na_k0);
            ra1 = *(const uint4*)(Ab + (size_t)(m0 + na_r0 + 64) * lda + k0 + na_k0);
        }
        rb = *(const uint4*)(Bb + (size_t)(k0 + b_kr) * ldb + b_nc);
    };
    auto st = [&](int s) {
        __half* as = As + s * ABUFH;
        __half* bs = Bs + s * BBUFH;
        if (TRANSA) {
            *(uint4*)&as[ta_kr * BAS + ta_mc]        = ra0;
            *(uint4*)&as[(ta_kr + 16) * BAS + ta_mc] = ra1;
        } else {
            *(uint4*)&as[na_r0 * NAS + na_k0]        = ra0;
            *(uint4*)&as[(na_r0 + 64) * NAS + na_k0] = ra1;
        }
        *(uint4*)&bs[b_kr * BBS + b_nc] = rb;
    };

    ld(0); st(0);
    __syncthreads();

    for (int it = 0; it < iters; it++) {
        const bool more = (it + 1 < iters);
        if (more) ld((it + 1) << 5);

        const unsigned ab = (unsigned)((it & 1) * (ABUFH * 2));
        const unsigned bb = (unsigned)((it & 1) * (BBUFH * 2));
#pragma unroll
        for (int ks = 0; ks < 2; ks++) {
            const unsigned aks = TRANSA ? (unsigned)(ks * 16 * BAS * 2) : (unsigned)(ks << 5);
            const unsigned bks = (unsigned)(ks * 16 * BBS * 2);
            unsigned af[2][4], bf[2][4];
#pragma unroll
            for (int mt = 0; mt < 2; mt++) {
                if (TRANSA) ldsm_x4t(af[mt], aoff[mt] + ab + aks);
                else        ldsm_x4 (af[mt], aoff[mt] + ab + aks);
            }
#pragma unroll
            for (int p = 0; p < 2; p++) ldsm_x4t(bf[p], boff[p] + bb + bks);
#pragma unroll
            for (int mt = 0; mt < 2; mt++)
#pragma unroll
                for (int p = 0; p < 2; p++) {
                    mma_f16(acc[mt][2 * p],     af[mt], &bf[p][0]);
                    mma_f16(acc[mt][2 * p + 1], af[mt], &bf[p][2]);
                }
        }

        if (more) st((it + 1) & 1);
        __syncthreads();
    }

#pragma unroll
    for (int mt = 0; mt < 2; mt++) {
        int row = m0 + wm + mt * 16 + (lane >> 2);
        float dv0 = 1.f, dv1 = 1.f;
        if (DIV) {
            dv0 = 1.f / aux[(size_t)zb * sXb + (size_t)zh * sXh + (size_t)row * ldx];
            dv1 = 1.f / aux[(size_t)zb * sXb + (size_t)zh * sXh + (size_t)(row + 8) * ldx];
        }
#pragma unroll
        for (int nt = 0; nt < 4; nt++) {
            int col = wn + nt * 8 + ((lane & 3) << 1);
            float2 lo = make_float2(acc[mt][nt][0] * dv0, acc[mt][nt][1] * dv0);
            float2 hi = make_float2(acc[mt][nt][2] * dv1, acc[mt][nt][3] * dv1);
            if (sizeof(OutT) == 2) {
                *(__half2*)((__half*)Cb + (size_t)row * ldc + col)       = __floats2half2_rn(lo.x, lo.y);
                *(__half2*)((__half*)Cb + (size_t)(row + 8) * ldc + col) = __floats2half2_rn(hi.x, hi.y);
            } else {
                *(float2*)((float*)Cb + (size_t)row * ldc + col)       = lo;
                *(float2*)((float*)Cb + (size_t)(row + 8) * ldc + col) = hi;
            }
        }
    }
}

// ---------------- small helper kernels --------------------------------------
__global__ void k_half4(const float4* __restrict__ in, __half2* __restrict__ out,
                        int n4)
{
    int i = blockIdx.x * 256 + threadIdx.x;
    if (i < n4) {
        float4 v = in[i];
        out[2 * i]     = __floats2half2_rn(v.x, v.y);
        out[2 * i + 1] = __floats2half2_rn(v.z, v.w);
    }
}

__global__ void k_transH(const float* __restrict__ in, __half* __restrict__ out,
                         int K, int N)
{
    __shared__ float t[32][33];
    const int n0 = blockIdx.x * 32, k0 = blockIdx.y * 32;
#pragma unroll
    for (int i = 0; i < 4; i++) {
        int kk = threadIdx.y + i * 8;
        t[kk][threadIdx.x] = in[(size_t)(k0 + kk) * N + n0 + threadIdx.x];
    }
    __syncthreads();
#pragma unroll
    for (int i = 0; i < 4; i++) {
        int nn = threadIdx.y + i * 8;
        out[(size_t)(n0 + nn) * K + k0 + threadIdx.x] = __float2half(t[threadIdx.x][nn]);
    }
}

__global__ void k_projH(const float* __restrict__ proj, __half* __restrict__ ph)
{
    int i = blockIdx.x * 256 + threadIdx.x;
    if (i < MMF * DHH)
        ph[i] = __float2half(proj[i] * 0.35355339059327373f);
}

__global__ void k_kvred(const float4* __restrict__ part, __half2* __restrict__ kv)
{
    int i = blockIdx.x * 256 + threadIdx.x;
    if (i < KVN / 4) {
        float4 a = part[i];
        float4 b = part[i + KVN / 4];
        float4 c = part[i + 2 * (KVN / 4)];
        float4 d = part[i + 3 * (KVN / 4)];
        kv[2 * i]     = __floats2half2_rn(a.x + b.x + c.x + d.x, a.y + b.y + c.y + d.y);
        kv[2 * i + 1] = __floats2half2_rn(a.z + b.z + c.z + d.z, a.w + b.w + c.w + d.w);
    }
}

__global__ void k_ksum(const __half* __restrict__ kp, float* __restrict__ ksum)
{
    int z = blockIdx.y;
    int b = z >> 4, h = z & 15;
    int m = threadIdx.x;
    size_t base = (size_t)b * 16777216 + (size_t)h * 256 + m;
    float s = 0.f;
    int l0 = blockIdx.x * 512;
    for (int l = l0; l < l0 + 512; l++) s += __half2float(kp[base + (size_t)l * 4096]);
    atomicAdd(&ksum[z * 256 + m], s);
}

__global__ void k_denom(const __half* __restrict__ qp, const float* __restrict__ ksum,
                        float* __restrict__ den)
{
    size_t w   = ((size_t)blockIdx.x * blockDim.x + threadIdx.x) >> 5;
    int   lane = threadIdx.x & 31;
    int   b    = (int)(w >> 16);
    int   h    = (int)(w & 15);
    const __half2* row = (const __half2*)(qp + w * 256);
    const float4*  ks  = (const float4*)(ksum + ((size_t)b * 16 + h) * 256);
    float4 k0 = ks[lane * 2], k1 = ks[lane * 2 + 1];
    float2 a0 = __half22float2(row[lane * 4]);
    float2 a1 = __half22float2(row[lane * 4 + 1]);
    float2 a2 = __half22float2(row[lane * 4 + 2]);
    float2 a3 = __half22float2(row[lane * 4 + 3]);
    float s = a0.x * k0.x + a0.y * k0.y + a1.x * k0.z + a1.y * k0.w
            + a2.x * k1.x + a2.y * k1.y + a3.x * k1.z + a3.y * k1.w;
#pragma unroll
    for (int o = 16; o; o >>= 1) s += __shfl_xor_sync(0xffffffffu, s, o);
    if (lane == 0) den[w] = s;
}

template<bool WRITE_H>
__global__ void k_ln(const float* __restrict__ a, const float* __restrict__ r,
                     const float* __restrict__ g, const float* __restrict__ b,
                     float* __restrict__ out, __half* __restrict__ outh)
{
    const int row = blockIdx.x;
    const int t   = threadIdx.x;
    const size_t base = (size_t)row * 1024;
    float4 xa = *(const float4*)(a + base + t * 4);
    float4 xr = *(const float4*)(r + base + t * 4);
    float4 s  = make_float4(xa.x + xr.x, xa.y + xr.y, xa.z + xr.z, xa.w + xr.w);
    float sum = s.x + s.y + s.z + s.w;
    float sq  = s.x * s.x + s.y * s.y + s.z * s.z + s.w * s.w;
#pragma unroll
    for (int o = 16; o; o >>= 1) {
        sum += __shfl_xor_sync(0xffffffffu, sum, o);
        sq  += __shfl_xor_sync(0xffffffffu, sq,  o);
    }
    __shared__ float ssum[8], ssq[8];
    __shared__ float s_mu, s_inv;
    int w = t >> 5;
    if ((t & 31) == 0) { ssum[w] = sum; ssq[w] = sq; }
    __syncthreads();
    if (t == 0) {
        float ts = 0.f, tq = 0.f;
        for (int i = 0; i < 8; i++) { ts += ssum[i]; tq += ssq[i]; }
        float mu  = ts * (1.f / 1024.f);
        float var = tq * (1.f / 1024.f) - mu * mu;
        s_mu = mu;
        s_inv = rsqrtf(var + 1e-6f);
    }
    __syncthreads();
    float mu = s_mu, inv = s_inv;
    float4 gg = *(const float4*)(g + t * 4);
    float4 bb = *(const float4*)(b + t * 4);
    float4 o = make_float4((s.x - mu) * inv * gg.x + bb.x,
                           (s.y - mu) * inv * gg.y + bb.y,
                           (s.z - mu) * inv * gg.z + bb.z,
                           (s.w - mu) * inv * gg.w + bb.w);
    *(float4*)(out + base + t * 4) = o;
    if (WRITE_H) {
        __half2* oh = (__half2*)(outh + base + t * 4);
        oh[0] = __floats2half2_rn(o.x, o.y);
        oh[1] = __floats2half2_rn(o.z, o.w);
    }
}

// ---------------- driver -----------------------------------------------------
extern "C" void kernel_launch(void* const* d_in, const int* in_sizes, int n_in,
                              void* d_out, int out_size)
{
    const float* x    = (const float*)d_in[0];
    const float* wq   = (const float*)d_in[1];
    const float* wk   = (const float*)d_in[2];
    const float* wv   = (const float*)d_in[3];
    const float* wo   = (const float*)d_in[4];
    const float* proj = (const float*)d_in[5];
    const float* ln1g = (const float*)d_in[6];
    const float* ln1b = (const float*)d_in[7];
    const float* ln2g = (const float*)d_in[8];
    const float* ln2b = (const float*)d_in[9];
    const float* w1   = (const float*)d_in[10];
    const float* b1   = (const float*)d_in[11];
    const float* w2   = (const float*)d_in[12];
    const float* b2   = (const float*)d_in[13];
    float* out = (float*)d_out;

    float *p_kvp, *p_ksum, *p_den, *p_tmp, *p_out1;
    __half *p_xh, *p_qh, *p_kh, *p_vh, *p_qph, *p_kph, *p_kvh;
    __half *p_out1h, *p_attnh, *p_hh, *p_projh;
    __half *p_wqT, *p_wkT, *p_wvT, *p_woT, *p_w1T, *p_w2T;
    unsigned* p_kmax;
    cudaGetSymbolAddress((void**)&p_kvp,   g_kvp);
    cudaGetSymbolAddress((void**)&p_ksum,  g_ksum);
    cudaGetSymbolAddress((void**)&p_den,   g_den);
    cudaGetSymbolAddress((void**)&p_tmp,   g_tmp);
    cudaGetSymbolAddress((void**)&p_out1,  g_out1);
    cudaGetSymbolAddress((void**)&p_kmax,  g_kmax);
    cudaGetSymbolAddress((void**)&p_xh,    g_xh);
    cudaGetSymbolAddress((void**)&p_qh,    g_qh);
    cudaGetSymbolAddress((void**)&p_kh,    g_kh);
    cudaGetSymbolAddress((void**)&p_vh,    g_vh);
    cudaGetSymbolAddress((void**)&p_qph,   g_qph);
    cudaGetSymbolAddress((void**)&p_kph,   g_kph);
    cudaGetSymbolAddress((void**)&p_kvh,   g_kvh);
    cudaGetSymbolAddress((void**)&p_out1h, g_out1h);
    cudaGetSymbolAddress((void**)&p_attnh, g_attnh);
    cudaGetSymbolAddress((void**)&p_hh,    g_hh);
    cudaGetSymbolAddress((void**)&p_projh, g_projh);
    cudaGetSymbolAddress((void**)&p_wqT,   g_wqT);
    cudaGetSymbolAddress((void**)&p_wkT,   g_wkT);
    cudaGetSymbolAddress((void**)&p_wvT,   g_wvT);
    cudaGetSymbolAddress((void**)&p_woT,   g_woT);
    cudaGetSymbolAddress((void**)&p_w1T,   g_w1T);
    cudaGetSymbolAddress((void**)&p_w2T,   g_w2T);

    // prep
    k_half4<<<(NT * DD / 4 + 255) / 256, 256>>>((const float4*)x, (__half2*)p_xh, NT * DD / 4);
    k_transH<<<dim3(32, 32), dim3(32, 8)>>>(wq, p_wqT, DD, DD);
    k_transH<<<dim3(32, 32), dim3(32, 8)>>>(wk, p_wkT, DD, DD);
    k_transH<<<dim3(32, 32), dim3(32, 8)>>>(wv, p_wvT, DD, DD);
    k_projH<<<64, 256>>>(proj, p_projh);

    // q,k,v projections -> fp16
    hgemm<EPI_NONE, __half, false><<<dim3(8, 128), 256>>>(p_xh, p_wqT, nullptr, p_qh, NT, 1024, 1024);
    hgemm<EPI_NONE, __half, false><<<dim3(8, 128), 256>>>(p_xh, p_wkT, nullptr, p_kh, NT, 1024, 1024);
    hgemm<EPI_NONE, __half, false><<<dim3(8, 128), 256>>>(p_xh, p_wvT, nullptr, p_vh, NT, 1024, 1024);

    // remaining prep
    k_transH<<<dim3(32, 32),  dim3(32, 8)>>>(wo, p_woT, DD, DD);
    k_transH<<<dim3(128, 32), dim3(32, 8)>>>(w1, p_w1T, DD, DFF);
    k_transH<<<dim3(32, 128), dim3(32, 8)>>>(w2, p_w2T, DFF, DD);

    cudaMemsetAsync(p_kmax, 0, 4);
    cudaMemsetAsync(p_ksum, 0, BB * HH * MMF * sizeof(float));

    // fused dd + feature maps (q: row max; k: global max pass then exp pass)
    ddexp<DD_Q>   <<<NR / 64, 256>>>(p_qh, p_projh, p_qph, nullptr);
    ddexp<DD_KMAX><<<NR / 64, 256>>>(p_kh, p_projh, nullptr, p_kmax);
    ddexp<DD_KEXP><<<NR / 64, 256>>>(p_kh, p_projh, p_kph, p_kmax);

    // kv partials: fp16 split-K=4 over K=4096 (each 1024)
    hgemm_bh<true, false, float, 4><<<dim3(1, 2, 256), 256>>>(
        p_kph, (size_t)16777216, (size_t)256, 4096,
        p_vh,  (size_t)4194304,  (size_t)64,  1024,
        p_kvp, (size_t)(16 * 16384), (size_t)16384, 64, (size_t)KVN,
        nullptr, 0, 0, 0,
        256, 64, 1024);
    k_kvred<<<(KVN / 4 + 255) / 256, 256>>>((const float4*)p_kvp, (__half2*)p_kvh);

    k_ksum<<<dim3(8, 64), 256>>>(p_kph, p_ksum);
    k_denom<<<NR / 8, 256>>>(p_qph, p_ksum, p_den);

    // attn = (qp @ kv) / denom : fp16 -> fp16
    hgemm_bh<false, true, __half, 1><<<dim3(1, 32, 64), 256>>>(
        p_qph, (size_t)16777216, (size_t)256, 4096,
        p_kvh, (size_t)(16 * 16384), (size_t)16384, 64,
        p_attnh, (size_t)4194304, (size_t)64, 1024, (size_t)0,
        p_den,  (size_t)65536,   (size_t)1,  16,
        4096, 64, 256);

    // attn_out = attn @ wo^T -> fp32 tmp
    hgemm<EPI_NONE, float, false><<<dim3(8, 128), 256>>>(p_attnh, p_woT, nullptr, p_tmp, NT, 1024, 1024);

    // out1 = LN(x + attn_out) -> fp32 + fp16
    k_ln<true><<<NT, 256>>>(p_tmp, x, ln1g, ln1b, p_out1, p_out1h);

    // FFN
    hgemm<EPI_BIAS_ELU, __half, false><<<dim3(32, 128), 256>>>(p_out1h, p_w1T, b1, p_hh, NT, DFF, 1024);
    hgemm<EPI_BIAS, float, false><<<dim3(8, 128), 256>>>(p_hh, p_w2T, b2, p_tmp, NT, 1024, DFF);

    // out2 = LN(out1 + ffn)
    k_ln<false><<<NT, 256>>>(p_tmp, p_out1, ln2g, ln2b, out, nullptr);
}

// round 12
// speedup vs baseline: 2.7003x; 1.0065x over previous
#include <cuda_runtime.h>
#include <cuda_fp16.h>
#include <math.h>
#include <stdint.h>

#define BB   4
#define LL   4096
#define DD   1024
#define HH   16
#define DHH  64
#define MMF  256
#define DFF  4096
#define NT   (BB*LL)      /* 16384 tokens  */
#define NR   (NT*HH)      /* 262144 (t,h) rows */
#define KVN  (BB*HH*MMF*DHH)   /* 1048576 */

// ---------------- scratch (device globals; no allocation allowed) ----------
__device__ float  g_kvp  [4*KVN];
__device__ float  g_ksum [BB*HH*MMF];
__device__ float  g_den  [NR];
__device__ float  g_tmp  [(size_t)NT*DD];
__device__ float  g_out1 [(size_t)NT*DD];
__device__ unsigned g_kmax;
// fp16 buffers
__device__ __half g_xh   [(size_t)NT*DD];
__device__ __half g_qh   [(size_t)NT*DD];
__device__ __half g_kh   [(size_t)NT*DD];
__device__ __half g_vh   [(size_t)NT*DD];
__device__ __half g_qph  [(size_t)NR*MMF];
__device__ __half g_kph  [(size_t)NR*MMF];
__device__ __half g_kvh  [KVN];
__device__ __half g_out1h[(size_t)NT*DD];
__device__ __half g_attnh[(size_t)NT*DD];
__device__ __half g_hh   [(size_t)NT*DFF];
__device__ __half g_projh[MMF*DHH];
__device__ __half g_wqT  [DD*DD];
__device__ __half g_wkT  [DD*DD];
__device__ __half g_wvT  [DD*DD];
__device__ __half g_woT  [DD*DD];
__device__ __half g_w1T  [(size_t)DFF*DD];
__device__ __half g_w2T  [(size_t)DD*DFF];

enum { EPI_NONE = 0, EPI_BIAS = 1, EPI_BIAS_ELU = 2 };
enum { DD_Q = 0, DD_KMAX = 1, DD_KEXP = 2 };

// ---------------- helpers ----------------------------------------------------
__device__ __forceinline__ float rtf(float x)
{
    unsigned u;
    asm("cvt.rna.tf32.f32 %0, %1;" : "=r"(u) : "f"(x));
    return __uint_as_float(u);
}

__device__ __forceinline__ void mma_f16(float* d, const unsigned* a,
                                        const unsigned* b)
{
    asm volatile(
        "mma.sync.aligned.m16n8k16.row.col.f32.f16.f16.f32 "
        "{%0,%1,%2,%3}, {%4,%5,%6,%7}, {%8,%9}, {%0,%1,%2,%3};\n"
        : "+f"(d[0]), "+f"(d[1]), "+f"(d[2]), "+f"(d[3])
        : "r"(a[0]), "r"(a[1]), "r"(a[2]), "r"(a[3]),
          "r"(b[0]), "r"(b[1]));
}

__device__ __forceinline__ void ldsm_x4(unsigned* r, unsigned addr)
{
    asm volatile("ldmatrix.sync.aligned.m8n8.x4.shared.b16 {%0,%1,%2,%3}, [%4];"
        : "=r"(r[0]), "=r"(r[1]), "=r"(r[2]), "=r"(r[3]) : "r"(addr));
}

__device__ __forceinline__ void ldsm_x4t(unsigned* r, unsigned addr)
{
    asm volatile("ldmatrix.sync.aligned.m8n8.x4.trans.shared.b16 {%0,%1,%2,%3}, [%4];"
        : "=r"(r[0]), "=r"(r[1]), "=r"(r[2]), "=r"(r[3]) : "r"(addr));
}

__device__ __forceinline__ float unflip(unsigned u)
{
    return __uint_as_float((u & 0x80000000u) ? (u ^ 0x80000000u) : ~u);
}

// two fp16 exp2 in one MUFU op
__device__ __forceinline__ __half2 h2ex2(__half2 x)
{
    unsigned u = *(unsigned*)&x, y;
    asm("ex2.approx.f16x2 %0, %1;" : "=r"(y) : "r"(u));
    return *(__half2*)&y;
}

// ---------------- fp16 tensor-core GEMM: C[M,N] = A[M,K] @ B^T ----------------
// (unchanged — proven) double-buffered, ldmatrix, 8 warps 32x64.
#define HS 40
#define HBUF (128 * HS)
#define HBUFB (HBUF * 2)

template<int EPI, typename OutT, bool RND>
__global__ __launch_bounds__(256, 2)
void hgemm(const __half* __restrict__ A, const __half* __restrict__ B,
           const float* __restrict__ bias, OutT* __restrict__ C,
           int M, int N, int K)
{
    __shared__ __align__(16) __half As[2 * HBUF];
    __shared__ __align__(16) __half Bs[2 * HBUF];

    const int tid  = threadIdx.x;
    const int wid  = tid >> 5;
    const int lane = tid & 31;
    const int wm   = (wid >> 1) * 32;
    const int wn   = (wid & 1)  * 64;
    const size_t m0 = (size_t)blockIdx.y * 128;
    const int    n0 = blockIdx.x * 128;

    const int ar0 = tid >> 2,          aq0 = (tid & 3) << 3;
    const int ar1 = (tid + 256) >> 2,  aq1 = ((tid + 256) & 3) << 3;

    const int matid = lane >> 3, rowin = lane & 7;
    const unsigned sAb = (unsigned)__cvta_generic_to_shared(As);
    const unsigned sBb = (unsigned)__cvta_generic_to_shared(Bs);
    unsigned aoff[2], boff[4];
#pragma unroll
    for (int mt = 0; mt < 2; mt++)
        aoff[mt] = sAb + (unsigned)(((wm + mt * 16 + rowin + ((matid & 1) << 3)) * HS
                                     + ((matid & 2) << 2)) << 1);
#pragma unroll
    for (int p = 0; p < 4; p++)
        boff[p] = sBb + (unsigned)(((wn + ((p << 1) + ((matid >> 1) & 1)) * 8 + rowin) * HS
                                     + ((matid & 1) << 3)) << 1);

    uint4 ra0, ra1, rb0, rb1;
    float acc[2][8][4];
#pragma unroll
    for (int mt = 0; mt < 2; mt++)
#pragma unroll
        for (int nt = 0; nt < 8; nt++)
#pragma unroll
            for (int i = 0; i < 4; i++) acc[mt][nt][i] = 0.f;

    const int iters = K >> 5;

    ra0 = *(const uint4*)(A + (m0 + ar0) * K + aq0);
    ra1 = *(const uint4*)(A + (m0 + ar1) * K + aq1);
    rb0 = *(const uint4*)(B + (size_t)(n0 + ar0) * K + aq0);
    rb1 = *(const uint4*)(B + (size_t)(n0 + ar1) * K + aq1);
    *(uint4*)&As[ar0 * HS + aq0] = ra0;
    *(uint4*)&As[ar1 * HS + aq1] = ra1;
    *(uint4*)&Bs[ar0 * HS + aq0] = rb0;
    *(uint4*)&Bs[ar1 * HS + aq1] = rb1;
    __syncthreads();

    for (int it = 0; it < iters; it++) {
        const bool more = (it + 1 < iters);
        if (more) {
            int k0 = (it + 1) << 5;
            ra0 = *(const uint4*)(A + (m0 + ar0) * K + k0 + aq0);
            ra1 = *(const uint4*)(A + (m0 + ar1) * K + k0 + aq1);
            rb0 = *(const uint4*)(B + (size_t)(n0 + ar0) * K + k0 + aq0);
            rb1 = *(const uint4*)(B + (size_t)(n0 + ar1) * K + k0 + aq1);
        }

        const unsigned bo = (unsigned)((it & 1) * HBUFB);
#pragma unroll
        for (int ks = 0; ks < 2; ks++) {
            const unsigned cb = bo + (unsigned)(ks << 5);
            unsigned af[2][4], bf[4][4];
#pragma unroll
            for (int mt = 0; mt < 2; mt++) ldsm_x4(af[mt], aoff[mt] + cb);
#pragma unroll
            for (int p = 0; p < 4; p++)   ldsm_x4(bf[p],  boff[p]  + cb);
#pragma unroll
            for (int mt = 0; mt < 2; mt++)
#pragma unroll
                for (int p = 0; p < 4; p++) {
                    mma_f16(acc[mt][2 * p],     af[mt], &bf[p][0]);
                    mma_f16(acc[mt][2 * p + 1], af[mt], &bf[p][2]);
                }
        }

        if (more) {
            const int s = ((it + 1) & 1) * HBUF;
            *(uint4*)&As[s + ar0 * HS + aq0] = ra0;
            *(uint4*)&As[s + ar1 * HS + aq1] = ra1;
            *(uint4*)&Bs[s + ar0 * HS + aq0] = rb0;
            *(uint4*)&Bs[s + ar1 * HS + aq1] = rb1;
        }
        __syncthreads();
    }

#pragma unroll
    for (int mt = 0; mt < 2; mt++) {
#pragma unroll
        for (int nt = 0; nt < 8; nt++) {
            size_t row = m0 + wm + mt * 16 + (lane >> 2);
            int col = n0 + wn + nt * 8 + ((lane & 3) << 1);
            float2 lo = make_float2(acc[mt][nt][0], acc[mt][nt][1]);
            float2 hi = make_float2(acc[mt][nt][2], acc[mt][nt][3]);
            if (EPI == EPI_BIAS || EPI == EPI_BIAS_ELU) {
                float2 bb = *(const float2*)(bias + col);
                lo.x += bb.x; lo.y += bb.y;
                hi.x += bb.x; hi.y += bb.y;
            }
            if (EPI == EPI_BIAS_ELU) {
                lo.x = lo.x > 0.f ? lo.x : expm1f(lo.x);
                lo.y = lo.y > 0.f ? lo.y : expm1f(lo.y);
                hi.x = hi.x > 0.f ? hi.x : expm1f(hi.x);
                hi.y = hi.y > 0.f ? hi.y : expm1f(hi.y);
            }
            if (sizeof(OutT) == 2) {
                *(__half2*)((__half*)C + row * N + col)       = __floats2half2_rn(lo.x, lo.y);
                *(__half2*)((__half*)C + (row + 8) * N + col) = __floats2half2_rn(hi.x, hi.y);
            } else {
                if (RND) {
                    lo.x = rtf(lo.x); lo.y = rtf(lo.y);
                    hi.x = rtf(hi.x); hi.y = rtf(hi.y);
                }
                *(float2*)((float*)C + row * N + col)       = lo;
                *(float2*)((float*)C + (row + 8) * N + col) = hi;
            }
        }
    }
}

// ---------------- fused dd GEMM + Performer feature map -----------------------
// dd[M,256] = A[M,64] @ projh^T, CTA tile 64x256, K=64 single stage.
// Feature-map exp via ex2.approx.f16x2 (2 exps / MUFU op).
#define DS 72

template<int MODE>
__global__ __launch_bounds__(256, 2)
void ddexp(const __half* __restrict__ A, const __half* __restrict__ Bp,
           __half* __restrict__ outp, unsigned* __restrict__ gmax)
{
    __shared__ __align__(16) __half As[64 * DS];
    __shared__ __align__(16) __half Bs[256 * DS];
    __shared__ float sdiag[64];
    __shared__ float srmax[4][64];

    const int tid  = threadIdx.x;
    const int wid  = tid >> 5;
    const int lane = tid & 31;
    const int wm   = (wid >> 2) * 32;
    const int wn   = (wid & 3)  * 64;
    const size_t m0 = (size_t)blockIdx.x * 64;

#pragma unroll
    for (int i = 0; i < 2; i++) {
        int c = tid + i * 256;
        int r = c >> 3, cc = (c & 7) << 3;
        *(uint4*)&As[r * DS + cc] = *(const uint4*)(A + (m0 + r) * 64 + cc);
    }
#pragma unroll
    for (int i = 0; i < 8; i++) {
        int c = tid + i * 256;
        int r = c >> 3, cc = (c & 7) << 3;
        *(uint4*)&Bs[r * DS + cc] = *(const uint4*)(Bp + (size_t)r * 64 + cc);
    }
    __syncthreads();

    if (MODE != DD_KMAX && tid < 64) {
        const __half2* row = (const __half2*)&As[tid * DS];
        float ss = 0.f;
#pragma unroll
        for (int i = 0; i < 32; i++) {
            float2 v = __half22float2(row[i]);
            ss += v.x * v.x + v.y * v.y;
        }
        sdiag[tid] = ss;
    }

    const int matid = lane >> 3, rowin = lane & 7;
    const unsigned sA = (unsigned)__cvta_generic_to_shared(As);
    const unsigned sB = (unsigned)__cvta_generic_to_shared(Bs);
    unsigned aoff[2], boff[4];
#pragma unroll
    for (int mt = 0; mt < 2; mt++)
        aoff[mt] = sA + (unsigned)(((wm + mt * 16 + rowin + ((matid & 1) << 3)) * DS
                                    + ((matid & 2) << 2)) << 1);
#pragma unroll
    for (int p = 0; p < 4; p++)
        boff[p] = sB + (unsigned)(((wn + ((p << 1) + ((matid >> 1) & 1)) * 8 + rowin) * DS
                                    + ((matid & 1) << 3)) << 1);

    float acc[2][8][4];
#pragma unroll
    for (int mt = 0; mt < 2; mt++)
#pragma unroll
        for (int nt = 0; nt < 8; nt++)
#pragma unroll
            for (int i = 0; i < 4; i++) acc[mt][nt][i] = 0.f;

#pragma unroll
    for (int ks = 0; ks < 4; ks++) {
        const unsigned cb = (unsigned)(ks << 5);
        unsigned af[2][4], bf[4][4];
#pragma unroll
        for (int mt = 0; mt < 2; mt++) ldsm_x4(af[mt], aoff[mt] + cb);
#pragma unroll
        for (int p = 0; p < 4; p++)   ldsm_x4(bf[p],  boff[p]  + cb);
#pragma unroll
        for (int mt = 0; mt < 2; mt++)
#pragma unroll
            for (int p = 0; p < 4; p++) {
                mma_f16(acc[mt][2 * p],     af[mt], &bf[p][0]);
                mma_f16(acc[mt][2 * p + 1], af[mt], &bf[p][2]);
            }
    }

    if (MODE == DD_KMAX) {
        float mx = -3.4e38f;
#pragma unroll
        for (int mt = 0; mt < 2; mt++)
#pragma unroll
            for (int nt = 0; nt < 8; nt++)
#pragma unroll
                for (int i = 0; i < 4; i++) mx = fmaxf(mx, acc[mt][nt][i]);
#pragma unroll
        for (int o = 16; o; o >>= 1) mx = fmaxf(mx, __shfl_xor_sync(0xffffffffu, mx, o));
        if (lane == 0) {
            unsigned u = __float_as_uint(mx);
            u = (u & 0x80000000u) ? ~u : (u | 0x80000000u);
            atomicMax(gmax, u);
        }
        return;
    }

    if (MODE == DD_Q) {
#pragma unroll
        for (int mt = 0; mt < 2; mt++) {
            float m0v = -3.4e38f, m1v = -3.4e38f;
#pragma unroll
            for (int nt = 0; nt < 8; nt++) {
                m0v = fmaxf(m0v, fmaxf(acc[mt][nt][0], acc[mt][nt][1]));
                m1v = fmaxf(m1v, fmaxf(acc[mt][nt][2], acc[mt][nt][3]));
            }
#pragma unroll
            for (int o = 1; o <= 2; o <<= 1) {
                m0v = fmaxf(m0v, __shfl_xor_sync(0xffffffffu, m0v, o));
                m1v = fmaxf(m1v, __shfl_xor_sync(0xffffffffu, m1v, o));
            }
            if ((lane & 3) == 0) {
                srmax[wid & 3][wm + mt * 16 + (lane >> 2)]     = m0v;
                srmax[wid & 3][wm + mt * 16 + 8 + (lane >> 2)] = m1v;
            }
        }
    }
    __syncthreads();

    const float gm = (MODE == DD_KEXP) ? unflip(*gmax) : 0.f;
    const float L2E = 1.4426950408889634f;
    const __half2 eps2 = __float2half2_rn(1e-6f);
    const __half2 rat2 = __float2half2_rn(0.0625f);

#pragma unroll
    for (int mt = 0; mt < 2; mt++) {
        const int r0 = wm + mt * 16 + (lane >> 2);
        const int r1 = r0 + 8;
        float c0, c1;
        if (MODE == DD_Q) {
            float rm0 = fmaxf(fmaxf(srmax[0][r0], srmax[1][r0]),
                              fmaxf(srmax[2][r0], srmax[3][r0]));
            float rm1 = fmaxf(fmaxf(srmax[0][r1], srmax[1][r1]),
                              fmaxf(srmax[2][r1], srmax[3][r1]));
            c0 = 0.0625f * sdiag[r0] + rm0;
            c1 = 0.0625f * sdiag[r1] + rm1;
        } else {
            c0 = 0.0625f * sdiag[r0] + gm;
            c1 = 0.0625f * sdiag[r1] + gm;
        }
        const float c0l = c0 * L2E, c1l = c1 * L2E;
#pragma unroll
        for (int nt = 0; nt < 8; nt++) {
            const int col = wn + nt * 8 + ((lane & 3) << 1);
            // exp(x-c) = ex2((x-c)*log2e), two at a time in fp16
            __half2 t01 = __floats2half2_rn(fmaf(acc[mt][nt][0], L2E, -c0l),
                                            fmaf(acc[mt][nt][1], L2E, -c0l));
            __half2 t23 = __floats2half2_rn(fmaf(acc[mt][nt][2], L2E, -c1l),
                                            fmaf(acc[mt][nt][3], L2E, -c1l));
            __half2 e01 = __hmul2(__hadd2(h2ex2(t01), eps2), rat2);
            __half2 e23 = __hmul2(__hadd2(h2ex2(t23), eps2), rat2);
            *(__half2*)(outp + (m0 + r0) * 256 + col) = e01;
            *(__half2*)(outp + (m0 + r1) * 256 + col) = e23;
        }
    }
}

// ------------- fp16 batched strided GEMM over (b,h), optional split-K --------
// (unchanged — proven)
#define BAS 136
#define NAS 40
#define BBS 72

template<bool TRANSA, bool DIV, typename OutT, int NSPLIT>
__global__ __launch_bounds__(256, 2)
void hgemm_bh(const __half* __restrict__ A, size_t sAb, size_t sAh, int lda,
              const __half* __restrict__ B, size_t sBb, size_t sBh, int ldb,
              OutT* __restrict__ C, size_t sCb, size_t sCh, int ldc, size_t sCsplit,
              const float* __restrict__ aux, size_t sXb, size_t sXh, int ldx,
              int M, int N, int K)
{
    constexpr int ABUFH = TRANSA ? (32 * BAS) : (128 * NAS);
    constexpr int BBUFH = 32 * BBS;
    __shared__ __align__(16) __half As[2 * ABUFH];
    __shared__ __align__(16) __half Bs[2 * BBUFH];

    const int z     = blockIdx.z;
    const int split = (NSPLIT > 1) ? (z >> 6) : 0;
    const int zz    = (NSPLIT > 1) ? (z & 63) : z;
    const int zb = zz >> 4, zh = zz & 15;
    const __half* Ab = A + (size_t)zb * sAb + (size_t)zh * sAh;
    const __half* Bb = B + (size_t)zb * sBb + (size_t)zh * sBh;
    OutT*         Cb = C + (size_t)zb * sCb + (size_t)zh * sCh
                         + (size_t)split * sCsplit;
    if (NSPLIT > 1) {
        Ab += (size_t)split * K * lda;
        Bb += (size_t)split * K * ldb;
    }

    const int tid  = threadIdx.x;
    const int wid  = tid >> 5;
    const int lane = tid & 31;
    const int wm   = (wid >> 1) * 32;
    const int wn   = (wid & 1)  * 32;
    const int m0   = blockIdx.y * 128;

    const int matid = lane >> 3, rowin = lane & 7;
    const unsigned sAs = (unsigned)__cvta_generic_to_shared(As);
    const unsigned sBs = (unsigned)__cvta_generic_to_shared(Bs);

    unsigned aoff[2], boff[2];
#pragma unroll
    for (int mt = 0; mt < 2; mt++) {
        if (TRANSA)
            aoff[mt] = sAs + (unsigned)(((rowin + ((matid >> 1) << 3)) * BAS
                                         + wm + mt * 16 + ((matid & 1) << 3)) << 1);
        else
            aoff[mt] = sAs + (unsigned)(((wm + mt * 16 + rowin + ((matid & 1) << 3)) * NAS
                                         + ((matid & 2) << 2)) << 1);
    }
#pragma unroll
    for (int p = 0; p < 2; p++)
        boff[p] = sBs + (unsigned)(((rowin + ((matid & 1) << 3)) * BBS
                                    + wn + (p << 4) + ((matid >> 1) << 3)) << 1);

    const int ta_kr = tid >> 4, ta_mc = (tid & 15) << 3;
    const int na_r0 = tid >> 2, na_k0 = (tid & 3) << 3;
    const int b_kr  = tid >> 3, b_nc  = (tid & 7) << 3;

    uint4 ra0, ra1, rb;
    float acc[2][4][4];
#pragma unroll
    for (int mt = 0; mt < 2; mt++)
#pragma unroll
        for (int nt = 0; nt < 4; nt++)
#pragma unroll
            for (int i = 0; i < 4; i++) acc[mt][nt][i] = 0.f;

    const int iters = K >> 5;

    auto ld = [&](int k0) {
        if (TRANSA) {
            ra0 = *(const uint4*)(Ab + (size_t)(k0 + ta_kr)      * lda + m0 + ta_mc);
            ra1 = *(const uint4*)(Ab + (size_t)(k0 + ta_kr + 16) * lda + m0 + ta_mc);
        } else {
            ra0 = *(const uint4*)(Ab + (size_t)(m0 + na_r0)      * lda + k0 + na_k0);
            ra1 = *(const uint4*)(Ab + (size_t)(m0 + na_r0 + 64) * lda + k0 + na_k0);
        }
        rb = *(const uint4*)(Bb + (size_t)(k0 + b_kr) * ldb + b_nc);
    };
    auto st = [&](int s) {
        __half* as = As + s * ABUFH;
        __half* bs = Bs + s * BBUFH;
        if (TRANSA) {
            *(uint4*)&as[ta_kr * BAS + ta_mc]        = ra0;
            *(uint4*)&as[(ta_kr + 16) * BAS + ta_mc] = ra1;
        } else {
            *(uint4*)&as[na_r0 * NAS + na_k0]        = ra0;
            *(uint4*)&as[(na_r0 + 64) * NAS + na_k0] = ra1;
        }
        *(uint4*)&bs[b_kr * BBS + b_nc] = rb;
    };

    ld(0); st(0);
    __syncthreads();

    for (int it = 0; it < iters; it++) {
        const bool more = (it + 1 < iters);
        if (more) ld((it + 1) << 5);

        const unsigned ab = (unsigned)((it & 1) * (ABUFH * 2));
        const unsigned bb = (unsigned)((it & 1) * (BBUFH * 2));
#pragma unroll
        for (int ks = 0; ks < 2; ks++) {
            const unsigned aks = TRANSA ? (unsigned)(ks * 16 * BAS * 2) : (unsigned)(ks << 5);
            const unsigned bks = (unsigned)(ks * 16 * BBS * 2);
            unsigned af[2][4], bf[2][4];
#pragma unroll
            for (int mt = 0; mt < 2; mt++) {
                if (TRANSA) ldsm_x4t(af[mt], aoff[mt] + ab + aks);
                else        ldsm_x4 (af[mt], aoff[mt] + ab + aks);
            }
#pragma unroll
            for (int p = 0; p < 2; p++) ldsm_x4t(bf[p], boff[p] + bb + bks);
#pragma unroll
            for (int mt = 0; mt < 2; mt++)
#pragma unroll
                for (int p = 0; p < 2; p++) {
                    mma_f16(acc[mt][2 * p],     af[mt], &bf[p][0]);
                    mma_f16(acc[mt][2 * p + 1], af[mt], &bf[p][2]);
                }
        }

        if (more) st((it + 1) & 1);
        __syncthreads();
    }

#pragma unroll
    for (int mt = 0; mt < 2; mt++) {
        int row = m0 + wm + mt * 16 + (lane >> 2);
        float dv0 = 1.f, dv1 = 1.f;
        if (DIV) {
            dv0 = 1.f / aux[(size_t)zb * sXb + (size_t)zh * sXh + (size_t)row * ldx];
            dv1 = 1.f / aux[(size_t)zb * sXb + (size_t)zh * sXh + (size_t)(row + 8) * ldx];
        }
#pragma unroll
        for (int nt = 0; nt < 4; nt++) {
            int col = wn + nt * 8 + ((lane & 3) << 1);
            float2 lo = make_float2(acc[mt][nt][0] * dv0, acc[mt][nt][1] * dv0);
            float2 hi = make_float2(acc[mt][nt][2] * dv1, acc[mt][nt][3] * dv1);
            if (sizeof(OutT) == 2) {
                *(__half2*)((__half*)Cb + (size_t)row * ldc + col)       = __floats2half2_rn(lo.x, lo.y);
                *(__half2*)((__half*)Cb + (size_t)(row + 8) * ldc + col) = __floats2half2_rn(hi.x, hi.y);
            } else {
                *(float2*)((float*)Cb + (size_t)row * ldc + col)       = lo;
                *(float2*)((float*)Cb + (size_t)(row + 8) * ldc + col) = hi;
            }
        }
    }
}

// ---------------- small helper kernels --------------------------------------
__global__ void k_half4(const float4* __restrict__ in, __half2* __restrict__ out,
                        int n4)
{
    int i = blockIdx.x * 256 + threadIdx.x;
    if (i < n4) {
        float4 v = in[i];
        out[2 * i]     = __floats2half2_rn(v.x, v.y);
        out[2 * i + 1] = __floats2half2_rn(v.z, v.w);
    }
}

__global__ void k_transH(const float* __restrict__ in, __half* __restrict__ out,
                         int K, int N)
{
    __shared__ float t[32][33];
    const int n0 = blockIdx.x * 32, k0 = blockIdx.y * 32;
#pragma unroll
    for (int i = 0; i < 4; i++) {
        int kk = threadIdx.y + i * 8;
        t[kk][threadIdx.x] = in[(size_t)(k0 + kk) * N + n0 + threadIdx.x];
    }
    __syncthreads();
#pragma unroll
    for (int i = 0; i < 4; i++) {
        int nn = threadIdx.y + i * 8;
        out[(size_t)(n0 + nn) * K + k0 + threadIdx.x] = __float2half(t[threadIdx.x][nn]);
    }
}

__global__ void k_projH(const float* __restrict__ proj, __half* __restrict__ ph)
{
    int i = blockIdx.x * 256 + threadIdx.x;
    if (i < MMF * DHH)
        ph[i] = __float2half(proj[i] * 0.35355339059327373f);
}

__global__ void k_kvred(const float4* __restrict__ part, __half2* __restrict__ kv)
{
    int i = blockIdx.x * 256 + threadIdx.x;
    if (i < KVN / 4) {
        float4 a = part[i];
        float4 b = part[i + KVN / 4];
        float4 c = part[i + 2 * (KVN / 4)];
        float4 d = part[i + 3 * (KVN / 4)];
        kv[2 * i]     = __floats2half2_rn(a.x + b.x + c.x + d.x, a.y + b.y + c.y + d.y);
        kv[2 * i + 1] = __floats2half2_rn(a.z + b.z + c.z + d.z, a.w + b.w + c.w + d.w);
    }
}

__global__ void k_ksum(const __half* __restrict__ kp, float* __restrict__ ksum)
{
    int z = blockIdx.y;
    int b = z >> 4, h = z & 15;
    int m = threadIdx.x;
    size_t base = (size_t)b * 16777216 + (size_t)h * 256 + m;
    float s = 0.f;
    int l0 = blockIdx.x * 512;
    for (int l = l0; l < l0 + 512; l++) s += __half2float(kp[base + (size_t)l * 4096]);
    atomicAdd(&ksum[z * 256 + m], s);
}

__global__ void k_denom(const __half* __restrict__ qp, const float* __restrict__ ksum,
                        float* __restrict__ den)
{
    size_t w   = ((size_t)blockIdx.x * blockDim.x + threadIdx.x) >> 5;
    int   lane = threadIdx.x & 31;
    int   b    = (int)(w >> 16);
    int   h    = (int)(w & 15);
    const __half2* row = (const __half2*)(qp + w * 256);
    const float4*  ks  = (const float4*)(ksum + ((size_t)b * 16 + h) * 256);
    float4 k0 = ks[lane * 2], k1 = ks[lane * 2 + 1];
    float2 a0 = __half22float2(row[lane * 4]);
    float2 a1 = __half22float2(row[lane * 4 + 1]);
    float2 a2 = __half22float2(row[lane * 4 + 2]);
    float2 a3 = __half22float2(row[lane * 4 + 3]);
    float s = a0.x * k0.x + a0.y * k0.y + a1.x * k0.z + a1.y * k0.w
            + a2.x * k1.x + a2.y * k1.y + a3.x * k1.z + a3.y * k1.w;
#pragma unroll
    for (int o = 16; o; o >>= 1) s += __shfl_xor_sync(0xffffffffu, s, o);
    if (lane == 0) den[w] = s;
}

template<bool WRITE_H>
__global__ void k_ln(const float* __restrict__ a, const float* __restrict__ r,
                     const float* __restrict__ g, const float* __restrict__ b,
                     float* __restrict__ out, __half* __restrict__ outh)
{
    const int row = blockIdx.x;
    const int t   = threadIdx.x;
    const size_t base = (size_t)row * 1024;
    float4 xa = *(const float4*)(a + base + t * 4);
    float4 xr = *(const float4*)(r + base + t * 4);
    float4 s  = make_float4(xa.x + xr.x, xa.y + xr.y, xa.z + xr.z, xa.w + xr.w);
    float sum = s.x + s.y + s.z + s.w;
    float sq  = s.x * s.x + s.y * s.y + s.z * s.z + s.w * s.w;
#pragma unroll
    for (int o = 16; o; o >>= 1) {
        sum += __shfl_xor_sync(0xffffffffu, sum, o);
        sq  += __shfl_xor_sync(0xffffffffu, sq,  o);
    }
    __shared__ float ssum[8], ssq[8];
    __shared__ float s_mu, s_inv;
    int w = t >> 5;
    if ((t & 31) == 0) { ssum[w] = sum; ssq[w] = sq; }
    __syncthreads();
    if (t == 0) {
        float ts = 0.f, tq = 0.f;
        for (int i = 0; i < 8; i++) { ts += ssum[i]; tq += ssq[i]; }
        float mu  = ts * (1.f / 1024.f);
        float var = tq * (1.f / 1024.f) - mu * mu;
        s_mu = mu;
        s_inv = rsqrtf(var + 1e-6f);
    }
    __syncthreads();
    float mu = s_mu, inv = s_inv;
    float4 gg = *(const float4*)(g + t * 4);
    float4 bb = *(const float4*)(b + t * 4);
    float4 o = make_float4((s.x - mu) * inv * gg.x + bb.x,
                           (s.y - mu) * inv * gg.y + bb.y,
                           (s.z - mu) * inv * gg.z + bb.z,
                           (s.w - mu) * inv * gg.w + bb.w);
    *(float4*)(out + base + t * 4) = o;
    if (WRITE_H) {
        __half2* oh = (__half2*)(outh + base + t * 4);
        oh[0] = __floats2half2_rn(o.x, o.y);
        oh[1] = __floats2half2_rn(o.z, o.w);
    }
}

// ---------------- driver -----------------------------------------------------
extern "C" void kernel_launch(void* const* d_in, const int* in_sizes, int n_in,
                              void* d_out, int out_size)
{
    const float* x    = (const float*)d_in[0];
    const float* wq   = (const float*)d_in[1];
    const float* wk   = (const float*)d_in[2];
    const float* wv   = (const float*)d_in[3];
    const float* wo   = (const float*)d_in[4];
    const float* proj = (const float*)d_in[5];
    const float* ln1g = (const float*)d_in[6];
    const float* ln1b = (const float*)d_in[7];
    const float* ln2g = (const float*)d_in[8];
    const float* ln2b = (const float*)d_in[9];
    const float* w1   = (const float*)d_in[10];
    const float* b1   = (const float*)d_in[11];
    const float* w2   = (const float*)d_in[12];
    const float* b2   = (const float*)d_in[13];
    float* out = (float*)d_out;

    float *p_kvp, *p_ksum, *p_den, *p_tmp, *p_out1;
    __half *p_xh, *p_qh, *p_kh, *p_vh, *p_qph, *p_kph, *p_kvh;
    __half *p_out1h, *p_attnh, *p_hh, *p_projh;
    __half *p_wqT, *p_wkT, *p_wvT, *p_woT, *p_w1T, *p_w2T;
    unsigned* p_kmax;
    cudaGetSymbolAddress((void**)&p_kvp,   g_kvp);
    cudaGetSymbolAddress((void**)&p_ksum,  g_ksum);
    cudaGetSymbolAddress((void**)&p_den,   g_den);
    cudaGetSymbolAddress((void**)&p_tmp,   g_tmp);
    cudaGetSymbolAddress((void**)&p_out1,  g_out1);
    cudaGetSymbolAddress((void**)&p_kmax,  g_kmax);
    cudaGetSymbolAddress((void**)&p_xh,    g_xh);
    cudaGetSymbolAddress((void**)&p_qh,    g_qh);
    cudaGetSymbolAddress((void**)&p_kh,    g_kh);
    cudaGetSymbolAddress((void**)&p_vh,    g_vh);
    cudaGetSymbolAddress((void**)&p_qph,   g_qph);
    cudaGetSymbolAddress((void**)&p_kph,   g_kph);
    cudaGetSymbolAddress((void**)&p_kvh,   g_kvh);
    cudaGetSymbolAddress((void**)&p_out1h, g_out1h);
    cudaGetSymbolAddress((void**)&p_attnh, g_attnh);
    cudaGetSymbolAddress((void**)&p_hh,    g_hh);
    cudaGetSymbolAddress((void**)&p_projh, g_projh);
    cudaGetSymbolAddress((void**)&p_wqT,   g_wqT);
    cudaGetSymbolAddress((void**)&p_wkT,   g_wkT);
    cudaGetSymbolAddress((void**)&p_wvT,   g_wvT);
    cudaGetSymbolAddress((void**)&p_woT,   g_woT);
    cudaGetSymbolAddress((void**)&p_w1T,   g_w1T);
    cudaGetSymbolAddress((void**)&p_w2T,   g_w2T);

    // prep
    k_half4<<<(NT * DD / 4 + 255) / 256, 256>>>((const float4*)x, (__half2*)p_xh, NT * DD / 4);
    k_transH<<<dim3(32, 32), dim3(32, 8)>>>(wq, p_wqT, DD, DD);
    k_transH<<<dim3(32, 32), dim3(32, 8)>>>(wk, p_wkT, DD, DD);
    k_transH<<<dim3(32, 32), dim3(32, 8)>>>(wv, p_wvT, DD, DD);
    k_projH<<<64, 256>>>(proj, p_projh);

    // q,k,v projections -> fp16
    hgemm<EPI_NONE, __half, false><<<dim3(8, 128), 256>>>(p_xh, p_wqT, nullptr, p_qh, NT, 1024, 1024);
    hgemm<EPI_NONE, __half, false><<<dim3(8, 128), 256>>>(p_xh, p_wkT, nullptr, p_kh, NT, 1024, 1024);
    hgemm<EPI_NONE, __half, false><<<dim3(8, 128), 256>>>(p_xh, p_wvT, nullptr, p_vh, NT, 1024, 1024);

    // remaining prep
    k_transH<<<dim3(32, 32),  dim3(32, 8)>>>(wo, p_woT, DD, DD);
    k_transH<<<dim3(128, 32), dim3(32, 8)>>>(w1, p_w1T, DD, DFF);
    k_transH<<<dim3(32, 128), dim3(32, 8)>>>(w2, p_w2T, DFF, DD);

    cudaMemsetAsync(p_kmax, 0, 4);
    cudaMemsetAsync(p_ksum, 0, BB * HH * MMF * sizeof(float));

    // fused dd + feature maps (q: row max; k: global max pass then exp pass)
    ddexp<DD_Q>   <<<NR / 64, 256>>>(p_qh, p_projh, p_qph, nullptr);
    ddexp<DD_KMAX><<<NR / 64, 256>>>(p_kh, p_projh, nullptr, p_kmax);
    ddexp<DD_KEXP><<<NR / 64, 256>>>(p_kh, p_projh, p_kph, p_kmax);

    // kv partials: fp16 split-K=4 over K=4096 (each 1024)
    hgemm_bh<true, false, float, 4><<<dim3(1, 2, 256), 256>>>(
        p_kph, (size_t)16777216, (size_t)256, 4096,
        p_vh,  (size_t)4194304,  (size_t)64,  1024,
        p_kvp, (size_t)(16 * 16384), (size_t)16384, 64, (size_t)KVN,
        nullptr, 0, 0, 0,
        256, 64, 1024);
    k_kvred<<<(KVN / 4 + 255) / 256, 256>>>((const float4*)p_kvp, (__half2*)p_kvh);

    k_ksum<<<dim3(8, 64), 256>>>(p_kph, p_ksum);
    k_denom<<<NR / 8, 256>>>(p_qph, p_ksum, p_den);

    // attn = (qp @ kv) / denom : fp16 -> fp16
    hgemm_bh<false, true, __half, 1><<<dim3(1, 32, 64), 256>>>(
        p_qph, (size_t)16777216, (size_t)256, 4096,
        p_kvh, (size_t)(16 * 16384), (size_t)16384, 64,
        p_attnh, (size_t)4194304, (size_t)64, 1024, (size_t)0,
        p_den,  (size_t)65536,   (size_t)1,  16,
        4096, 64, 256);

    // attn_out = attn @ wo^T -> fp32 tmp
    hgemm<EPI_NONE, float, false><<<dim3(8, 128), 256>>>(p_attnh, p_woT, nullptr, p_tmp, NT, 1024, 1024);

    // out1 = LN(x + attn_out) -> fp32 + fp16
    k_ln<true><<<NT, 256>>>(p_tmp, x, ln1g, ln1b, p_out1, p_out1h);

    // FFN
    hgemm<EPI_BIAS_ELU, __half, false><<<dim3(32, 128), 256>>>(p_out1h, p_w1T, b1, p_hh, NT, DFF, 1024);
    hgemm<EPI_BIAS, float, false><<<dim3(8, 128), 256>>>(p_hh, p_w2T, b2, p_tmp, NT, 1024, DFF);

    // out2 = LN(out1 + ffn)
    k_ln<false><<<NT, 256>>>(p_tmp, p_out1, ln2g, ln2b, out, nullptr);
}